// round 2
// baseline (speedup 1.0000x reference)
#include <cuda_runtime.h>
#include <cuda_bf16.h>
#include <cstdint>
#include <cstddef>

#define NN 4096
#define TT 24
#define FF 16
#define HH 128
#define GG 384
#define NHD 4
#define DOD 32
#define SEMD 64
#define PHD 32

// ---------------- scratch (static device globals; no runtime allocation) ----
__device__ float g_gi[(size_t)TT * NN * GG];   // [t][n][g]
__device__ float g_support[NN * HH];
__device__ float g_supP[NN * HH];
__device__ float g_supN[NN * HH];
__device__ float g_residP[NN * HH];
__device__ float g_residN[NN * HH];
__device__ float g_selfE[NN * HH];
__device__ float g_f1P[NHD * NN];
__device__ float g_f2P[NHD * NN];
__device__ float g_f1N[NHD * NN];
__device__ float g_f2N[NHD * NN];
__device__ float g_gatP[NN * HH];
__device__ float g_gatN[NN * HH];
__device__ float g_posE[NN * HH];
__device__ float g_negE[NN * HH];
__device__ float g_fused[NN * HH];
__device__ float g_colsum[HH];

__device__ __forceinline__ float warpsum(float v) {
#pragma unroll
    for (int o = 16; o >= 1; o >>= 1) v += __shfl_down_sync(0xffffffffu, v, o);
    return v;
}
__device__ __forceinline__ float sigmoidf_(float x) { return 1.f / (1.f + __expf(-x)); }

// ---------------- kernel 1: gi[t,n,:] = features[n,t,:] @ Wih^T + bih -------
__global__ void k_gi(const float* __restrict__ feat, const float* __restrict__ Wih,
                     const float* __restrict__ bih) {
    int idx = blockIdx.x * blockDim.x + threadIdx.x;
    int g4 = idx % 96;
    int n  = (idx / 96) % NN;
    int t  = idx / (96 * NN);
    if (t >= TT) return;
    const float* x = feat + ((size_t)n * TT + t) * FF;
    float xv[FF];
#pragma unroll
    for (int f = 0; f < FF; f++) xv[f] = __ldg(&x[f]);
    float acc[4];
#pragma unroll
    for (int j = 0; j < 4; j++) {
        int g = g4 * 4 + j;
        float s = __ldg(&bih[g]);
        const float* wr = Wih + (size_t)g * FF;
#pragma unroll
        for (int f = 0; f < FF; f++) s += xv[f] * __ldg(&wr[f]);
        acc[j] = s;
    }
    *(float4*)(g_gi + ((size_t)t * NN + n) * GG + g4 * 4) =
        make_float4(acc[0], acc[1], acc[2], acc[3]);
}

// ---------------- kernel 2: GRU scan (32 nodes per block, 24 steps) ---------
#define WHH_LD 384
#define GRU_SMEM ((128 * WHH_LD + GG + 32 * HH) * 4)

__global__ void __launch_bounds__(256, 1) k_gru(const float* __restrict__ Whh,
                                                const float* __restrict__ bhh) {
    extern __shared__ float sm[];
    float* Whh_t = sm;                       // [128][384], Whh_t[k][g] = Whh[g][k]
    float* bhh_s = sm + 128 * WHH_LD;
    float* h_s   = bhh_s + GG;               // [32][128]
    int tid = threadIdx.x;
    int tx = tid & 31, ty = tid >> 5;

    for (int i = tid; i < GG * HH; i += 256) {
        int g = i >> 7, k = i & 127;
        Whh_t[k * WHH_LD + g] = Whh[i];
    }
    for (int i = tid; i < GG; i += 256) bhh_s[i] = bhh[i];
    for (int i = tid; i < 32 * HH; i += 256) h_s[i] = 0.f;
    __syncthreads();

    float br[4], bz[4], bn[4];
#pragma unroll
    for (int j = 0; j < 4; j++) {
        br[j] = bhh_s[tx * 4 + j];
        bz[j] = bhh_s[128 + tx * 4 + j];
        bn[j] = bhh_s[256 + tx * 4 + j];
    }
    int node0 = blockIdx.x * 32;

    for (int t = 0; t < TT; t++) {
        float4 gr[4], gz[4], gnn[4];
#pragma unroll
        for (int q = 0; q < 4; q++) {
            size_t base = ((size_t)t * NN + node0 + ty * 4 + q) * GG + tx * 4;
            gr[q]  = *(const float4*)(g_gi + base);
            gz[q]  = *(const float4*)(g_gi + base + 128);
            gnn[q] = *(const float4*)(g_gi + base + 256);
        }
        float ar[4][4], az[4][4], an[4][4];
#pragma unroll
        for (int q = 0; q < 4; q++)
#pragma unroll
            for (int j = 0; j < 4; j++) { ar[q][j] = 0.f; az[q][j] = 0.f; an[q][j] = 0.f; }

#pragma unroll 2
        for (int k = 0; k < HH; k++) {
            const float* wrow = &Whh_t[k * WHH_LD + tx * 4];
            float4 wr = *(const float4*)(wrow);
            float4 wz = *(const float4*)(wrow + 128);
            float4 wn = *(const float4*)(wrow + 256);
#pragma unroll
            for (int q = 0; q < 4; q++) {
                float hk = h_s[(ty * 4 + q) * HH + k];
                ar[q][0] += wr.x * hk; ar[q][1] += wr.y * hk;
                ar[q][2] += wr.z * hk; ar[q][3] += wr.w * hk;
                az[q][0] += wz.x * hk; az[q][1] += wz.y * hk;
                az[q][2] += wz.z * hk; az[q][3] += wz.w * hk;
                an[q][0] += wn.x * hk; an[q][1] += wn.y * hk;
                an[q][2] += wn.z * hk; an[q][3] += wn.w * hk;
            }
        }
        __syncthreads();

#pragma unroll
        for (int q = 0; q < 4; q++) {
            int hoff = (ty * 4 + q) * HH + tx * 4;
            float4 hold = *(float4*)&h_s[hoff];
            float gir[4] = {gr[q].x, gr[q].y, gr[q].z, gr[q].w};
            float giz[4] = {gz[q].x, gz[q].y, gz[q].z, gz[q].w};
            float gin[4] = {gnn[q].x, gnn[q].y, gnn[q].z, gnn[q].w};
            float ho[4]  = {hold.x, hold.y, hold.z, hold.w};
            float hnw[4];
#pragma unroll
            for (int j = 0; j < 4; j++) {
                float r  = sigmoidf_(gir[j] + ar[q][j] + br[j]);
                float z  = sigmoidf_(giz[j] + az[q][j] + bz[j]);
                float nv = tanhf(gin[j] + r * (an[q][j] + bn[j]));
                hnw[j] = (1.f - z) * nv + z * ho[j];
            }
            *(float4*)&h_s[hoff] = make_float4(hnw[0], hnw[1], hnw[2], hnw[3]);
        }
        __syncthreads();
    }

    for (int i = tid; i < 32 * HH; i += 256)
        g_support[(size_t)(node0 + (i >> 7)) * HH + (i & 127)] = h_s[i];
}

// ---------------- kernel 3: C[4096,128] = A[4096,128] @ B[128,128] (+b1+b2) -
struct GemmJob { const float* A; const float* B; const float* b1; const float* b2; float* C; };
struct GemmJobs { GemmJob j[5]; };

#define GEMM_SMEM ((128 * 128 + 64 * 132) * 4)

__global__ void __launch_bounds__(256) k_gemm(GemmJobs jobs) {
    GemmJob job = jobs.j[blockIdx.y];
    extern __shared__ float sm[];
    float* Bs = sm;              // [128][128]
    float* As = sm + 16384;      // [64][132]
    int tid = threadIdx.x;
    int node0 = blockIdx.x * 64;

    for (int i = tid; i < 128 * 128; i += 256) Bs[i] = job.B[i];
    for (int i = tid; i < 64 * 128; i += 256) {
        int n = i >> 7, k = i & 127;
        As[n * 132 + k] = job.A[(size_t)(node0 + n) * HH + k];
    }
    __syncthreads();

    int tx = tid & 15, tyy = tid >> 4;
    float acc[4][8];
#pragma unroll
    for (int q = 0; q < 4; q++)
#pragma unroll
        for (int j = 0; j < 8; j++) acc[q][j] = 0.f;

    for (int k = 0; k < HH; k++) {
        float4 b0 = *(const float4*)&Bs[k * 128 + tx * 8];
        float4 b1v = *(const float4*)&Bs[k * 128 + tx * 8 + 4];
#pragma unroll
        for (int q = 0; q < 4; q++) {
            float a = As[(tyy * 4 + q) * 132 + k];
            acc[q][0] += a * b0.x;  acc[q][1] += a * b0.y;
            acc[q][2] += a * b0.z;  acc[q][3] += a * b0.w;
            acc[q][4] += a * b1v.x; acc[q][5] += a * b1v.y;
            acc[q][6] += a * b1v.z; acc[q][7] += a * b1v.w;
        }
    }
    float badd[8];
#pragma unroll
    for (int j = 0; j < 8; j++) {
        int o = tx * 8 + j;
        float b = 0.f;
        if (job.b1) b += job.b1[o];
        if (job.b2) b += job.b2[o];
        badd[j] = b;
    }
#pragma unroll
    for (int q = 0; q < 4; q++) {
        int n = node0 + tyy * 4 + q;
        *(float4*)&job.C[(size_t)n * HH + tx * 8] =
            make_float4(acc[q][0] + badd[0], acc[q][1] + badd[1],
                        acc[q][2] + badd[2], acc[q][3] + badd[3]);
        *(float4*)&job.C[(size_t)n * HH + tx * 8 + 4] =
            make_float4(acc[q][4] + badd[4], acc[q][5] + badd[5],
                        acc[q][6] + badd[6], acc[q][7] + badd[7]);
    }
}

// ---------------- kernel 4: f1/f2 per head -----------------------------------
__global__ void k_f1f2(const float* __restrict__ uP, const float* __restrict__ vP,
                       const float* __restrict__ uN, const float* __restrict__ vN) {
    const float* sup; const float* u; const float* v; float* f1; float* f2;
    if (blockIdx.y == 0) { sup = g_supP; u = uP; v = vP; f1 = g_f1P; f2 = g_f2P; }
    else                 { sup = g_supN; u = uN; v = vN; f1 = g_f1N; f2 = g_f2N; }
    int n = blockIdx.x * 8 + (threadIdx.x >> 5);
    int lane = threadIdx.x & 31;
#pragma unroll
    for (int h = 0; h < NHD; h++) {
        float s = sup[(size_t)n * HH + h * DOD + lane];
        float a = s * u[h * DOD + lane];
        float b = s * v[h * DOD + lane];
        a = warpsum(a); b = warpsum(b);
        if (lane == 0) { f1[h * NN + n] = a; f2[h * NN + n] = b; }
    }
}

// ---------------- kernel 5: GAT masked-attention aggregation -----------------
__global__ void __launch_bounds__(128) k_gat(const float* __restrict__ adjP,
                                             const float* __restrict__ adjN) {
    __shared__ int s_cnt;
    __shared__ int s_list[512];
    __shared__ float s_a[512];
    const float* adj; const float* sup; const float* f1; const float* f2;
    const float* resid; float* outp;
    if (blockIdx.y == 0) { adj = adjP; sup = g_supP; f1 = g_f1P; f2 = g_f2P; resid = g_residP; outp = g_gatP; }
    else                 { adj = adjN; sup = g_supN; f1 = g_f1N; f2 = g_f2N; resid = g_residN; outp = g_gatN; }
    int i = blockIdx.x, tid = threadIdx.x;
    int h = tid >> 5;
    float f2i = f2[h * NN + i];
    float num = 0.f, den = 0.f;

    // chunked nonzero-gather (density 1% -> ~41 nnz; 512-slot buffer per chunk)
    for (int c0 = 0; c0 < NN; c0 += 16384) {
        if (tid == 0) s_cnt = 0;
        __syncthreads();
        int cend = c0 + 16384; if (cend > NN) cend = NN;
        for (int j = c0 + tid; j < cend; j += 128) {
            float a = adj[(size_t)i * NN + j];
            if (a != 0.f) {
                int p = atomicAdd(&s_cnt, 1);
                s_list[p] = j;
                s_a[p] = a;
            }
        }
        __syncthreads();
        int cnt = s_cnt;
        for (int t = 0; t < cnt; t++) {
            int j = s_list[t];
            float w = f1[h * NN + j] + f2i;
            w = (w > 0.f) ? w : 0.2f * w;
            w *= s_a[t];
            den += w;
            num += w * sup[(size_t)j * HH + tid];
        }
        __syncthreads();
    }
    float d = (den == 0.f) ? 1.f : den;
    outp[(size_t)i * HH + tid] = num / d + resid[(size_t)i * HH + tid];
}

// ---------------- kernel 6: zero colsum --------------------------------------
__global__ void k_zero() { if (threadIdx.x < HH) g_colsum[threadIdx.x] = 0.f; }

// ---------------- kernel 7: semantic attention + fused + column sums ---------
__global__ void __launch_bounds__(256) k_sem(const float* __restrict__ W1,
                                             const float* __restrict__ b1,
                                             const float* __restrict__ W2) {
    __shared__ float W1s[HH * SEMD];
    __shared__ float W2s[SEMD], b1s[SEMD];
    __shared__ float embs[3][HH];
    __shared__ float red[3][SEMD];
    __shared__ float betas[3];
    int tid = threadIdx.x;
    for (int i = tid; i < HH * SEMD; i += 256) W1s[i] = W1[i];
    if (tid < SEMD) { W2s[tid] = W2[tid]; b1s[tid] = b1[tid]; }
    __syncthreads();
    int e = tid >> 6, s = tid & 63;
    for (int ln = 0; ln < 32; ln++) {
        int n = blockIdx.x * 32 + ln;
        if (tid < HH) {
            embs[0][tid] = g_selfE[(size_t)n * HH + tid];
            embs[1][tid] = g_posE[(size_t)n * HH + tid];
            embs[2][tid] = g_negE[(size_t)n * HH + tid];
        }
        __syncthreads();
        if (tid < 192) {
            float acc = b1s[s];
#pragma unroll 4
            for (int k = 0; k < HH; k++) acc += embs[e][k] * W1s[k * SEMD + s];
            red[e][s] = tanhf(acc) * W2s[s];
        }
        __syncthreads();
#pragma unroll
        for (int off = 32; off >= 1; off >>= 1) {
            if (tid < 192 && s < off) red[e][s] += red[e][s + off];
            __syncthreads();
        }
        if (tid == 0) {
            float w0 = red[0][0], w1 = red[1][0], w2 = red[2][0];
            float m = fmaxf(w0, fmaxf(w1, w2));
            float e0 = __expf(w0 - m), e1 = __expf(w1 - m), e2 = __expf(w2 - m);
            float inv = 1.f / (e0 + e1 + e2);
            betas[0] = e0 * inv; betas[1] = e1 * inv; betas[2] = e2 * inv;
        }
        __syncthreads();
        if (tid < HH) {
            float f = betas[0] * embs[0][tid] + betas[1] * embs[1][tid] + betas[2] * embs[2][tid];
            g_fused[(size_t)n * HH + tid] = f;
            atomicAdd(&g_colsum[tid], f);
        }
        __syncthreads();
    }
}

// ---------------- kernel 8: pairnorm + predictor -----------------------------
__global__ void __launch_bounds__(256) k_pred(const float* __restrict__ W1,
                                              const float* __restrict__ b1,
                                              const float* __restrict__ W2,
                                              const float* __restrict__ b2,
                                              float* __restrict__ out) {
    __shared__ float W1s[HH * PHD];
    __shared__ float xns[8][HH];
    int tid = threadIdx.x;
    for (int i = tid; i < HH * PHD; i += 256) W1s[i] = W1[i];
    int w = tid >> 5, lane = tid & 31;
    int n = blockIdx.x * 8 + w;
    float xv[4]; float ss = 0.f;
    const float invN = 1.f / (float)NN;
#pragma unroll
    for (int j = 0; j < 4; j++) {
        int d = lane + j * 32;
        float x = g_fused[(size_t)n * HH + d] - g_colsum[d] * invN;
        xv[j] = x; ss += x * x;
    }
    ss = warpsum(ss);
    ss = __shfl_sync(0xffffffffu, ss, 0);
    float rinv = rsqrtf(1e-6f + ss);
#pragma unroll
    for (int j = 0; j < 4; j++) xns[w][lane + j * 32] = xv[j] * rinv;
    __syncthreads();

    float acc = b1[lane];
#pragma unroll 4
    for (int k = 0; k < HH; k++) acc += xns[w][k] * W1s[k * PHD + lane];
    float hgt = acc > 0.f ? acc : 0.f;            // relu
    float o = warpsum(hgt * W2[lane]);
    if (lane == 0) out[n] = sigmoidf_(o + b2[0]);
}

// ---------------- launch -----------------------------------------------------
extern "C" void kernel_launch(void* const* d_in, const int* in_sizes, int n_in,
                              void* d_out, int out_size) {
    const float* features = (const float*)d_in[0];
    const float* pos_adj  = (const float*)d_in[1];
    const float* neg_adj  = (const float*)d_in[2];
    const float* gru_Wih  = (const float*)d_in[3];
    const float* gru_Whh  = (const float*)d_in[4];
    const float* gru_bih  = (const float*)d_in[5];
    const float* gru_bhh  = (const float*)d_in[6];
    const float* pos_W    = (const float*)d_in[7];
    const float* pos_u    = (const float*)d_in[8];
    const float* pos_v    = (const float*)d_in[9];
    const float* pos_b    = (const float*)d_in[10];
    const float* pos_pW   = (const float*)d_in[11];
    const float* pos_pb   = (const float*)d_in[12];
    const float* neg_W    = (const float*)d_in[13];
    const float* neg_u    = (const float*)d_in[14];
    const float* neg_v    = (const float*)d_in[15];
    const float* neg_b    = (const float*)d_in[16];
    const float* neg_pW   = (const float*)d_in[17];
    const float* neg_pb   = (const float*)d_in[18];
    const float* self_W   = (const float*)d_in[19];
    const float* self_b   = (const float*)d_in[20];
    const float* mpos_W   = (const float*)d_in[21];
    const float* mpos_b   = (const float*)d_in[22];
    const float* mneg_W   = (const float*)d_in[23];
    const float* mneg_b   = (const float*)d_in[24];
    const float* sem_W1   = (const float*)d_in[25];
    const float* sem_b1   = (const float*)d_in[26];
    const float* sem_W2   = (const float*)d_in[27];
    const float* pred_W1  = (const float*)d_in[28];
    const float* pred_b1  = (const float*)d_in[29];
    const float* pred_W2  = (const float*)d_in[30];
    const float* pred_b2  = (const float*)d_in[31];
    float* out = (float*)d_out;

    static bool attr_done = false;
    if (!attr_done) {
        cudaFuncSetAttribute(k_gru, cudaFuncAttributeMaxDynamicSharedMemorySize, GRU_SMEM);
        cudaFuncSetAttribute(k_gemm, cudaFuncAttributeMaxDynamicSharedMemorySize, GEMM_SMEM);
        attr_done = true;
    }

    // scratch pointers (device symbols)
    float *p_support, *p_supP, *p_supN, *p_residP, *p_residN, *p_selfE;
    float *p_gatP, *p_gatN, *p_posE, *p_negE;
    cudaGetSymbolAddress((void**)&p_support, g_support);
    cudaGetSymbolAddress((void**)&p_supP, g_supP);
    cudaGetSymbolAddress((void**)&p_supN, g_supN);
    cudaGetSymbolAddress((void**)&p_residP, g_residP);
    cudaGetSymbolAddress((void**)&p_residN, g_residN);
    cudaGetSymbolAddress((void**)&p_selfE, g_selfE);
    cudaGetSymbolAddress((void**)&p_gatP, g_gatP);
    cudaGetSymbolAddress((void**)&p_gatN, g_gatN);
    cudaGetSymbolAddress((void**)&p_posE, g_posE);
    cudaGetSymbolAddress((void**)&p_negE, g_negE);

    // 1) gi precompute
    {
        long total = (long)TT * NN * 96;
        k_gi<<<(unsigned)((total + 255) / 256), 256>>>(features, gru_Wih, gru_bih);
    }
    // 2) GRU scan
    k_gru<<<NN / 32, 256, GRU_SMEM>>>(gru_Whh, gru_bhh);

    // 3) 5 GEMMs off support
    {
        GemmJobs jb;
        jb.j[0] = { p_support, pos_W,  nullptr, nullptr, p_supP };
        jb.j[1] = { p_support, neg_W,  nullptr, nullptr, p_supN };
        jb.j[2] = { p_support, pos_pW, pos_b,   pos_pb,  p_residP };
        jb.j[3] = { p_support, neg_pW, neg_b,   neg_pb,  p_residN };
        jb.j[4] = { p_support, self_W, self_b,  nullptr, p_selfE };
        dim3 grid(NN / 64, 5);
        k_gemm<<<grid, 256, GEMM_SMEM>>>(jb);
    }
    // 4) attention logits
    {
        dim3 grid(NN / 8, 2);
        k_f1f2<<<grid, 256>>>(pos_u, pos_v, neg_u, neg_v);
    }
    // 5) GAT aggregation
    {
        dim3 grid(NN, 2);
        k_gat<<<grid, 128>>>(pos_adj, neg_adj);
    }
    // 6) message GEMMs
    {
        GemmJobs jb;
        jb.j[0] = { p_gatP, mpos_W, mpos_b, nullptr, p_posE };
        jb.j[1] = { p_gatN, mneg_W, mneg_b, nullptr, p_negE };
        jb.j[2] = jb.j[0]; jb.j[3] = jb.j[0]; jb.j[4] = jb.j[0];
        dim3 grid(NN / 64, 2);
        k_gemm<<<grid, 256, GEMM_SMEM>>>(jb);
    }
    // 7) semantic attention + fusion
    k_zero<<<1, 128>>>();
    k_sem<<<NN / 32, 256>>>(sem_W1, sem_b1, sem_W2);
    // 8) pairnorm + predictor
    k_pred<<<NN / 8, 256>>>(pred_W1, pred_b1, pred_W2, pred_b2, out);
}

// round 3
// speedup vs baseline: 4.0286x; 4.0286x over previous
#include <cuda_runtime.h>
#include <cuda_bf16.h>
#include <cstdint>
#include <cstddef>

#define NN 4096
#define TT 24
#define FF 16
#define HH 128
#define GG 384
#define NHD 4
#define DOD 32
#define SEMD 64
#define PHD 32

// ---------------- scratch (static device globals; no runtime allocation) ----
__device__ float g_gi[(size_t)TT * NN * GG];   // [t][n][g]
__device__ float g_support[NN * HH];
__device__ float g_supP[NN * HH];
__device__ float g_supN[NN * HH];
__device__ float g_residP[NN * HH];
__device__ float g_residN[NN * HH];
__device__ float g_selfE[NN * HH];
__device__ float g_f1P[NHD * NN];
__device__ float g_f2P[NHD * NN];
__device__ float g_f1N[NHD * NN];
__device__ float g_f2N[NHD * NN];
__device__ float g_gatP[NN * HH];
__device__ float g_gatN[NN * HH];
__device__ float g_posE[NN * HH];
__device__ float g_negE[NN * HH];
__device__ float g_fused[NN * HH];
__device__ float g_colsum[HH];

__device__ __forceinline__ float warpsum(float v) {
#pragma unroll
    for (int o = 16; o >= 1; o >>= 1) v += __shfl_down_sync(0xffffffffu, v, o);
    return v;
}
__device__ __forceinline__ float sigmoidf_(float x) { return 1.f / (1.f + __expf(-x)); }

// ---------------- kernel 1 (v2): gi = feat @ Wih^T + bih, smem-tiled GEMM ---
// Rows are (t,n) pairs, row = t*NN + n. Each block: 64 rows, Wih^T staged in smem.
// Each warp: 8 rows (two groups of 4), each lane: 12 outputs (3x float4).
__global__ void __launch_bounds__(256) k_gi(const float* __restrict__ feat,
                                            const float* __restrict__ Wih,
                                            const float* __restrict__ bih) {
    __shared__ float Wt[FF * GG];     // Wt[f][g] = Wih[g][f]
    __shared__ float bs[GG];
    int tid = threadIdx.x;
    for (int i = tid; i < GG * FF; i += 256) {
        int g = i >> 4, f = i & 15;
        Wt[f * GG + g] = Wih[i];
    }
    for (int i = tid; i < GG; i += 256) bs[i] = bih[i];
    __syncthreads();

    int warp = tid >> 5, lane = tid & 31;
    int row0 = blockIdx.x * 64 + warp * 8;

#pragma unroll
    for (int half = 0; half < 2; half++) {
        int rbase = row0 + half * 4;
        // fetch features for 4 rows (broadcast LDG - all lanes same address)
        float fv[4][FF];
#pragma unroll
        for (int q = 0; q < 4; q++) {
            int row = rbase + q;
            int t = row >> 12, n = row & 4095;
            const float4* fp = (const float4*)(feat + ((size_t)n * TT + t) * FF);
#pragma unroll
            for (int v = 0; v < 4; v++) {
                float4 x = __ldg(&fp[v]);
                fv[q][v * 4 + 0] = x.x; fv[q][v * 4 + 1] = x.y;
                fv[q][v * 4 + 2] = x.z; fv[q][v * 4 + 3] = x.w;
            }
        }
        // accumulators: 4 rows x 12 outputs (g = lane*4 + 128*jj + c)
        float acc[4][12];
#pragma unroll
        for (int jj = 0; jj < 3; jj++) {
            float4 b = *(const float4*)&bs[lane * 4 + 128 * jj];
#pragma unroll
            for (int q = 0; q < 4; q++) {
                acc[q][jj * 4 + 0] = b.x; acc[q][jj * 4 + 1] = b.y;
                acc[q][jj * 4 + 2] = b.z; acc[q][jj * 4 + 3] = b.w;
            }
        }
#pragma unroll
        for (int f = 0; f < FF; f++) {
            float4 w0 = *(const float4*)&Wt[f * GG + lane * 4];
            float4 w1 = *(const float4*)&Wt[f * GG + lane * 4 + 128];
            float4 w2 = *(const float4*)&Wt[f * GG + lane * 4 + 256];
#pragma unroll
            for (int q = 0; q < 4; q++) {
                float x = fv[q][f];
                acc[q][0] += x * w0.x; acc[q][1] += x * w0.y;
                acc[q][2] += x * w0.z; acc[q][3] += x * w0.w;
                acc[q][4] += x * w1.x; acc[q][5] += x * w1.y;
                acc[q][6] += x * w1.z; acc[q][7] += x * w1.w;
                acc[q][8] += x * w2.x; acc[q][9] += x * w2.y;
                acc[q][10] += x * w2.z; acc[q][11] += x * w2.w;
            }
        }
#pragma unroll
        for (int q = 0; q < 4; q++) {
            float* orow = g_gi + (size_t)(rbase + q) * GG;
#pragma unroll
            for (int jj = 0; jj < 3; jj++) {
                *(float4*)&orow[lane * 4 + 128 * jj] =
                    make_float4(acc[q][jj * 4 + 0], acc[q][jj * 4 + 1],
                                acc[q][jj * 4 + 2], acc[q][jj * 4 + 3]);
            }
        }
    }
}

// ---------------- kernel 2: GRU scan (32 nodes per block, 24 steps) ---------
#define WHH_LD 384
#define GRU_SMEM ((128 * WHH_LD + GG + 32 * HH) * 4)

__global__ void __launch_bounds__(256, 1) k_gru(const float* __restrict__ Whh,
                                                const float* __restrict__ bhh) {
    extern __shared__ float sm[];
    float* Whh_t = sm;                       // [128][384], Whh_t[k][g] = Whh[g][k]
    float* bhh_s = sm + 128 * WHH_LD;
    float* h_s   = bhh_s + GG;               // [32][128]
    int tid = threadIdx.x;
    int tx = tid & 31, ty = tid >> 5;

    for (int i = tid; i < GG * HH; i += 256) {
        int g = i >> 7, k = i & 127;
        Whh_t[k * WHH_LD + g] = Whh[i];
    }
    for (int i = tid; i < GG; i += 256) bhh_s[i] = bhh[i];
    for (int i = tid; i < 32 * HH; i += 256) h_s[i] = 0.f;
    __syncthreads();

    float br[4], bz[4], bn[4];
#pragma unroll
    for (int j = 0; j < 4; j++) {
        br[j] = bhh_s[tx * 4 + j];
        bz[j] = bhh_s[128 + tx * 4 + j];
        bn[j] = bhh_s[256 + tx * 4 + j];
    }
    int node0 = blockIdx.x * 32;

    for (int t = 0; t < TT; t++) {
        float4 gr[4], gz[4], gnn[4];
#pragma unroll
        for (int q = 0; q < 4; q++) {
            size_t base = ((size_t)t * NN + node0 + ty * 4 + q) * GG + tx * 4;
            gr[q]  = *(const float4*)(g_gi + base);
            gz[q]  = *(const float4*)(g_gi + base + 128);
            gnn[q] = *(const float4*)(g_gi + base + 256);
        }
        float ar[4][4], az[4][4], an[4][4];
#pragma unroll
        for (int q = 0; q < 4; q++)
#pragma unroll
            for (int j = 0; j < 4; j++) { ar[q][j] = 0.f; az[q][j] = 0.f; an[q][j] = 0.f; }

#pragma unroll 2
        for (int k = 0; k < HH; k++) {
            const float* wrow = &Whh_t[k * WHH_LD + tx * 4];
            float4 wr = *(const float4*)(wrow);
            float4 wz = *(const float4*)(wrow + 128);
            float4 wn = *(const float4*)(wrow + 256);
#pragma unroll
            for (int q = 0; q < 4; q++) {
                float hk = h_s[(ty * 4 + q) * HH + k];
                ar[q][0] += wr.x * hk; ar[q][1] += wr.y * hk;
                ar[q][2] += wr.z * hk; ar[q][3] += wr.w * hk;
                az[q][0] += wz.x * hk; az[q][1] += wz.y * hk;
                az[q][2] += wz.z * hk; az[q][3] += wz.w * hk;
                an[q][0] += wn.x * hk; an[q][1] += wn.y * hk;
                an[q][2] += wn.z * hk; an[q][3] += wn.w * hk;
            }
        }
        __syncthreads();

#pragma unroll
        for (int q = 0; q < 4; q++) {
            int hoff = (ty * 4 + q) * HH + tx * 4;
            float4 hold = *(float4*)&h_s[hoff];
            float gir[4] = {gr[q].x, gr[q].y, gr[q].z, gr[q].w};
            float giz[4] = {gz[q].x, gz[q].y, gz[q].z, gz[q].w};
            float gin[4] = {gnn[q].x, gnn[q].y, gnn[q].z, gnn[q].w};
            float ho[4]  = {hold.x, hold.y, hold.z, hold.w};
            float hnw[4];
#pragma unroll
            for (int j = 0; j < 4; j++) {
                float r  = sigmoidf_(gir[j] + ar[q][j] + br[j]);
                float z  = sigmoidf_(giz[j] + az[q][j] + bz[j]);
                float nv = tanhf(gin[j] + r * (an[q][j] + bn[j]));
                hnw[j] = (1.f - z) * nv + z * ho[j];
            }
            *(float4*)&h_s[hoff] = make_float4(hnw[0], hnw[1], hnw[2], hnw[3]);
        }
        __syncthreads();
    }

    for (int i = tid; i < 32 * HH; i += 256)
        g_support[(size_t)(node0 + (i >> 7)) * HH + (i & 127)] = h_s[i];
}

// ---------------- kernel 3: C[4096,128] = A[4096,128] @ B[128,128] (+b1+b2) -
struct GemmJob { const float* A; const float* B; const float* b1; const float* b2; float* C; };
struct GemmJobs { GemmJob j[5]; };

#define GEMM_SMEM ((128 * 128 + 64 * 132) * 4)

__global__ void __launch_bounds__(256) k_gemm(GemmJobs jobs) {
    GemmJob job = jobs.j[blockIdx.y];
    extern __shared__ float sm[];
    float* Bs = sm;              // [128][128]
    float* As = sm + 16384;      // [64][132]
    int tid = threadIdx.x;
    int node0 = blockIdx.x * 64;

    for (int i = tid; i < 128 * 128; i += 256) Bs[i] = job.B[i];
    for (int i = tid; i < 64 * 128; i += 256) {
        int n = i >> 7, k = i & 127;
        As[n * 132 + k] = job.A[(size_t)(node0 + n) * HH + k];
    }
    __syncthreads();

    int tx = tid & 15, tyy = tid >> 4;
    float acc[4][8];
#pragma unroll
    for (int q = 0; q < 4; q++)
#pragma unroll
        for (int j = 0; j < 8; j++) acc[q][j] = 0.f;

    for (int k = 0; k < HH; k++) {
        float4 b0 = *(const float4*)&Bs[k * 128 + tx * 8];
        float4 b1v = *(const float4*)&Bs[k * 128 + tx * 8 + 4];
#pragma unroll
        for (int q = 0; q < 4; q++) {
            float a = As[(tyy * 4 + q) * 132 + k];
            acc[q][0] += a * b0.x;  acc[q][1] += a * b0.y;
            acc[q][2] += a * b0.z;  acc[q][3] += a * b0.w;
            acc[q][4] += a * b1v.x; acc[q][5] += a * b1v.y;
            acc[q][6] += a * b1v.z; acc[q][7] += a * b1v.w;
        }
    }
    float badd[8];
#pragma unroll
    for (int j = 0; j < 8; j++) {
        int o = tx * 8 + j;
        float b = 0.f;
        if (job.b1) b += job.b1[o];
        if (job.b2) b += job.b2[o];
        badd[j] = b;
    }
#pragma unroll
    for (int q = 0; q < 4; q++) {
        int n = node0 + tyy * 4 + q;
        *(float4*)&job.C[(size_t)n * HH + tx * 8] =
            make_float4(acc[q][0] + badd[0], acc[q][1] + badd[1],
                        acc[q][2] + badd[2], acc[q][3] + badd[3]);
        *(float4*)&job.C[(size_t)n * HH + tx * 8 + 4] =
            make_float4(acc[q][4] + badd[4], acc[q][5] + badd[5],
                        acc[q][6] + badd[6], acc[q][7] + badd[7]);
    }
}

// ---------------- kernel 4: f1/f2 per head -----------------------------------
__global__ void k_f1f2(const float* __restrict__ uP, const float* __restrict__ vP,
                       const float* __restrict__ uN, const float* __restrict__ vN) {
    const float* sup; const float* u; const float* v; float* f1; float* f2;
    if (blockIdx.y == 0) { sup = g_supP; u = uP; v = vP; f1 = g_f1P; f2 = g_f2P; }
    else                 { sup = g_supN; u = uN; v = vN; f1 = g_f1N; f2 = g_f2N; }
    int n = blockIdx.x * 8 + (threadIdx.x >> 5);
    int lane = threadIdx.x & 31;
#pragma unroll
    for (int h = 0; h < NHD; h++) {
        float s = sup[(size_t)n * HH + h * DOD + lane];
        float a = s * u[h * DOD + lane];
        float b = s * v[h * DOD + lane];
        a = warpsum(a); b = warpsum(b);
        if (lane == 0) { f1[h * NN + n] = a; f2[h * NN + n] = b; }
    }
}

// ---------------- kernel 5: GAT masked-attention aggregation -----------------
__global__ void __launch_bounds__(128) k_gat(const float* __restrict__ adjP,
                                             const float* __restrict__ adjN) {
    __shared__ int s_cnt;
    __shared__ int s_list[512];
    __shared__ float s_a[512];
    const float* adj; const float* sup; const float* f1; const float* f2;
    const float* resid; float* outp;
    if (blockIdx.y == 0) { adj = adjP; sup = g_supP; f1 = g_f1P; f2 = g_f2P; resid = g_residP; outp = g_gatP; }
    else                 { adj = adjN; sup = g_supN; f1 = g_f1N; f2 = g_f2N; resid = g_residN; outp = g_gatN; }
    int i = blockIdx.x, tid = threadIdx.x;
    int h = tid >> 5;
    float f2i = f2[h * NN + i];
    float num = 0.f, den = 0.f;

    for (int c0 = 0; c0 < NN; c0 += 16384) {
        if (tid == 0) s_cnt = 0;
        __syncthreads();
        int cend = c0 + 16384; if (cend > NN) cend = NN;
        for (int j = c0 + tid; j < cend; j += 128) {
            float a = adj[(size_t)i * NN + j];
            if (a != 0.f) {
                int p = atomicAdd(&s_cnt, 1);
                s_list[p] = j;
                s_a[p] = a;
            }
        }
        __syncthreads();
        int cnt = s_cnt;
        for (int t = 0; t < cnt; t++) {
            int j = s_list[t];
            float w = f1[h * NN + j] + f2i;
            w = (w > 0.f) ? w : 0.2f * w;
            w *= s_a[t];
            den += w;
            num += w * sup[(size_t)j * HH + tid];
        }
        __syncthreads();
    }
    float d = (den == 0.f) ? 1.f : den;
    outp[(size_t)i * HH + tid] = num / d + resid[(size_t)i * HH + tid];
}

// ---------------- kernel 6: zero colsum --------------------------------------
__global__ void k_zero() { if (threadIdx.x < HH) g_colsum[threadIdx.x] = 0.f; }

// ---------------- kernel 7: semantic attention + fused + column sums ---------
__global__ void __launch_bounds__(256) k_sem(const float* __restrict__ W1,
                                             const float* __restrict__ b1,
                                             const float* __restrict__ W2) {
    __shared__ float W1s[HH * SEMD];
    __shared__ float W2s[SEMD], b1s[SEMD];
    __shared__ float embs[3][HH];
    __shared__ float red[3][SEMD];
    __shared__ float betas[3];
    int tid = threadIdx.x;
    for (int i = tid; i < HH * SEMD; i += 256) W1s[i] = W1[i];
    if (tid < SEMD) { W2s[tid] = W2[tid]; b1s[tid] = b1[tid]; }
    __syncthreads();
    int e = tid >> 6, s = tid & 63;
    for (int ln = 0; ln < 32; ln++) {
        int n = blockIdx.x * 32 + ln;
        if (tid < HH) {
            embs[0][tid] = g_selfE[(size_t)n * HH + tid];
            embs[1][tid] = g_posE[(size_t)n * HH + tid];
            embs[2][tid] = g_negE[(size_t)n * HH + tid];
        }
        __syncthreads();
        if (tid < 192) {
            float acc = b1s[s];
#pragma unroll 4
            for (int k = 0; k < HH; k++) acc += embs[e][k] * W1s[k * SEMD + s];
            red[e][s] = tanhf(acc) * W2s[s];
        }
        __syncthreads();
#pragma unroll
        for (int off = 32; off >= 1; off >>= 1) {
            if (tid < 192 && s < off) red[e][s] += red[e][s + off];
            __syncthreads();
        }
        if (tid == 0) {
            float w0 = red[0][0], w1 = red[1][0], w2 = red[2][0];
            float m = fmaxf(w0, fmaxf(w1, w2));
            float e0 = __expf(w0 - m), e1 = __expf(w1 - m), e2 = __expf(w2 - m);
            float inv = 1.f / (e0 + e1 + e2);
            betas[0] = e0 * inv; betas[1] = e1 * inv; betas[2] = e2 * inv;
        }
        __syncthreads();
        if (tid < HH) {
            float f = betas[0] * embs[0][tid] + betas[1] * embs[1][tid] + betas[2] * embs[2][tid];
            g_fused[(size_t)n * HH + tid] = f;
            atomicAdd(&g_colsum[tid], f);
        }
        __syncthreads();
    }
}

// ---------------- kernel 8: pairnorm + predictor -----------------------------
__global__ void __launch_bounds__(256) k_pred(const float* __restrict__ W1,
                                              const float* __restrict__ b1,
                                              const float* __restrict__ W2,
                                              const float* __restrict__ b2,
                                              float* __restrict__ out) {
    __shared__ float W1s[HH * PHD];
    __shared__ float xns[8][HH];
    int tid = threadIdx.x;
    for (int i = tid; i < HH * PHD; i += 256) W1s[i] = W1[i];
    int w = tid >> 5, lane = tid & 31;
    int n = blockIdx.x * 8 + w;
    float xv[4]; float ss = 0.f;
    const float invN = 1.f / (float)NN;
#pragma unroll
    for (int j = 0; j < 4; j++) {
        int d = lane + j * 32;
        float x = g_fused[(size_t)n * HH + d] - g_colsum[d] * invN;
        xv[j] = x; ss += x * x;
    }
    ss = warpsum(ss);
    ss = __shfl_sync(0xffffffffu, ss, 0);
    float rinv = rsqrtf(1e-6f + ss);
#pragma unroll
    for (int j = 0; j < 4; j++) xns[w][lane + j * 32] = xv[j] * rinv;
    __syncthreads();

    float acc = b1[lane];
#pragma unroll 4
    for (int k = 0; k < HH; k++) acc += xns[w][k] * W1s[k * PHD + lane];
    float hgt = acc > 0.f ? acc : 0.f;
    float o = warpsum(hgt * W2[lane]);
    if (lane == 0) out[n] = sigmoidf_(o + b2[0]);
}

// ---------------- launch -----------------------------------------------------
extern "C" void kernel_launch(void* const* d_in, const int* in_sizes, int n_in,
                              void* d_out, int out_size) {
    const float* features = (const float*)d_in[0];
    const float* pos_adj  = (const float*)d_in[1];
    const float* neg_adj  = (const float*)d_in[2];
    const float* gru_Wih  = (const float*)d_in[3];
    const float* gru_Whh  = (const float*)d_in[4];
    const float* gru_bih  = (const float*)d_in[5];
    const float* gru_bhh  = (const float*)d_in[6];
    const float* pos_W    = (const float*)d_in[7];
    const float* pos_u    = (const float*)d_in[8];
    const float* pos_v    = (const float*)d_in[9];
    const float* pos_b    = (const float*)d_in[10];
    const float* pos_pW   = (const float*)d_in[11];
    const float* pos_pb   = (const float*)d_in[12];
    const float* neg_W    = (const float*)d_in[13];
    const float* neg_u    = (const float*)d_in[14];
    const float* neg_v    = (const float*)d_in[15];
    const float* neg_b    = (const float*)d_in[16];
    const float* neg_pW   = (const float*)d_in[17];
    const float* neg_pb   = (const float*)d_in[18];
    const float* self_W   = (const float*)d_in[19];
    const float* self_b   = (const float*)d_in[20];
    const float* mpos_W   = (const float*)d_in[21];
    const float* mpos_b   = (const float*)d_in[22];
    const float* mneg_W   = (const float*)d_in[23];
    const float* mneg_b   = (const float*)d_in[24];
    const float* sem_W1   = (const float*)d_in[25];
    const float* sem_b1   = (const float*)d_in[26];
    const float* sem_W2   = (const float*)d_in[27];
    const float* pred_W1  = (const float*)d_in[28];
    const float* pred_b1  = (const float*)d_in[29];
    const float* pred_W2  = (const float*)d_in[30];
    const float* pred_b2  = (const float*)d_in[31];
    float* out = (float*)d_out;

    static bool attr_done = false;
    if (!attr_done) {
        cudaFuncSetAttribute(k_gru, cudaFuncAttributeMaxDynamicSharedMemorySize, GRU_SMEM);
        cudaFuncSetAttribute(k_gemm, cudaFuncAttributeMaxDynamicSharedMemorySize, GEMM_SMEM);
        attr_done = true;
    }

    float *p_support, *p_supP, *p_supN, *p_residP, *p_residN, *p_selfE;
    float *p_gatP, *p_gatN, *p_posE, *p_negE;
    cudaGetSymbolAddress((void**)&p_support, g_support);
    cudaGetSymbolAddress((void**)&p_supP, g_supP);
    cudaGetSymbolAddress((void**)&p_supN, g_supN);
    cudaGetSymbolAddress((void**)&p_residP, g_residP);
    cudaGetSymbolAddress((void**)&p_residN, g_residN);
    cudaGetSymbolAddress((void**)&p_selfE, g_selfE);
    cudaGetSymbolAddress((void**)&p_gatP, g_gatP);
    cudaGetSymbolAddress((void**)&p_gatN, g_gatN);
    cudaGetSymbolAddress((void**)&p_posE, g_posE);
    cudaGetSymbolAddress((void**)&p_negE, g_negE);

    // 1) gi precompute: 98304 rows / 64 per block
    k_gi<<<(TT * NN) / 64, 256>>>(features, gru_Wih, gru_bih);
    // 2) GRU scan
    k_gru<<<NN / 32, 256, GRU_SMEM>>>(gru_Whh, gru_bhh);
    // 3) 5 GEMMs off support
    {
        GemmJobs jb;
        jb.j[0] = { p_support, pos_W,  nullptr, nullptr, p_supP };
        jb.j[1] = { p_support, neg_W,  nullptr, nullptr, p_supN };
        jb.j[2] = { p_support, pos_pW, pos_b,   pos_pb,  p_residP };
        jb.j[3] = { p_support, neg_pW, neg_b,   neg_pb,  p_residN };
        jb.j[4] = { p_support, self_W, self_b,  nullptr, p_selfE };
        dim3 grid(NN / 64, 5);
        k_gemm<<<grid, 256, GEMM_SMEM>>>(jb);
    }
    // 4) attention logits
    {
        dim3 grid(NN / 8, 2);
        k_f1f2<<<grid, 256>>>(pos_u, pos_v, neg_u, neg_v);
    }
    // 5) GAT aggregation
    {
        dim3 grid(NN, 2);
        k_gat<<<grid, 128>>>(pos_adj, neg_adj);
    }
    // 6) message GEMMs
    {
        GemmJobs jb;
        jb.j[0] = { p_gatP, mpos_W, mpos_b, nullptr, p_posE };
        jb.j[1] = { p_gatN, mneg_W, mneg_b, nullptr, p_negE };
        jb.j[2] = jb.j[0]; jb.j[3] = jb.j[0]; jb.j[4] = jb.j[0];
        dim3 grid(NN / 64, 2);
        k_gemm<<<grid, 256, GEMM_SMEM>>>(jb);
    }
    // 7) semantic attention + fusion
    k_zero<<<1, 128>>>();
    k_sem<<<NN / 32, 256>>>(sem_W1, sem_b1, sem_W2);
    // 8) pairnorm + predictor
    k_pred<<<NN / 8, 256>>>(pred_W1, pred_b1, pred_W2, pred_b2, out);
}

// round 4
// speedup vs baseline: 4.6926x; 1.1648x over previous
#include <cuda_runtime.h>
#include <cuda_bf16.h>
#include <cstdint>
#include <cstddef>

#define NN 4096
#define TT 24
#define FF 16
#define HH 128
#define GG 384
#define NHD 4
#define DOD 32
#define SEMD 64
#define PHD 32

// ---------------- scratch (static device globals; no runtime allocation) ----
__device__ float g_gi[(size_t)TT * NN * GG];   // [t][n][g]
__device__ float g_support[NN * HH];
__device__ float g_supP[NN * HH];
__device__ float g_supN[NN * HH];
__device__ float g_residP[NN * HH];
__device__ float g_residN[NN * HH];
__device__ float g_selfE[NN * HH];
__device__ float g_f1P[NHD * NN];
__device__ float g_f2P[NHD * NN];
__device__ float g_f1N[NHD * NN];
__device__ float g_f2N[NHD * NN];
__device__ float g_gatP[NN * HH];
__device__ float g_gatN[NN * HH];
__device__ float g_posE[NN * HH];
__device__ float g_negE[NN * HH];
__device__ float g_fused[NN * HH];
__device__ float g_colsum[HH];
// fragment-ordered Whh for tensor-core GRU
__device__ __align__(16) float    g_Bhi[16 * 8 * 6 * 32 * 2];   // 49152 floats (tf32 hi)
__device__ __align__(16) uint32_t g_Blo[16 * 8 * 32 * 8];       // bf16 lo pairs, 8 words/lane/kt

__device__ __forceinline__ float warpsum(float v) {
#pragma unroll
    for (int o = 16; o >= 1; o >>= 1) v += __shfl_down_sync(0xffffffffu, v, o);
    return v;
}
__device__ __forceinline__ float sigmoidf_(float x) { return 1.f / (1.f + __expf(-x)); }

__device__ __forceinline__ uint32_t f2tf32(float f) {
    uint32_t u; asm("cvt.rna.tf32.f32 %0, %1;" : "=r"(u) : "f"(f)); return u;
}
__device__ __forceinline__ void mma_tf32(float d[4], const uint32_t a[4],
                                         uint32_t b0, uint32_t b1) {
    asm volatile("mma.sync.aligned.m16n8k8.row.col.f32.tf32.tf32.f32 "
                 "{%0,%1,%2,%3}, {%4,%5,%6,%7}, {%8,%9}, {%0,%1,%2,%3};"
                 : "+f"(d[0]), "+f"(d[1]), "+f"(d[2]), "+f"(d[3])
                 : "r"(a[0]), "r"(a[1]), "r"(a[2]), "r"(a[3]), "r"(b0), "r"(b1));
}

// ---------------- kernel 0: build fragment-ordered Whh (hi tf32 / lo bf16) --
__global__ void k_prep(const float* __restrict__ Whh) {
    int idx = blockIdx.x * 256 + threadIdx.x;       // 24576 = 16*8*6*32
    if (idx >= 16 * 8 * 6 * 32) return;
    int lane = idx & 31; int r = idx >> 5;
    int nt = r % 6; r /= 6;
    int w = r & 7; int kt = r >> 3;
    int g = nt >> 1, s = nt & 1;
    int n = g * 128 + w * 16 + s * 8 + (lane >> 2);
    float b0 = Whh[n * 128 + kt * 8 + (lane & 3)];
    float b1 = Whh[n * 128 + kt * 8 + (lane & 3) + 4];
    uint32_t h0 = f2tf32(b0), h1 = f2tf32(b1);
    g_Bhi[idx * 2 + 0] = __uint_as_float(h0);
    g_Bhi[idx * 2 + 1] = __uint_as_float(h1);
    __nv_bfloat16 l0 = __float2bfloat16(b0 - __uint_as_float(h0));
    __nv_bfloat16 l1 = __float2bfloat16(b1 - __uint_as_float(h1));
    uint32_t word = (uint32_t)__bfloat16_as_ushort(l0) |
                    ((uint32_t)__bfloat16_as_ushort(l1) << 16);
    g_Blo[((kt * 8 + w) * 32 + lane) * 8 + nt] = word;
}

// ---------------- kernel 1: gi = feat @ Wih^T + bih, smem-tiled GEMM --------
__global__ void __launch_bounds__(256) k_gi(const float* __restrict__ feat,
                                            const float* __restrict__ Wih,
                                            const float* __restrict__ bih) {
    __shared__ float Wt[FF * GG];
    __shared__ float bs[GG];
    int tid = threadIdx.x;
    for (int i = tid; i < GG * FF; i += 256) {
        int g = i >> 4, f = i & 15;
        Wt[f * GG + g] = Wih[i];
    }
    for (int i = tid; i < GG; i += 256) bs[i] = bih[i];
    __syncthreads();

    int warp = tid >> 5, lane = tid & 31;
    int row0 = blockIdx.x * 64 + warp * 8;

#pragma unroll
    for (int half = 0; half < 2; half++) {
        int rbase = row0 + half * 4;
        float fv[4][FF];
#pragma unroll
        for (int q = 0; q < 4; q++) {
            int row = rbase + q;
            int t = row >> 12, n = row & 4095;
            const float4* fp = (const float4*)(feat + ((size_t)n * TT + t) * FF);
#pragma unroll
            for (int v = 0; v < 4; v++) {
                float4 x = __ldg(&fp[v]);
                fv[q][v * 4 + 0] = x.x; fv[q][v * 4 + 1] = x.y;
                fv[q][v * 4 + 2] = x.z; fv[q][v * 4 + 3] = x.w;
            }
        }
        float acc[4][12];
#pragma unroll
        for (int jj = 0; jj < 3; jj++) {
            float4 b = *(const float4*)&bs[lane * 4 + 128 * jj];
#pragma unroll
            for (int q = 0; q < 4; q++) {
                acc[q][jj * 4 + 0] = b.x; acc[q][jj * 4 + 1] = b.y;
                acc[q][jj * 4 + 2] = b.z; acc[q][jj * 4 + 3] = b.w;
            }
        }
#pragma unroll
        for (int f = 0; f < FF; f++) {
            float4 w0 = *(const float4*)&Wt[f * GG + lane * 4];
            float4 w1 = *(const float4*)&Wt[f * GG + lane * 4 + 128];
            float4 w2 = *(const float4*)&Wt[f * GG + lane * 4 + 256];
#pragma unroll
            for (int q = 0; q < 4; q++) {
                float x = fv[q][f];
                acc[q][0] += x * w0.x; acc[q][1] += x * w0.y;
                acc[q][2] += x * w0.z; acc[q][3] += x * w0.w;
                acc[q][4] += x * w1.x; acc[q][5] += x * w1.y;
                acc[q][6] += x * w1.z; acc[q][7] += x * w1.w;
                acc[q][8] += x * w2.x; acc[q][9] += x * w2.y;
                acc[q][10] += x * w2.z; acc[q][11] += x * w2.w;
            }
        }
#pragma unroll
        for (int q = 0; q < 4; q++) {
            float* orow = g_gi + (size_t)(rbase + q) * GG;
#pragma unroll
            for (int jj = 0; jj < 3; jj++) {
                *(float4*)&orow[lane * 4 + 128 * jj] =
                    make_float4(acc[q][jj * 4 + 0], acc[q][jj * 4 + 1],
                                acc[q][jj * 4 + 2], acc[q][jj * 4 + 3]);
            }
        }
    }
}

// ---------------- kernel 2: GRU scan, tensor-core tf32 split ----------------
// smem: Bhi frags 49152 floats + h_hi[32][132] + h_lo[32][132]
#define GRU_SMEM ((49152 + 2 * 32 * 132) * 4)

__global__ void __launch_bounds__(256, 1) k_gru(const float* __restrict__ bhh) {
    extern __shared__ float sm[];
    float* Bhi_s = sm;                       // fragment-ordered
    float* h_hi  = sm + 49152;               // [32][132]
    float* h_lo  = h_hi + 32 * 132;
    int tid = threadIdx.x;
    int w = tid >> 5, lane = tid & 31;
    int qr = lane >> 2, qc = lane & 3;
    int hc = w * 16;
    int node0 = blockIdx.x * 32;

    // stage B_hi, zero h
    {
        const float4* src = (const float4*)g_Bhi;
        float4* dst = (float4*)Bhi_s;
        for (int i = tid; i < 49152 / 4; i += 256) dst[i] = src[i];
        for (int i = tid; i < 2 * 32 * 132; i += 256) h_hi[i] = 0.f;
    }
    // biases for this lane's 12 gate positions
    float bR[2][2], bZ[2][2], bN[2][2];
#pragma unroll
    for (int s = 0; s < 2; s++)
#pragma unroll
        for (int jj = 0; jj < 2; jj++) {
            int c = hc + s * 8 + 2 * qc + jj;
            bR[s][jj] = __ldg(&bhh[c]);
            bZ[s][jj] = __ldg(&bhh[128 + c]);
            bN[s][jj] = __ldg(&bhh[256 + c]);
        }
    __syncthreads();

    const float2* Bhi2 = (const float2*)Bhi_s;

    for (int t = 0; t < TT; t++) {
        // prefetch gi fragments [m][s][g][rg] -> float2 (jj pair)
        float gi_[2][2][3][2][2];
#pragma unroll
        for (int m = 0; m < 2; m++)
#pragma unroll
            for (int s = 0; s < 2; s++)
#pragma unroll
                for (int g = 0; g < 3; g++)
#pragma unroll
                    for (int rg = 0; rg < 2; rg++) {
                        int row = m * 16 + qr + rg * 8;
                        float2 v = *(const float2*)(g_gi +
                            ((size_t)t * NN + node0 + row) * GG + g * 128 + hc + s * 8 + 2 * qc);
                        gi_[m][s][g][rg][0] = v.x;
                        gi_[m][s][g][rg][1] = v.y;
                    }

        float d[2][2][3][4];
#pragma unroll
        for (int m = 0; m < 2; m++)
#pragma unroll
            for (int s = 0; s < 2; s++)
#pragma unroll
                for (int g = 0; g < 3; g++)
#pragma unroll
                    for (int j = 0; j < 4; j++) d[m][s][g][j] = 0.f;

        if (t) {
            // B_lo pipeline: load kt=0
            uint32_t blw[6], nw[6];
            {
                const uint32_t* p = &g_Blo[((0 * 8 + w) * 32 + lane) * 8];
                uint4 v4 = *(const uint4*)p;
                uint2 v2 = *(const uint2*)(p + 4);
                blw[0] = v4.x; blw[1] = v4.y; blw[2] = v4.z;
                blw[3] = v4.w; blw[4] = v2.x; blw[5] = v2.y;
            }
#pragma unroll 2
            for (int kt = 0; kt < 16; kt++) {
                if (kt < 15) {
                    const uint32_t* p = &g_Blo[(((kt + 1) * 8 + w) * 32 + lane) * 8];
                    uint4 v4 = *(const uint4*)p;
                    uint2 v2 = *(const uint2*)(p + 4);
                    nw[0] = v4.x; nw[1] = v4.y; nw[2] = v4.z;
                    nw[3] = v4.w; nw[4] = v2.x; nw[5] = v2.y;
                }
                int kc = kt * 8 + qc;
                uint32_t ah[2][4], al[2][4];
#pragma unroll
                for (int m = 0; m < 2; m++) {
                    int r0 = m * 16 + qr;
                    ah[m][0] = __float_as_uint(h_hi[r0 * 132 + kc]);
                    ah[m][1] = __float_as_uint(h_hi[(r0 + 8) * 132 + kc]);
                    ah[m][2] = __float_as_uint(h_hi[r0 * 132 + kc + 4]);
                    ah[m][3] = __float_as_uint(h_hi[(r0 + 8) * 132 + kc + 4]);
                    al[m][0] = __float_as_uint(h_lo[r0 * 132 + kc]);
                    al[m][1] = __float_as_uint(h_lo[(r0 + 8) * 132 + kc]);
                    al[m][2] = __float_as_uint(h_lo[r0 * 132 + kc + 4]);
                    al[m][3] = __float_as_uint(h_lo[(r0 + 8) * 132 + kc + 4]);
                }
#pragma unroll
                for (int g = 0; g < 3; g++)
#pragma unroll
                    for (int s = 0; s < 2; s++) {
                        int nt = g * 2 + s;
                        float2 bh = Bhi2[((kt * 8 + w) * 6 + nt) * 32 + lane];
                        uint32_t bh0 = __float_as_uint(bh.x);
                        uint32_t bh1 = __float_as_uint(bh.y);
                        uint32_t wlo = blw[nt];
                        uint32_t bl0 = wlo << 16;
                        uint32_t bl1 = wlo & 0xFFFF0000u;
#pragma unroll
                        for (int m = 0; m < 2; m++) {
                            mma_tf32(d[m][s][g], ah[m], bh0, bh1);
                            mma_tf32(d[m][s][g], al[m], bh0, bh1);
                            mma_tf32(d[m][s][g], ah[m], bl0, bl1);
                        }
                    }
#pragma unroll
                for (int i = 0; i < 6; i++) blw[i] = nw[i];
            }
        }

        // gate math
        float hn[2][2][2][2];
#pragma unroll
        for (int m = 0; m < 2; m++)
#pragma unroll
            for (int s = 0; s < 2; s++)
#pragma unroll
                for (int rg = 0; rg < 2; rg++) {
                    int row = m * 16 + qr + rg * 8;
                    int col = hc + s * 8 + 2 * qc;
                    float2 hh = *(const float2*)&h_hi[row * 132 + col];
                    float2 hl = *(const float2*)&h_lo[row * 132 + col];
#pragma unroll
                    for (int jj = 0; jj < 2; jj++) {
                        float hold = jj ? (hh.y + hl.y) : (hh.x + hl.x);
                        int di = rg * 2 + jj;
                        float rr = sigmoidf_(gi_[m][s][0][rg][jj] + d[m][s][0][di] + bR[s][jj]);
                        float zz = sigmoidf_(gi_[m][s][1][rg][jj] + d[m][s][1][di] + bZ[s][jj]);
                        float nv = tanhf(gi_[m][s][2][rg][jj] + rr * (d[m][s][2][di] + bN[s][jj]));
                        hn[m][s][rg][jj] = (1.f - zz) * nv + zz * hold;
                    }
                }
        __syncthreads();
#pragma unroll
        for (int m = 0; m < 2; m++)
#pragma unroll
            for (int s = 0; s < 2; s++)
#pragma unroll
                for (int rg = 0; rg < 2; rg++) {
                    int row = m * 16 + qr + rg * 8;
                    int col = hc + s * 8 + 2 * qc;
                    float h0 = hn[m][s][rg][0], h1 = hn[m][s][rg][1];
                    uint32_t u0 = f2tf32(h0), u1 = f2tf32(h1);
                    float l0 = h0 - __uint_as_float(u0);
                    float l1 = h1 - __uint_as_float(u1);
                    *(float2*)&h_hi[row * 132 + col] =
                        make_float2(__uint_as_float(u0), __uint_as_float(u1));
                    *(float2*)&h_lo[row * 132 + col] =
                        make_float2(__uint_as_float(f2tf32(l0)), __uint_as_float(f2tf32(l1)));
                }
        __syncthreads();
    }

    for (int i = tid; i < 32 * HH; i += 256) {
        int row = i >> 7, col = i & 127;
        g_support[(size_t)(node0 + row) * HH + col] =
            h_hi[row * 132 + col] + h_lo[row * 132 + col];
    }
}

// ---------------- kernel 3: C[4096,128] = A[4096,128] @ B[128,128] (+b1+b2) -
struct GemmJob { const float* A; const float* B; const float* b1; const float* b2; float* C; };
struct GemmJobs { GemmJob j[5]; };

#define GEMM_SMEM ((128 * 128 + 64 * 132) * 4)

__global__ void __launch_bounds__(256) k_gemm(GemmJobs jobs) {
    GemmJob job = jobs.j[blockIdx.y];
    extern __shared__ float sm[];
    float* Bs = sm;
    float* As = sm + 16384;
    int tid = threadIdx.x;
    int node0 = blockIdx.x * 64;

    for (int i = tid; i < 128 * 128; i += 256) Bs[i] = job.B[i];
    for (int i = tid; i < 64 * 128; i += 256) {
        int n = i >> 7, k = i & 127;
        As[n * 132 + k] = job.A[(size_t)(node0 + n) * HH + k];
    }
    __syncthreads();

    int tx = tid & 15, tyy = tid >> 4;
    float acc[4][8];
#pragma unroll
    for (int q = 0; q < 4; q++)
#pragma unroll
        for (int j = 0; j < 8; j++) acc[q][j] = 0.f;

    for (int k = 0; k < HH; k++) {
        float4 b0 = *(const float4*)&Bs[k * 128 + tx * 8];
        float4 b1v = *(const float4*)&Bs[k * 128 + tx * 8 + 4];
#pragma unroll
        for (int q = 0; q < 4; q++) {
            float a = As[(tyy * 4 + q) * 132 + k];
            acc[q][0] += a * b0.x;  acc[q][1] += a * b0.y;
            acc[q][2] += a * b0.z;  acc[q][3] += a * b0.w;
            acc[q][4] += a * b1v.x; acc[q][5] += a * b1v.y;
            acc[q][6] += a * b1v.z; acc[q][7] += a * b1v.w;
        }
    }
    float badd[8];
#pragma unroll
    for (int j = 0; j < 8; j++) {
        int o = tx * 8 + j;
        float b = 0.f;
        if (job.b1) b += job.b1[o];
        if (job.b2) b += job.b2[o];
        badd[j] = b;
    }
#pragma unroll
    for (int q = 0; q < 4; q++) {
        int n = node0 + tyy * 4 + q;
        *(float4*)&job.C[(size_t)n * HH + tx * 8] =
            make_float4(acc[q][0] + badd[0], acc[q][1] + badd[1],
                        acc[q][2] + badd[2], acc[q][3] + badd[3]);
        *(float4*)&job.C[(size_t)n * HH + tx * 8 + 4] =
            make_float4(acc[q][4] + badd[4], acc[q][5] + badd[5],
                        acc[q][6] + badd[6], acc[q][7] + badd[7]);
    }
}

// ---------------- kernel 4: f1/f2 per head -----------------------------------
__global__ void k_f1f2(const float* __restrict__ uP, const float* __restrict__ vP,
                       const float* __restrict__ uN, const float* __restrict__ vN) {
    const float* sup; const float* u; const float* v; float* f1; float* f2;
    if (blockIdx.y == 0) { sup = g_supP; u = uP; v = vP; f1 = g_f1P; f2 = g_f2P; }
    else                 { sup = g_supN; u = uN; v = vN; f1 = g_f1N; f2 = g_f2N; }
    int n = blockIdx.x * 8 + (threadIdx.x >> 5);
    int lane = threadIdx.x & 31;
#pragma unroll
    for (int h = 0; h < NHD; h++) {
        float s = sup[(size_t)n * HH + h * DOD + lane];
        float a = s * u[h * DOD + lane];
        float b = s * v[h * DOD + lane];
        a = warpsum(a); b = warpsum(b);
        if (lane == 0) { f1[h * NN + n] = a; f2[h * NN + n] = b; }
    }
}

// ---------------- kernel 5: GAT masked-attention aggregation -----------------
__global__ void __launch_bounds__(128) k_gat(const float* __restrict__ adjP,
                                             const float* __restrict__ adjN) {
    __shared__ int s_cnt;
    __shared__ int s_list[512];
    __shared__ float s_a[512];
    const float* adj; const float* sup; const float* f1; const float* f2;
    const float* resid; float* outp;
    if (blockIdx.y == 0) { adj = adjP; sup = g_supP; f1 = g_f1P; f2 = g_f2P; resid = g_residP; outp = g_gatP; }
    else                 { adj = adjN; sup = g_supN; f1 = g_f1N; f2 = g_f2N; resid = g_residN; outp = g_gatN; }
    int i = blockIdx.x, tid = threadIdx.x;
    int h = tid >> 5;
    float f2i = f2[h * NN + i];
    float num = 0.f, den = 0.f;

    for (int c0 = 0; c0 < NN; c0 += 16384) {
        if (tid == 0) s_cnt = 0;
        __syncthreads();
        int cend = c0 + 16384; if (cend > NN) cend = NN;
        for (int j = c0 + tid; j < cend; j += 128) {
            float a = adj[(size_t)i * NN + j];
            if (a != 0.f) {
                int p = atomicAdd(&s_cnt, 1);
                s_list[p] = j;
                s_a[p] = a;
            }
        }
        __syncthreads();
        int cnt = s_cnt;
        for (int t = 0; t < cnt; t++) {
            int j = s_list[t];
            float w = f1[h * NN + j] + f2i;
            w = (w > 0.f) ? w : 0.2f * w;
            w *= s_a[t];
            den += w;
            num += w * sup[(size_t)j * HH + tid];
        }
        __syncthreads();
    }
    float d = (den == 0.f) ? 1.f : den;
    outp[(size_t)i * HH + tid] = num / d + resid[(size_t)i * HH + tid];
}

// ---------------- kernel 6: zero colsum --------------------------------------
__global__ void k_zero() { if (threadIdx.x < HH) g_colsum[threadIdx.x] = 0.f; }

// ---------------- kernel 7: semantic attention + fused + column sums ---------
__global__ void __launch_bounds__(256) k_sem(const float* __restrict__ W1,
                                             const float* __restrict__ b1,
                                             const float* __restrict__ W2) {
    __shared__ float W1s[HH * SEMD];
    __shared__ float W2s[SEMD], b1s[SEMD];
    __shared__ float embs[3][HH];
    __shared__ float red[3][SEMD];
    __shared__ float betas[3];
    int tid = threadIdx.x;
    for (int i = tid; i < HH * SEMD; i += 256) W1s[i] = W1[i];
    if (tid < SEMD) { W2s[tid] = W2[tid]; b1s[tid] = b1[tid]; }
    __syncthreads();
    int e = tid >> 6, s = tid & 63;
    for (int ln = 0; ln < 32; ln++) {
        int n = blockIdx.x * 32 + ln;
        if (tid < HH) {
            embs[0][tid] = g_selfE[(size_t)n * HH + tid];
            embs[1][tid] = g_posE[(size_t)n * HH + tid];
            embs[2][tid] = g_negE[(size_t)n * HH + tid];
        }
        __syncthreads();
        if (tid < 192) {
            float acc = b1s[s];
#pragma unroll 4
            for (int k = 0; k < HH; k++) acc += embs[e][k] * W1s[k * SEMD + s];
            red[e][s] = tanhf(acc) * W2s[s];
        }
        __syncthreads();
#pragma unroll
        for (int off = 32; off >= 1; off >>= 1) {
            if (tid < 192 && s < off) red[e][s] += red[e][s + off];
            __syncthreads();
        }
        if (tid == 0) {
            float w0 = red[0][0], w1 = red[1][0], w2 = red[2][0];
            float m = fmaxf(w0, fmaxf(w1, w2));
            float e0 = __expf(w0 - m), e1 = __expf(w1 - m), e2 = __expf(w2 - m);
            float inv = 1.f / (e0 + e1 + e2);
            betas[0] = e0 * inv; betas[1] = e1 * inv; betas[2] = e2 * inv;
        }
        __syncthreads();
        if (tid < HH) {
            float f = betas[0] * embs[0][tid] + betas[1] * embs[1][tid] + betas[2] * embs[2][tid];
            g_fused[(size_t)n * HH + tid] = f;
            atomicAdd(&g_colsum[tid], f);
        }
        __syncthreads();
    }
}

// ---------------- kernel 8: pairnorm + predictor -----------------------------
__global__ void __launch_bounds__(256) k_pred(const float* __restrict__ W1,
                                              const float* __restrict__ b1,
                                              const float* __restrict__ W2,
                                              const float* __restrict__ b2,
                                              float* __restrict__ out) {
    __shared__ float W1s[HH * PHD];
    __shared__ float xns[8][HH];
    int tid = threadIdx.x;
    for (int i = tid; i < HH * PHD; i += 256) W1s[i] = W1[i];
    int w = tid >> 5, lane = tid & 31;
    int n = blockIdx.x * 8 + w;
    float xv[4]; float ss = 0.f;
    const float invN = 1.f / (float)NN;
#pragma unroll
    for (int j = 0; j < 4; j++) {
        int d = lane + j * 32;
        float x = g_fused[(size_t)n * HH + d] - g_colsum[d] * invN;
        xv[j] = x; ss += x * x;
    }
    ss = warpsum(ss);
    ss = __shfl_sync(0xffffffffu, ss, 0);
    float rinv = rsqrtf(1e-6f + ss);
#pragma unroll
    for (int j = 0; j < 4; j++) xns[w][lane + j * 32] = xv[j] * rinv;
    __syncthreads();

    float acc = b1[lane];
#pragma unroll 4
    for (int k = 0; k < HH; k++) acc += xns[w][k] * W1s[k * PHD + lane];
    float hgt = acc > 0.f ? acc : 0.f;
    float o = warpsum(hgt * W2[lane]);
    if (lane == 0) out[n] = sigmoidf_(o + b2[0]);
}

// ---------------- launch -----------------------------------------------------
extern "C" void kernel_launch(void* const* d_in, const int* in_sizes, int n_in,
                              void* d_out, int out_size) {
    const float* features = (const float*)d_in[0];
    const float* pos_adj  = (const float*)d_in[1];
    const float* neg_adj  = (const float*)d_in[2];
    const float* gru_Wih  = (const float*)d_in[3];
    const float* gru_Whh  = (const float*)d_in[4];
    const float* gru_bih  = (const float*)d_in[5];
    const float* gru_bhh  = (const float*)d_in[6];
    const float* pos_W    = (const float*)d_in[7];
    const float* pos_u    = (const float*)d_in[8];
    const float* pos_v    = (const float*)d_in[9];
    const float* pos_b    = (const float*)d_in[10];
    const float* pos_pW   = (const float*)d_in[11];
    const float* pos_pb   = (const float*)d_in[12];
    const float* neg_W    = (const float*)d_in[13];
    const float* neg_u    = (const float*)d_in[14];
    const float* neg_v    = (const float*)d_in[15];
    const float* neg_b    = (const float*)d_in[16];
    const float* neg_pW   = (const float*)d_in[17];
    const float* neg_pb   = (const float*)d_in[18];
    const float* self_W   = (const float*)d_in[19];
    const float* self_b   = (const float*)d_in[20];
    const float* mpos_W   = (const float*)d_in[21];
    const float* mpos_b   = (const float*)d_in[22];
    const float* mneg_W   = (const float*)d_in[23];
    const float* mneg_b   = (const float*)d_in[24];
    const float* sem_W1   = (const float*)d_in[25];
    const float* sem_b1   = (const float*)d_in[26];
    const float* sem_W2   = (const float*)d_in[27];
    const float* pred_W1  = (const float*)d_in[28];
    const float* pred_b1  = (const float*)d_in[29];
    const float* pred_W2  = (const float*)d_in[30];
    const float* pred_b2  = (const float*)d_in[31];
    float* out = (float*)d_out;

    static bool attr_done = false;
    if (!attr_done) {
        cudaFuncSetAttribute(k_gru, cudaFuncAttributeMaxDynamicSharedMemorySize, GRU_SMEM);
        cudaFuncSetAttribute(k_gemm, cudaFuncAttributeMaxDynamicSharedMemorySize, GEMM_SMEM);
        attr_done = true;
    }

    float *p_support, *p_supP, *p_supN, *p_residP, *p_residN, *p_selfE;
    float *p_gatP, *p_gatN, *p_posE, *p_negE;
    cudaGetSymbolAddress((void**)&p_support, g_support);
    cudaGetSymbolAddress((void**)&p_supP, g_supP);
    cudaGetSymbolAddress((void**)&p_supN, g_supN);
    cudaGetSymbolAddress((void**)&p_residP, g_residP);
    cudaGetSymbolAddress((void**)&p_residN, g_residN);
    cudaGetSymbolAddress((void**)&p_selfE, g_selfE);
    cudaGetSymbolAddress((void**)&p_gatP, g_gatP);
    cudaGetSymbolAddress((void**)&p_gatN, g_gatN);
    cudaGetSymbolAddress((void**)&p_posE, g_posE);
    cudaGetSymbolAddress((void**)&p_negE, g_negE);

    // 0) fragment-ordered Whh
    k_prep<<<96, 256>>>(gru_Whh);
    // 1) gi precompute
    k_gi<<<(TT * NN) / 64, 256>>>(features, gru_Wih, gru_bih);
    // 2) GRU scan (tensor cores)
    k_gru<<<NN / 32, 256, GRU_SMEM>>>(gru_bhh);
    // 3) 5 GEMMs off support
    {
        GemmJobs jb;
        jb.j[0] = { p_support, pos_W,  nullptr, nullptr, p_supP };
        jb.j[1] = { p_support, neg_W,  nullptr, nullptr, p_supN };
        jb.j[2] = { p_support, pos_pW, pos_b,   pos_pb,  p_residP };
        jb.j[3] = { p_support, neg_pW, neg_b,   neg_pb,  p_residN };
        jb.j[4] = { p_support, self_W, self_b,  nullptr, p_selfE };
        dim3 grid(NN / 64, 5);
        k_gemm<<<grid, 256, GEMM_SMEM>>>(jb);
    }
    // 4) attention logits
    {
        dim3 grid(NN / 8, 2);
        k_f1f2<<<grid, 256>>>(pos_u, pos_v, neg_u, neg_v);
    }
    // 5) GAT aggregation
    {
        dim3 grid(NN, 2);
        k_gat<<<grid, 128>>>(pos_adj, neg_adj);
    }
    // 6) message GEMMs
    {
        GemmJobs jb;
        jb.j[0] = { p_gatP, mpos_W, mpos_b, nullptr, p_posE };
        jb.j[1] = { p_gatN, mneg_W, mneg_b, nullptr, p_negE };
        jb.j[2] = jb.j[0]; jb.j[3] = jb.j[0]; jb.j[4] = jb.j[0];
        dim3 grid(NN / 64, 2);
        k_gemm<<<grid, 256, GEMM_SMEM>>>(jb);
    }
    // 7) semantic attention + fusion
    k_zero<<<1, 128>>>();
    k_sem<<<NN / 32, 256>>>(sem_W1, sem_b1, sem_W2);
    // 8) pairnorm + predictor
    k_pred<<<NN / 8, 256>>>(pred_W1, pred_b1, pred_W2, pred_b2, out);
}

// round 5
// speedup vs baseline: 5.6981x; 1.2143x over previous
#include <cuda_runtime.h>
#include <cuda_bf16.h>
#include <cstdint>
#include <cstddef>

#define NN 4096
#define TT 24
#define FF 16
#define HH 128
#define GG 384
#define NHD 4
#define DOD 32
#define SEMD 64
#define PHD 32

// ---------------- scratch (static device globals; no runtime allocation) ----
__device__ float g_gi[(size_t)TT * NN * GG];   // [t][n][g]
__device__ float g_support[NN * HH];
__device__ float g_supP[NN * HH];
__device__ float g_supN[NN * HH];
__device__ float g_residP[NN * HH];
__device__ float g_residN[NN * HH];
__device__ float g_selfE[NN * HH];
__device__ float g_f1P[NHD * NN];
__device__ float g_f2P[NHD * NN];
__device__ float g_f1N[NHD * NN];
__device__ float g_f2N[NHD * NN];
__device__ float g_gatP[NN * HH];
__device__ float g_gatN[NN * HH];
__device__ float g_posE[NN * HH];
__device__ float g_negE[NN * HH];
__device__ float g_fused[NN * HH];
__device__ float g_colsum[HH];
// fragment-ordered Whh for tensor-core GRU
__device__ __align__(16) float    g_Bhi[16 * 8 * 6 * 32 * 2];
__device__ __align__(16) uint32_t g_Blo[16 * 8 * 32 * 8];

__device__ __forceinline__ float warpsum(float v) {
#pragma unroll
    for (int o = 16; o >= 1; o >>= 1) v += __shfl_down_sync(0xffffffffu, v, o);
    return v;
}
__device__ __forceinline__ float warpsum_bfly(float v) {
#pragma unroll
    for (int o = 16; o >= 1; o >>= 1) v += __shfl_xor_sync(0xffffffffu, v, o);
    return v;
}
__device__ __forceinline__ float sigmoid_fast(float x) {
    return __fdividef(1.f, 1.f + __expf(-x));
}
__device__ __forceinline__ float tanh_fast(float x) {
    float e = __expf(-2.f * x);
    return __fdividef(2.f, 1.f + e) - 1.f;
}
__device__ __forceinline__ uint32_t f2tf32(float f) {
    uint32_t u; asm("cvt.rna.tf32.f32 %0, %1;" : "=r"(u) : "f"(f)); return u;
}
__device__ __forceinline__ void mma_tf32(float d[4], const uint32_t a[4],
                                         uint32_t b0, uint32_t b1) {
    asm volatile("mma.sync.aligned.m16n8k8.row.col.f32.tf32.tf32.f32 "
                 "{%0,%1,%2,%3}, {%4,%5,%6,%7}, {%8,%9}, {%0,%1,%2,%3};"
                 : "+f"(d[0]), "+f"(d[1]), "+f"(d[2]), "+f"(d[3])
                 : "r"(a[0]), "r"(a[1]), "r"(a[2]), "r"(a[3]), "r"(b0), "r"(b1));
}

// ---------------- kernel 0: build fragment-ordered Whh (hi tf32 / lo bf16) --
__global__ void k_prep(const float* __restrict__ Whh) {
    int idx = blockIdx.x * 256 + threadIdx.x;       // 24576 = 16*8*6*32
    if (idx >= 16 * 8 * 6 * 32) return;
    int lane = idx & 31; int r = idx >> 5;
    int nt = r % 6; r /= 6;
    int w = r & 7; int kt = r >> 3;
    int g = nt >> 1, s = nt & 1;
    int n = g * 128 + w * 16 + s * 8 + (lane >> 2);
    float b0 = Whh[n * 128 + kt * 8 + (lane & 3)];
    float b1 = Whh[n * 128 + kt * 8 + (lane & 3) + 4];
    uint32_t h0 = f2tf32(b0), h1 = f2tf32(b1);
    g_Bhi[idx * 2 + 0] = __uint_as_float(h0);
    g_Bhi[idx * 2 + 1] = __uint_as_float(h1);
    __nv_bfloat16 l0 = __float2bfloat16(b0 - __uint_as_float(h0));
    __nv_bfloat16 l1 = __float2bfloat16(b1 - __uint_as_float(h1));
    uint32_t word = (uint32_t)__bfloat16_as_ushort(l0) |
                    ((uint32_t)__bfloat16_as_ushort(l1) << 16);
    g_Blo[((kt * 8 + w) * 32 + lane) * 8 + nt] = word;
}

// ---------------- kernel 1: gi = feat @ Wih^T + bih, smem-tiled GEMM --------
__global__ void __launch_bounds__(256) k_gi(const float* __restrict__ feat,
                                            const float* __restrict__ Wih,
                                            const float* __restrict__ bih) {
    __shared__ float Wt[FF * GG];
    __shared__ float bs[GG];
    int tid = threadIdx.x;
    for (int i = tid; i < GG * FF; i += 256) {
        int g = i >> 4, f = i & 15;
        Wt[f * GG + g] = Wih[i];
    }
    for (int i = tid; i < GG; i += 256) bs[i] = bih[i];
    __syncthreads();

    int warp = tid >> 5, lane = tid & 31;
    int row0 = blockIdx.x * 64 + warp * 8;

#pragma unroll
    for (int half = 0; half < 2; half++) {
        int rbase = row0 + half * 4;
        float fv[4][FF];
#pragma unroll
        for (int q = 0; q < 4; q++) {
            int row = rbase + q;
            int t = row >> 12, n = row & 4095;
            const float4* fp = (const float4*)(feat + ((size_t)n * TT + t) * FF);
#pragma unroll
            for (int v = 0; v < 4; v++) {
                float4 x = __ldg(&fp[v]);
                fv[q][v * 4 + 0] = x.x; fv[q][v * 4 + 1] = x.y;
                fv[q][v * 4 + 2] = x.z; fv[q][v * 4 + 3] = x.w;
            }
        }
        float acc[4][12];
#pragma unroll
        for (int jj = 0; jj < 3; jj++) {
            float4 b = *(const float4*)&bs[lane * 4 + 128 * jj];
#pragma unroll
            for (int q = 0; q < 4; q++) {
                acc[q][jj * 4 + 0] = b.x; acc[q][jj * 4 + 1] = b.y;
                acc[q][jj * 4 + 2] = b.z; acc[q][jj * 4 + 3] = b.w;
            }
        }
#pragma unroll
        for (int f = 0; f < FF; f++) {
            float4 w0 = *(const float4*)&Wt[f * GG + lane * 4];
            float4 w1 = *(const float4*)&Wt[f * GG + lane * 4 + 128];
            float4 w2 = *(const float4*)&Wt[f * GG + lane * 4 + 256];
#pragma unroll
            for (int q = 0; q < 4; q++) {
                float x = fv[q][f];
                acc[q][0] += x * w0.x; acc[q][1] += x * w0.y;
                acc[q][2] += x * w0.z; acc[q][3] += x * w0.w;
                acc[q][4] += x * w1.x; acc[q][5] += x * w1.y;
                acc[q][6] += x * w1.z; acc[q][7] += x * w1.w;
                acc[q][8] += x * w2.x; acc[q][9] += x * w2.y;
                acc[q][10] += x * w2.z; acc[q][11] += x * w2.w;
            }
        }
#pragma unroll
        for (int q = 0; q < 4; q++) {
            float* orow = g_gi + (size_t)(rbase + q) * GG;
#pragma unroll
            for (int jj = 0; jj < 3; jj++) {
                *(float4*)&orow[lane * 4 + 128 * jj] =
                    make_float4(acc[q][jj * 4 + 0], acc[q][jj * 4 + 1],
                                acc[q][jj * 4 + 2], acc[q][jj * 4 + 3]);
            }
        }
    }
}

// ---------------- kernel 2: GRU scan, tensor-core tf32 split ----------------
#define GRU_SMEM ((49152 + 2 * 32 * 132) * 4)

__global__ void __launch_bounds__(256, 1) k_gru(const float* __restrict__ bhh) {
    extern __shared__ float sm[];
    float* Bhi_s = sm;
    float* h_hi  = sm + 49152;
    float* h_lo  = h_hi + 32 * 132;
    int tid = threadIdx.x;
    int w = tid >> 5, lane = tid & 31;
    int qr = lane >> 2, qc = lane & 3;
    int hc = w * 16;
    int node0 = blockIdx.x * 32;

    {
        const float4* src = (const float4*)g_Bhi;
        float4* dst = (float4*)Bhi_s;
        for (int i = tid; i < 49152 / 4; i += 256) dst[i] = src[i];
        for (int i = tid; i < 2 * 32 * 132; i += 256) h_hi[i] = 0.f;
    }
    float bR[2][2], bZ[2][2], bN[2][2];
#pragma unroll
    for (int s = 0; s < 2; s++)
#pragma unroll
        for (int jj = 0; jj < 2; jj++) {
            int c = hc + s * 8 + 2 * qc + jj;
            bR[s][jj] = __ldg(&bhh[c]);
            bZ[s][jj] = __ldg(&bhh[128 + c]);
            bN[s][jj] = __ldg(&bhh[256 + c]);
        }
    __syncthreads();

    const float2* Bhi2 = (const float2*)Bhi_s;

    for (int t = 0; t < TT; t++) {
        float gi_[2][2][3][2][2];
#pragma unroll
        for (int m = 0; m < 2; m++)
#pragma unroll
            for (int s = 0; s < 2; s++)
#pragma unroll
                for (int g = 0; g < 3; g++)
#pragma unroll
                    for (int rg = 0; rg < 2; rg++) {
                        int row = m * 16 + qr + rg * 8;
                        float2 v = *(const float2*)(g_gi +
                            ((size_t)t * NN + node0 + row) * GG + g * 128 + hc + s * 8 + 2 * qc);
                        gi_[m][s][g][rg][0] = v.x;
                        gi_[m][s][g][rg][1] = v.y;
                    }

        float d[2][2][3][4];
#pragma unroll
        for (int m = 0; m < 2; m++)
#pragma unroll
            for (int s = 0; s < 2; s++)
#pragma unroll
                for (int g = 0; g < 3; g++)
#pragma unroll
                    for (int j = 0; j < 4; j++) d[m][s][g][j] = 0.f;

        if (t) {
            uint32_t blw[6], nw[6];
            {
                const uint32_t* p = &g_Blo[((0 * 8 + w) * 32 + lane) * 8];
                uint4 v4 = *(const uint4*)p;
                uint2 v2 = *(const uint2*)(p + 4);
                blw[0] = v4.x; blw[1] = v4.y; blw[2] = v4.z;
                blw[3] = v4.w; blw[4] = v2.x; blw[5] = v2.y;
            }
#pragma unroll 2
            for (int kt = 0; kt < 16; kt++) {
                if (kt < 15) {
                    const uint32_t* p = &g_Blo[(((kt + 1) * 8 + w) * 32 + lane) * 8];
                    uint4 v4 = *(const uint4*)p;
                    uint2 v2 = *(const uint2*)(p + 4);
                    nw[0] = v4.x; nw[1] = v4.y; nw[2] = v4.z;
                    nw[3] = v4.w; nw[4] = v2.x; nw[5] = v2.y;
                }
                int kc = kt * 8 + qc;
                uint32_t ah[2][4], al[2][4];
#pragma unroll
                for (int m = 0; m < 2; m++) {
                    int r0 = m * 16 + qr;
                    ah[m][0] = __float_as_uint(h_hi[r0 * 132 + kc]);
                    ah[m][1] = __float_as_uint(h_hi[(r0 + 8) * 132 + kc]);
                    ah[m][2] = __float_as_uint(h_hi[r0 * 132 + kc + 4]);
                    ah[m][3] = __float_as_uint(h_hi[(r0 + 8) * 132 + kc + 4]);
                    al[m][0] = __float_as_uint(h_lo[r0 * 132 + kc]);
                    al[m][1] = __float_as_uint(h_lo[(r0 + 8) * 132 + kc]);
                    al[m][2] = __float_as_uint(h_lo[r0 * 132 + kc + 4]);
                    al[m][3] = __float_as_uint(h_lo[(r0 + 8) * 132 + kc + 4]);
                }
#pragma unroll
                for (int g = 0; g < 3; g++)
#pragma unroll
                    for (int s = 0; s < 2; s++) {
                        int nt = g * 2 + s;
                        float2 bh = Bhi2[((kt * 8 + w) * 6 + nt) * 32 + lane];
                        uint32_t bh0 = __float_as_uint(bh.x);
                        uint32_t bh1 = __float_as_uint(bh.y);
                        uint32_t wlo = blw[nt];
                        uint32_t bl0 = wlo << 16;
                        uint32_t bl1 = wlo & 0xFFFF0000u;
#pragma unroll
                        for (int m = 0; m < 2; m++) {
                            mma_tf32(d[m][s][g], ah[m], bh0, bh1);
                            mma_tf32(d[m][s][g], al[m], bh0, bh1);
                            mma_tf32(d[m][s][g], ah[m], bl0, bl1);
                        }
                    }
#pragma unroll
                for (int i = 0; i < 6; i++) blw[i] = nw[i];
            }
        }

        float hn[2][2][2][2];
#pragma unroll
        for (int m = 0; m < 2; m++)
#pragma unroll
            for (int s = 0; s < 2; s++)
#pragma unroll
                for (int rg = 0; rg < 2; rg++) {
                    int row = m * 16 + qr + rg * 8;
                    int col = hc + s * 8 + 2 * qc;
                    float2 hh = *(const float2*)&h_hi[row * 132 + col];
                    float2 hl = *(const float2*)&h_lo[row * 132 + col];
#pragma unroll
                    for (int jj = 0; jj < 2; jj++) {
                        float hold = jj ? (hh.y + hl.y) : (hh.x + hl.x);
                        int di = rg * 2 + jj;
                        float rr = sigmoid_fast(gi_[m][s][0][rg][jj] + d[m][s][0][di] + bR[s][jj]);
                        float zz = sigmoid_fast(gi_[m][s][1][rg][jj] + d[m][s][1][di] + bZ[s][jj]);
                        float nv = tanh_fast(gi_[m][s][2][rg][jj] + rr * (d[m][s][2][di] + bN[s][jj]));
                        hn[m][s][rg][jj] = (1.f - zz) * nv + zz * hold;
                    }
                }
        __syncthreads();
#pragma unroll
        for (int m = 0; m < 2; m++)
#pragma unroll
            for (int s = 0; s < 2; s++)
#pragma unroll
                for (int rg = 0; rg < 2; rg++) {
                    int row = m * 16 + qr + rg * 8;
                    int col = hc + s * 8 + 2 * qc;
                    float h0 = hn[m][s][rg][0], h1 = hn[m][s][rg][1];
                    uint32_t u0 = f2tf32(h0), u1 = f2tf32(h1);
                    float l0 = h0 - __uint_as_float(u0);
                    float l1 = h1 - __uint_as_float(u1);
                    *(float2*)&h_hi[row * 132 + col] =
                        make_float2(__uint_as_float(u0), __uint_as_float(u1));
                    *(float2*)&h_lo[row * 132 + col] =
                        make_float2(__uint_as_float(f2tf32(l0)), __uint_as_float(f2tf32(l1)));
                }
        __syncthreads();
    }

    for (int i = tid; i < 32 * HH; i += 256) {
        int row = i >> 7, col = i & 127;
        g_support[(size_t)(node0 + row) * HH + col] =
            h_hi[row * 132 + col] + h_lo[row * 132 + col];
    }
}

// ---------------- kernel 3: tensor-core GEMM C[4096,128] = A @ B (+b1+b2) ---
struct GemmJob { const float* A; const float* B; const float* b1; const float* b2; float* C; };
struct GemmJobs { GemmJob j[5]; };

#define GEMM_SMEM 204800

__global__ void __launch_bounds__(256) k_gemm(GemmJobs jobs) {
    GemmJob job = jobs.j[blockIdx.y];
    extern __shared__ char smc[];
    float* As_hi = (float*)smc;                               // [128][132]
    float* Bs_hi = As_hi + 128 * 132;                         // [128][132]
    uint16_t* As_lo = (uint16_t*)(Bs_hi + 128 * 132);         // [128][136]
    uint16_t* Bs_lo = As_lo + 128 * 136;                      // [128][136]
    int tid = threadIdx.x;
    int node0 = blockIdx.x * 128;

    for (int idx = tid; idx < 128 * 128; idx += 256) {
        int r = idx >> 7, c = idx & 127;
        float a = job.A[(size_t)(node0 + r) * HH + c];
        uint32_t ha = f2tf32(a);
        As_hi[r * 132 + c] = __uint_as_float(ha);
        As_lo[r * 136 + c] =
            __bfloat16_as_ushort(__float2bfloat16(a - __uint_as_float(ha)));
        float b = job.B[idx];              // B[k][n] row-major, k=r, n=c
        uint32_t hb = f2tf32(b);
        Bs_hi[r * 132 + c] = __uint_as_float(hb);
        Bs_lo[r * 136 + c] =
            __bfloat16_as_ushort(__float2bfloat16(b - __uint_as_float(hb)));
    }
    __syncthreads();

    int w = tid >> 5, lane = tid & 31;
    int qr = lane >> 2, qc = lane & 3;
    int r0 = w * 16;
    float acc[16][4];
#pragma unroll
    for (int ct = 0; ct < 16; ct++)
#pragma unroll
        for (int j = 0; j < 4; j++) acc[ct][j] = 0.f;

#pragma unroll 1
    for (int kt = 0; kt < 16; kt++) {
        int kc = kt * 8 + qc;
        uint32_t ah[4], al[4];
        ah[0] = __float_as_uint(As_hi[(r0 + qr) * 132 + kc]);
        ah[1] = __float_as_uint(As_hi[(r0 + qr + 8) * 132 + kc]);
        ah[2] = __float_as_uint(As_hi[(r0 + qr) * 132 + kc + 4]);
        ah[3] = __float_as_uint(As_hi[(r0 + qr + 8) * 132 + kc + 4]);
        al[0] = (uint32_t)As_lo[(r0 + qr) * 136 + kc] << 16;
        al[1] = (uint32_t)As_lo[(r0 + qr + 8) * 136 + kc] << 16;
        al[2] = (uint32_t)As_lo[(r0 + qr) * 136 + kc + 4] << 16;
        al[3] = (uint32_t)As_lo[(r0 + qr + 8) * 136 + kc + 4] << 16;
#pragma unroll
        for (int ct = 0; ct < 16; ct++) {
            int n0 = ct * 8;
            uint32_t bh0 = __float_as_uint(Bs_hi[kc * 132 + n0 + qr]);
            uint32_t bh1 = __float_as_uint(Bs_hi[(kc + 4) * 132 + n0 + qr]);
            uint32_t bl0 = (uint32_t)Bs_lo[kc * 136 + n0 + qr] << 16;
            uint32_t bl1 = (uint32_t)Bs_lo[(kc + 4) * 136 + n0 + qr] << 16;
            mma_tf32(acc[ct], ah, bh0, bh1);
            mma_tf32(acc[ct], al, bh0, bh1);
            mma_tf32(acc[ct], ah, bl0, bl1);
        }
    }

#pragma unroll
    for (int ct = 0; ct < 16; ct++) {
        int c0 = ct * 8 + 2 * qc;
        float b0 = 0.f, b1v = 0.f;
        if (job.b1) { b0 += __ldg(&job.b1[c0]); b1v += __ldg(&job.b1[c0 + 1]); }
        if (job.b2) { b0 += __ldg(&job.b2[c0]); b1v += __ldg(&job.b2[c0 + 1]); }
        int r = node0 + r0 + qr;
        *(float2*)&job.C[(size_t)r * HH + c0] =
            make_float2(acc[ct][0] + b0, acc[ct][1] + b1v);
        *(float2*)&job.C[(size_t)(r + 8) * HH + c0] =
            make_float2(acc[ct][2] + b0, acc[ct][3] + b1v);
    }
}

// ---------------- kernel 4: f1/f2 per head -----------------------------------
__global__ void k_f1f2(const float* __restrict__ uP, const float* __restrict__ vP,
                       const float* __restrict__ uN, const float* __restrict__ vN) {
    const float* sup; const float* u; const float* v; float* f1; float* f2;
    if (blockIdx.y == 0) { sup = g_supP; u = uP; v = vP; f1 = g_f1P; f2 = g_f2P; }
    else                 { sup = g_supN; u = uN; v = vN; f1 = g_f1N; f2 = g_f2N; }
    int n = blockIdx.x * 8 + (threadIdx.x >> 5);
    int lane = threadIdx.x & 31;
#pragma unroll
    for (int h = 0; h < NHD; h++) {
        float s = sup[(size_t)n * HH + h * DOD + lane];
        float a = s * u[h * DOD + lane];
        float b = s * v[h * DOD + lane];
        a = warpsum(a); b = warpsum(b);
        if (lane == 0) { f1[h * NN + n] = a; f2[h * NN + n] = b; }
    }
}

// ---------------- kernel 5: GAT masked-attention aggregation -----------------
__global__ void __launch_bounds__(128) k_gat(const float* __restrict__ adjP,
                                             const float* __restrict__ adjN) {
    __shared__ int s_cnt;
    __shared__ int s_list[512];
    __shared__ float s_a[512];
    const float* adj; const float* sup; const float* f1; const float* f2;
    const float* resid; float* outp;
    if (blockIdx.y == 0) { adj = adjP; sup = g_supP; f1 = g_f1P; f2 = g_f2P; resid = g_residP; outp = g_gatP; }
    else                 { adj = adjN; sup = g_supN; f1 = g_f1N; f2 = g_f2N; resid = g_residN; outp = g_gatN; }
    int i = blockIdx.x, tid = threadIdx.x;
    int h = tid >> 5;
    float f2i = f2[h * NN + i];
    float num = 0.f, den = 0.f;

    for (int c0 = 0; c0 < NN; c0 += 16384) {
        if (tid == 0) s_cnt = 0;
        __syncthreads();
        int cend = c0 + 16384; if (cend > NN) cend = NN;
        for (int j = c0 + tid; j < cend; j += 128) {
            float a = adj[(size_t)i * NN + j];
            if (a != 0.f) {
                int p = atomicAdd(&s_cnt, 1);
                s_list[p] = j;
                s_a[p] = a;
            }
        }
        __syncthreads();
        int cnt = s_cnt;
        for (int t = 0; t < cnt; t++) {
            int j = s_list[t];
            float w = f1[h * NN + j] + f2i;
            w = (w > 0.f) ? w : 0.2f * w;
            w *= s_a[t];
            den += w;
            num += w * sup[(size_t)j * HH + tid];
        }
        __syncthreads();
    }
    float d = (den == 0.f) ? 1.f : den;
    outp[(size_t)i * HH + tid] = num / d + resid[(size_t)i * HH + tid];
}

// ---------------- kernel 6: zero colsum --------------------------------------
__global__ void k_zero() { if (threadIdx.x < HH) g_colsum[threadIdx.x] = 0.f; }

// ---------------- kernel 7: semantic attention, warp-per-node ----------------
__global__ void __launch_bounds__(256) k_sem(const float* __restrict__ W1,
                                             const float* __restrict__ b1,
                                             const float* __restrict__ W2) {
    __shared__ float W1s[128 * 65];
    __shared__ float W2s[SEMD], b1s[SEMD];
    __shared__ float semb[8][3][128];
    int tid = threadIdx.x;
    for (int i = tid; i < 128 * 64; i += 256) {
        int k = i >> 6, s = i & 63;
        W1s[k * 65 + s] = W1[i];
    }
    if (tid < SEMD) { W2s[tid] = W2[tid]; b1s[tid] = b1[tid]; }
    __syncthreads();

    int w = tid >> 5, lane = tid & 31;
    float csum[4] = {0.f, 0.f, 0.f, 0.f};
    int nbase = (blockIdx.x * 8 + w) * 8;

    for (int i = 0; i < 8; i++) {
        int n = nbase + i;
        float4 ev[3];
        ev[0] = *(const float4*)&g_selfE[(size_t)n * HH + lane * 4];
        ev[1] = *(const float4*)&g_posE[(size_t)n * HH + lane * 4];
        ev[2] = *(const float4*)&g_negE[(size_t)n * HH + lane * 4];
        __syncwarp();
        *(float4*)&semb[w][0][lane * 4] = ev[0];
        *(float4*)&semb[w][1][lane * 4] = ev[1];
        *(float4*)&semb[w][2][lane * 4] = ev[2];
        __syncwarp();

        float acc[3][2];
#pragma unroll
        for (int e = 0; e < 3; e++) { acc[e][0] = b1s[lane]; acc[e][1] = b1s[lane + 32]; }
#pragma unroll 4
        for (int k = 0; k < HH; k++) {
            float w1a = W1s[k * 65 + lane];
            float w1b = W1s[k * 65 + lane + 32];
            float x0 = semb[w][0][k], x1 = semb[w][1][k], x2 = semb[w][2][k];
            acc[0][0] += x0 * w1a; acc[0][1] += x0 * w1b;
            acc[1][0] += x1 * w1a; acc[1][1] += x1 * w1b;
            acc[2][0] += x2 * w1a; acc[2][1] += x2 * w1b;
        }
        float wv[3];
#pragma unroll
        for (int e = 0; e < 3; e++) {
            float tsum = tanh_fast(acc[e][0]) * W2s[lane] +
                         tanh_fast(acc[e][1]) * W2s[lane + 32];
            wv[e] = warpsum_bfly(tsum);
        }
        float m = fmaxf(wv[0], fmaxf(wv[1], wv[2]));
        float e0 = __expf(wv[0] - m), e1 = __expf(wv[1] - m), e2 = __expf(wv[2] - m);
        float inv = __fdividef(1.f, e0 + e1 + e2);
        float be0 = e0 * inv, be1 = e1 * inv, be2 = e2 * inv;
        float4 f;
        f.x = be0 * ev[0].x + be1 * ev[1].x + be2 * ev[2].x;
        f.y = be0 * ev[0].y + be1 * ev[1].y + be2 * ev[2].y;
        f.z = be0 * ev[0].z + be1 * ev[1].z + be2 * ev[2].z;
        f.w = be0 * ev[0].w + be1 * ev[1].w + be2 * ev[2].w;
        *(float4*)&g_fused[(size_t)n * HH + lane * 4] = f;
        csum[0] += f.x; csum[1] += f.y; csum[2] += f.z; csum[3] += f.w;
    }
    atomicAdd(&g_colsum[lane * 4 + 0], csum[0]);
    atomicAdd(&g_colsum[lane * 4 + 1], csum[1]);
    atomicAdd(&g_colsum[lane * 4 + 2], csum[2]);
    atomicAdd(&g_colsum[lane * 4 + 3], csum[3]);
}

// ---------------- kernel 8: pairnorm + predictor -----------------------------
__global__ void __launch_bounds__(256) k_pred(const float* __restrict__ W1,
                                              const float* __restrict__ b1,
                                              const float* __restrict__ W2,
                                              const float* __restrict__ b2,
                                              float* __restrict__ out) {
    __shared__ float W1s[HH * PHD];
    __shared__ float xns[8][HH];
    int tid = threadIdx.x;
    for (int i = tid; i < HH * PHD; i += 256) W1s[i] = W1[i];
    int w = tid >> 5, lane = tid & 31;
    int n = blockIdx.x * 8 + w;
    float xv[4]; float ss = 0.f;
    const float invN = 1.f / (float)NN;
#pragma unroll
    for (int j = 0; j < 4; j++) {
        int d = lane + j * 32;
        float x = g_fused[(size_t)n * HH + d] - g_colsum[d] * invN;
        xv[j] = x; ss += x * x;
    }
    ss = warpsum(ss);
    ss = __shfl_sync(0xffffffffu, ss, 0);
    float rinv = rsqrtf(1e-6f + ss);
#pragma unroll
    for (int j = 0; j < 4; j++) xns[w][lane + j * 32] = xv[j] * rinv;
    __syncthreads();

    float acc = b1[lane];
#pragma unroll 4
    for (int k = 0; k < HH; k++) acc += xns[w][k] * W1s[k * PHD + lane];
    float hgt = acc > 0.f ? acc : 0.f;
    float o = warpsum(hgt * W2[lane]);
    if (lane == 0) out[n] = sigmoid_fast(o + b2[0]);
}

// ---------------- launch -----------------------------------------------------
extern "C" void kernel_launch(void* const* d_in, const int* in_sizes, int n_in,
                              void* d_out, int out_size) {
    const float* features = (const float*)d_in[0];
    const float* pos_adj  = (const float*)d_in[1];
    const float* neg_adj  = (const float*)d_in[2];
    const float* gru_Wih  = (const float*)d_in[3];
    const float* gru_Whh  = (const float*)d_in[4];
    const float* gru_bih  = (const float*)d_in[5];
    const float* gru_bhh  = (const float*)d_in[6];
    const float* pos_W    = (const float*)d_in[7];
    const float* pos_u    = (const float*)d_in[8];
    const float* pos_v    = (const float*)d_in[9];
    const float* pos_b    = (const float*)d_in[10];
    const float* pos_pW   = (const float*)d_in[11];
    const float* pos_pb   = (const float*)d_in[12];
    const float* neg_W    = (const float*)d_in[13];
    const float* neg_u    = (const float*)d_in[14];
    const float* neg_v    = (const float*)d_in[15];
    const float* neg_b    = (const float*)d_in[16];
    const float* neg_pW   = (const float*)d_in[17];
    const float* neg_pb   = (const float*)d_in[18];
    const float* self_W   = (const float*)d_in[19];
    const float* self_b   = (const float*)d_in[20];
    const float* mpos_W   = (const float*)d_in[21];
    const float* mpos_b   = (const float*)d_in[22];
    const float* mneg_W   = (const float*)d_in[23];
    const float* mneg_b   = (const float*)d_in[24];
    const float* sem_W1   = (const float*)d_in[25];
    const float* sem_b1   = (const float*)d_in[26];
    const float* sem_W2   = (const float*)d_in[27];
    const float* pred_W1  = (const float*)d_in[28];
    const float* pred_b1  = (const float*)d_in[29];
    const float* pred_W2  = (const float*)d_in[30];
    const float* pred_b2  = (const float*)d_in[31];
    float* out = (float*)d_out;

    static bool attr_done = false;
    if (!attr_done) {
        cudaFuncSetAttribute(k_gru, cudaFuncAttributeMaxDynamicSharedMemorySize, GRU_SMEM);
        cudaFuncSetAttribute(k_gemm, cudaFuncAttributeMaxDynamicSharedMemorySize, GEMM_SMEM);
        attr_done = true;
    }

    float *p_support, *p_gatP, *p_gatN, *p_supP, *p_supN;
    float *p_residP, *p_residN, *p_selfE, *p_posE, *p_negE;
    cudaGetSymbolAddress((void**)&p_support, g_support);
    cudaGetSymbolAddress((void**)&p_supP, g_supP);
    cudaGetSymbolAddress((void**)&p_supN, g_supN);
    cudaGetSymbolAddress((void**)&p_residP, g_residP);
    cudaGetSymbolAddress((void**)&p_residN, g_residN);
    cudaGetSymbolAddress((void**)&p_selfE, g_selfE);
    cudaGetSymbolAddress((void**)&p_gatP, g_gatP);
    cudaGetSymbolAddress((void**)&p_gatN, g_gatN);
    cudaGetSymbolAddress((void**)&p_posE, g_posE);
    cudaGetSymbolAddress((void**)&p_negE, g_negE);

    // launch order chosen so the 4th launch (ncu positional capture) = k_gru
    k_prep<<<96, 256>>>(gru_Whh);                                   // 1
    k_zero<<<1, 128>>>();                                           // 2
    k_gi<<<(TT * NN) / 64, 256>>>(features, gru_Wih, gru_bih);      // 3
    k_gru<<<NN / 32, 256, GRU_SMEM>>>(gru_bhh);                     // 4
    {
        GemmJobs jb;
        jb.j[0] = { p_support, pos_W,  nullptr, nullptr, p_supP };
        jb.j[1] = { p_support, neg_W,  nullptr, nullptr, p_supN };
        jb.j[2] = { p_support, pos_pW, pos_b,   pos_pb,  p_residP };
        jb.j[3] = { p_support, neg_pW, neg_b,   neg_pb,  p_residN };
        jb.j[4] = { p_support, self_W, self_b,  nullptr, p_selfE };
        dim3 grid(NN / 128, 5);
        k_gemm<<<grid, 256, GEMM_SMEM>>>(jb);                       // 5
    }
    {
        dim3 grid(NN / 8, 2);
        k_f1f2<<<grid, 256>>>(pos_u, pos_v, neg_u, neg_v);          // 6
    }
    {
        dim3 grid(NN, 2);
        k_gat<<<grid, 128>>>(pos_adj, neg_adj);                     // 7
    }
    {
        GemmJobs jb;
        jb.j[0] = { p_gatP, mpos_W, mpos_b, nullptr, p_posE };
        jb.j[1] = { p_gatN, mneg_W, mneg_b, nullptr, p_negE };
        jb.j[2] = jb.j[0]; jb.j[3] = jb.j[0]; jb.j[4] = jb.j[0];
        dim3 grid(NN / 128, 2);
        k_gemm<<<grid, 256, GEMM_SMEM>>>(jb);                       // 8
    }
    k_sem<<<NN / 64, 256>>>(sem_W1, sem_b1, sem_W2);                // 9
    k_pred<<<NN / 8, 256>>>(pred_W1, pred_b1, pred_W2, pred_b2, out); // 10
}

// round 6
// speedup vs baseline: 6.5401x; 1.1478x over previous
#include <cuda_runtime.h>
#include <cuda_bf16.h>
#include <cstdint>
#include <cstddef>

#define NN 4096
#define TT 24
#define FF 16
#define HH 128
#define GG 384
#define NHD 4
#define DOD 32
#define SEMD 64
#define PHD 32

// ---------------- scratch (static device globals; no runtime allocation) ----
__device__ float g_support[NN * HH];
__device__ float g_supP[NN * HH];
__device__ float g_supN[NN * HH];
__device__ float g_residP[NN * HH];
__device__ float g_residN[NN * HH];
__device__ float g_selfE[NN * HH];
__device__ float g_f1P[NHD * NN];
__device__ float g_f2P[NHD * NN];
__device__ float g_f1N[NHD * NN];
__device__ float g_f2N[NHD * NN];
__device__ float g_gatP[NN * HH];
__device__ float g_gatN[NN * HH];
__device__ float g_posE[NN * HH];
__device__ float g_negE[NN * HH];
__device__ float g_fused[NN * HH];
__device__ float g_colsum[HH];
// fragment-ordered Whh (hi tf32 in smem-staged form, lo bf16 streamed)
__device__ __align__(16) float    g_Bhi[16 * 8 * 6 * 32 * 2];
__device__ __align__(16) uint32_t g_Blo[16 * 8 * 32 * 8];
// fragment-ordered Wih (k=16 -> 2 k-tiles)
__device__ __align__(16) float    g_WihHi[2 * 8 * 6 * 32 * 2];
__device__ __align__(16) uint32_t g_WihLo[2 * 8 * 32 * 8];

__device__ __forceinline__ float warpsum(float v) {
#pragma unroll
    for (int o = 16; o >= 1; o >>= 1) v += __shfl_down_sync(0xffffffffu, v, o);
    return v;
}
__device__ __forceinline__ float warpsum_bfly(float v) {
#pragma unroll
    for (int o = 16; o >= 1; o >>= 1) v += __shfl_xor_sync(0xffffffffu, v, o);
    return v;
}
__device__ __forceinline__ float sigmoid_fast(float x) {
    return __fdividef(1.f, 1.f + __expf(-x));
}
__device__ __forceinline__ float tanh_fast(float x) {
    float e = __expf(-2.f * x);
    return __fdividef(2.f, 1.f + e) - 1.f;
}
__device__ __forceinline__ uint32_t f2tf32(float f) {
    uint32_t u; asm("cvt.rna.tf32.f32 %0, %1;" : "=r"(u) : "f"(f)); return u;
}
__device__ __forceinline__ void mma_tf32(float d[4], const uint32_t a[4],
                                         uint32_t b0, uint32_t b1) {
    asm volatile("mma.sync.aligned.m16n8k8.row.col.f32.tf32.tf32.f32 "
                 "{%0,%1,%2,%3}, {%4,%5,%6,%7}, {%8,%9}, {%0,%1,%2,%3};"
                 : "+f"(d[0]), "+f"(d[1]), "+f"(d[2]), "+f"(d[3])
                 : "r"(a[0]), "r"(a[1]), "r"(a[2]), "r"(a[3]), "r"(b0), "r"(b1));
}

// ---------------- kernel 0a: fragment-ordered Whh (hi tf32 / lo bf16) -------
__global__ void k_prep(const float* __restrict__ Whh) {
    int idx = blockIdx.x * 256 + threadIdx.x;       // 24576 = 16*8*6*32
    if (idx >= 16 * 8 * 6 * 32) return;
    int lane = idx & 31; int r = idx >> 5;
    int nt = r % 6; r /= 6;
    int w = r & 7; int kt = r >> 3;
    int g = nt >> 1, s = nt & 1;
    int n = g * 128 + w * 16 + s * 8 + (lane >> 2);
    float b0 = Whh[n * 128 + kt * 8 + (lane & 3)];
    float b1 = Whh[n * 128 + kt * 8 + (lane & 3) + 4];
    uint32_t h0 = f2tf32(b0), h1 = f2tf32(b1);
    g_Bhi[idx * 2 + 0] = __uint_as_float(h0);
    g_Bhi[idx * 2 + 1] = __uint_as_float(h1);
    __nv_bfloat16 l0 = __float2bfloat16(b0 - __uint_as_float(h0));
    __nv_bfloat16 l1 = __float2bfloat16(b1 - __uint_as_float(h1));
    uint32_t word = (uint32_t)__bfloat16_as_ushort(l0) |
                    ((uint32_t)__bfloat16_as_ushort(l1) << 16);
    g_Blo[((kt * 8 + w) * 32 + lane) * 8 + nt] = word;
}

// ---------------- kernel 0b: fragment-ordered Wih (k=16) --------------------
__global__ void k_prep_wih(const float* __restrict__ Wih) {
    int idx = blockIdx.x * 256 + threadIdx.x;       // 3072 = 2*8*6*32
    if (idx >= 2 * 8 * 6 * 32) return;
    int lane = idx & 31; int r = idx >> 5;
    int nt = r % 6; r /= 6;
    int w = r & 7; int kt = r >> 3;                  // kt in {0,1}
    int g = (nt >> 1) * 128 + w * 16 + (nt & 1) * 8 + (lane >> 2);
    float b0 = Wih[g * FF + kt * 8 + (lane & 3)];
    float b1 = Wih[g * FF + kt * 8 + (lane & 3) + 4];
    uint32_t h0 = f2tf32(b0), h1 = f2tf32(b1);
    g_WihHi[idx * 2 + 0] = __uint_as_float(h0);
    g_WihHi[idx * 2 + 1] = __uint_as_float(h1);
    __nv_bfloat16 l0 = __float2bfloat16(b0 - __uint_as_float(h0));
    __nv_bfloat16 l1 = __float2bfloat16(b1 - __uint_as_float(h1));
    uint32_t word = (uint32_t)__bfloat16_as_ushort(l0) |
                    ((uint32_t)__bfloat16_as_ushort(l1) << 16);
    g_WihLo[((kt * 8 + w) * 32 + lane) * 8 + nt] = word;
}

// ---------------- kernel 2: fused GRU scan (gi computed on the fly) ---------
#define GRU_SMEM ((49152 + 2 * 32 * 132) * 4)

__global__ void __launch_bounds__(256, 1) k_gru(const float* __restrict__ feat,
                                                const float* __restrict__ bih,
                                                const float* __restrict__ bhh) {
    extern __shared__ float sm[];
    float* Bhi_s = sm;
    float* h_hi  = sm + 49152;
    float* h_lo  = h_hi + 32 * 132;
    int tid = threadIdx.x;
    int w = tid >> 5, lane = tid & 31;
    int qr = lane >> 2, qc = lane & 3;
    int hc = w * 16;
    int node0 = blockIdx.x * 32;

    {
        const float4* src = (const float4*)g_Bhi;
        float4* dst = (float4*)Bhi_s;
        for (int i = tid; i < 49152 / 4; i += 256) dst[i] = src[i];
        for (int i = tid; i < 2 * 32 * 132; i += 256) h_hi[i] = 0.f;
    }
    // biases: r/z merged (bih+bhh); n-gate kept split (bih outside r*, bhh inside)
    float bRr[2][2], bRz[2][2], biN[2][2], bhN[2][2];
#pragma unroll
    for (int s = 0; s < 2; s++)
#pragma unroll
        for (int jj = 0; jj < 2; jj++) {
            int c = hc + s * 8 + 2 * qc + jj;
            bRr[s][jj] = __ldg(&bih[c]) + __ldg(&bhh[c]);
            bRz[s][jj] = __ldg(&bih[128 + c]) + __ldg(&bhh[128 + c]);
            biN[s][jj] = __ldg(&bih[256 + c]);
            bhN[s][jj] = __ldg(&bhh[256 + c]);
        }
    __syncthreads();

    const float2* Bhi2 = (const float2*)Bhi_s;
    const float2* WihHi2 = (const float2*)g_WihHi;

    for (int t = 0; t < TT; t++) {
        // ---- issue x loads early (raw fp32) : [m][kt][frag of 4] ----
        float xv[2][2][4];
#pragma unroll
        for (int m = 0; m < 2; m++)
#pragma unroll
            for (int kt = 0; kt < 2; kt++) {
                const float* base = feat + (size_t)(node0 + m * 16) * (TT * FF) + t * FF;
                int k0 = kt * 8 + qc;
                xv[m][kt][0] = __ldg(base + (size_t)qr * (TT * FF) + k0);
                xv[m][kt][1] = __ldg(base + (size_t)(qr + 8) * (TT * FF) + k0);
                xv[m][kt][2] = __ldg(base + (size_t)qr * (TT * FF) + k0 + 4);
                xv[m][kt][3] = __ldg(base + (size_t)(qr + 8) * (TT * FF) + k0 + 4);
            }

        float d[2][2][3][4];   // h-part accumulators (r,z,n)
        float dx[2][2][4];     // x-part of n-gate (kept separate)
#pragma unroll
        for (int m = 0; m < 2; m++)
#pragma unroll
            for (int s = 0; s < 2; s++) {
#pragma unroll
                for (int g = 0; g < 3; g++)
#pragma unroll
                    for (int j = 0; j < 4; j++) d[m][s][g][j] = 0.f;
#pragma unroll
                for (int j = 0; j < 4; j++) dx[m][s][j] = 0.f;
            }

        // ---- h @ Whh^T (tensor cores, 3-term tf32 split) ----
        if (t) {
            uint32_t blw[6], nw[6];
            {
                const uint32_t* p = &g_Blo[((0 * 8 + w) * 32 + lane) * 8];
                uint4 v4 = *(const uint4*)p;
                uint2 v2 = *(const uint2*)(p + 4);
                blw[0] = v4.x; blw[1] = v4.y; blw[2] = v4.z;
                blw[3] = v4.w; blw[4] = v2.x; blw[5] = v2.y;
            }
#pragma unroll 2
            for (int kt = 0; kt < 16; kt++) {
                if (kt < 15) {
                    const uint32_t* p = &g_Blo[(((kt + 1) * 8 + w) * 32 + lane) * 8];
                    uint4 v4 = *(const uint4*)p;
                    uint2 v2 = *(const uint2*)(p + 4);
                    nw[0] = v4.x; nw[1] = v4.y; nw[2] = v4.z;
                    nw[3] = v4.w; nw[4] = v2.x; nw[5] = v2.y;
                }
                int kc = kt * 8 + qc;
                uint32_t ah[2][4], al[2][4];
#pragma unroll
                for (int m = 0; m < 2; m++) {
                    int r0 = m * 16 + qr;
                    ah[m][0] = __float_as_uint(h_hi[r0 * 132 + kc]);
                    ah[m][1] = __float_as_uint(h_hi[(r0 + 8) * 132 + kc]);
                    ah[m][2] = __float_as_uint(h_hi[r0 * 132 + kc + 4]);
                    ah[m][3] = __float_as_uint(h_hi[(r0 + 8) * 132 + kc + 4]);
                    al[m][0] = __float_as_uint(h_lo[r0 * 132 + kc]);
                    al[m][1] = __float_as_uint(h_lo[(r0 + 8) * 132 + kc]);
                    al[m][2] = __float_as_uint(h_lo[r0 * 132 + kc + 4]);
                    al[m][3] = __float_as_uint(h_lo[(r0 + 8) * 132 + kc + 4]);
                }
#pragma unroll
                for (int g = 0; g < 3; g++)
#pragma unroll
                    for (int s = 0; s < 2; s++) {
                        int nt = g * 2 + s;
                        float2 bh = Bhi2[((kt * 8 + w) * 6 + nt) * 32 + lane];
                        uint32_t bh0 = __float_as_uint(bh.x);
                        uint32_t bh1 = __float_as_uint(bh.y);
                        uint32_t wlo = blw[nt];
                        uint32_t bl0 = wlo << 16;
                        uint32_t bl1 = wlo & 0xFFFF0000u;
#pragma unroll
                        for (int m = 0; m < 2; m++) {
                            mma_tf32(d[m][s][g], ah[m], bh0, bh1);
                            mma_tf32(d[m][s][g], al[m], bh0, bh1);
                            mma_tf32(d[m][s][g], ah[m], bl0, bl1);
                        }
                    }
#pragma unroll
                for (int i = 0; i < 6; i++) blw[i] = nw[i];
            }
        }

        // ---- x @ Wih^T fused (gi on the fly) ----
#pragma unroll
        for (int kt = 0; kt < 2; kt++) {
            uint32_t xh[2][4], xl[2][4];
#pragma unroll
            for (int m = 0; m < 2; m++)
#pragma unroll
                for (int j = 0; j < 4; j++) {
                    float v = xv[m][kt][j];
                    uint32_t hi = f2tf32(v);
                    xh[m][j] = hi;
                    xl[m][j] = f2tf32(v - __uint_as_float(hi));
                }
            const uint32_t* lp = &g_WihLo[((kt * 8 + w) * 32 + lane) * 8];
            uint4 lv4 = *(const uint4*)lp;
            uint2 lv2 = *(const uint2*)(lp + 4);
            uint32_t wloW[6] = {lv4.x, lv4.y, lv4.z, lv4.w, lv2.x, lv2.y};
#pragma unroll
            for (int g = 0; g < 3; g++)
#pragma unroll
                for (int s = 0; s < 2; s++) {
                    int nt = g * 2 + s;
                    float2 bh = WihHi2[((kt * 8 + w) * 6 + nt) * 32 + lane];
                    uint32_t bh0 = __float_as_uint(bh.x);
                    uint32_t bh1 = __float_as_uint(bh.y);
                    uint32_t wl = wloW[nt];
                    uint32_t bl0 = wl << 16;
                    uint32_t bl1 = wl & 0xFFFF0000u;
#pragma unroll
                    for (int m = 0; m < 2; m++) {
                        float* D = (g == 2) ? dx[m][s] : d[m][s][g];
                        mma_tf32(D, xh[m], bh0, bh1);
                        mma_tf32(D, xl[m], bh0, bh1);
                        mma_tf32(D, xh[m], bl0, bl1);
                    }
                }
        }

        // ---- gate math ----
        float hn[2][2][2][2];
#pragma unroll
        for (int m = 0; m < 2; m++)
#pragma unroll
            for (int s = 0; s < 2; s++)
#pragma unroll
                for (int rg = 0; rg < 2; rg++) {
                    int row = m * 16 + qr + rg * 8;
                    int col = hc + s * 8 + 2 * qc;
                    float2 hh = *(const float2*)&h_hi[row * 132 + col];
                    float2 hl = *(const float2*)&h_lo[row * 132 + col];
#pragma unroll
                    for (int jj = 0; jj < 2; jj++) {
                        float hold = jj ? (hh.y + hl.y) : (hh.x + hl.x);
                        int di = rg * 2 + jj;
                        float rr = sigmoid_fast(d[m][s][0][di] + bRr[s][jj]);
                        float zz = sigmoid_fast(d[m][s][1][di] + bRz[s][jj]);
                        float nv = tanh_fast(dx[m][s][di] + biN[s][jj] +
                                             rr * (d[m][s][2][di] + bhN[s][jj]));
                        hn[m][s][rg][jj] = (1.f - zz) * nv + zz * hold;
                    }
                }
        __syncthreads();
#pragma unroll
        for (int m = 0; m < 2; m++)
#pragma unroll
            for (int s = 0; s < 2; s++)
#pragma unroll
                for (int rg = 0; rg < 2; rg++) {
                    int row = m * 16 + qr + rg * 8;
                    int col = hc + s * 8 + 2 * qc;
                    float h0 = hn[m][s][rg][0], h1 = hn[m][s][rg][1];
                    uint32_t u0 = f2tf32(h0), u1 = f2tf32(h1);
                    float l0 = h0 - __uint_as_float(u0);
                    float l1 = h1 - __uint_as_float(u1);
                    *(float2*)&h_hi[row * 132 + col] =
                        make_float2(__uint_as_float(u0), __uint_as_float(u1));
                    *(float2*)&h_lo[row * 132 + col] =
                        make_float2(__uint_as_float(f2tf32(l0)), __uint_as_float(f2tf32(l1)));
                }
        __syncthreads();
    }

    for (int i = tid; i < 32 * HH; i += 256) {
        int row = i >> 7, col = i & 127;
        g_support[(size_t)(node0 + row) * HH + col] =
            h_hi[row * 132 + col] + h_lo[row * 132 + col];
    }
}

// ---------------- kernel 3: tensor-core GEMM C[4096,128] = A @ B (+b1+b2) ---
struct GemmJob { const float* A; const float* B; const float* b1; const float* b2; float* C; };
struct GemmJobs { GemmJob j[5]; };

#define GEMM_SMEM 204800

__global__ void __launch_bounds__(256) k_gemm(GemmJobs jobs) {
    GemmJob job = jobs.j[blockIdx.y];
    extern __shared__ char smc[];
    float* As_hi = (float*)smc;                               // [128][132]
    float* Bs_hi = As_hi + 128 * 132;                         // [128][132]
    uint16_t* As_lo = (uint16_t*)(Bs_hi + 128 * 132);         // [128][136]
    uint16_t* Bs_lo = As_lo + 128 * 136;                      // [128][136]
    int tid = threadIdx.x;
    int node0 = blockIdx.x * 128;

    for (int idx = tid; idx < 128 * 128; idx += 256) {
        int r = idx >> 7, c = idx & 127;
        float a = job.A[(size_t)(node0 + r) * HH + c];
        uint32_t ha = f2tf32(a);
        As_hi[r * 132 + c] = __uint_as_float(ha);
        As_lo[r * 136 + c] =
            __bfloat16_as_ushort(__float2bfloat16(a - __uint_as_float(ha)));
        float b = job.B[idx];
        uint32_t hb = f2tf32(b);
        Bs_hi[r * 132 + c] = __uint_as_float(hb);
        Bs_lo[r * 136 + c] =
            __bfloat16_as_ushort(__float2bfloat16(b - __uint_as_float(hb)));
    }
    __syncthreads();

    int w = tid >> 5, lane = tid & 31;
    int qr = lane >> 2, qc = lane & 3;
    int r0 = w * 16;
    float acc[16][4];
#pragma unroll
    for (int ct = 0; ct < 16; ct++)
#pragma unroll
        for (int j = 0; j < 4; j++) acc[ct][j] = 0.f;

#pragma unroll 1
    for (int kt = 0; kt < 16; kt++) {
        int kc = kt * 8 + qc;
        uint32_t ah[4], al[4];
        ah[0] = __float_as_uint(As_hi[(r0 + qr) * 132 + kc]);
        ah[1] = __float_as_uint(As_hi[(r0 + qr + 8) * 132 + kc]);
        ah[2] = __float_as_uint(As_hi[(r0 + qr) * 132 + kc + 4]);
        ah[3] = __float_as_uint(As_hi[(r0 + qr + 8) * 132 + kc + 4]);
        al[0] = (uint32_t)As_lo[(r0 + qr) * 136 + kc] << 16;
        al[1] = (uint32_t)As_lo[(r0 + qr + 8) * 136 + kc] << 16;
        al[2] = (uint32_t)As_lo[(r0 + qr) * 136 + kc + 4] << 16;
        al[3] = (uint32_t)As_lo[(r0 + qr + 8) * 136 + kc + 4] << 16;
#pragma unroll
        for (int ct = 0; ct < 16; ct++) {
            int n0 = ct * 8;
            uint32_t bh0 = __float_as_uint(Bs_hi[kc * 132 + n0 + qr]);
            uint32_t bh1 = __float_as_uint(Bs_hi[(kc + 4) * 132 + n0 + qr]);
            uint32_t bl0 = (uint32_t)Bs_lo[kc * 136 + n0 + qr] << 16;
            uint32_t bl1 = (uint32_t)Bs_lo[(kc + 4) * 136 + n0 + qr] << 16;
            mma_tf32(acc[ct], ah, bh0, bh1);
            mma_tf32(acc[ct], al, bh0, bh1);
            mma_tf32(acc[ct], ah, bl0, bl1);
        }
    }

#pragma unroll
    for (int ct = 0; ct < 16; ct++) {
        int c0 = ct * 8 + 2 * qc;
        float b0 = 0.f, b1v = 0.f;
        if (job.b1) { b0 += __ldg(&job.b1[c0]); b1v += __ldg(&job.b1[c0 + 1]); }
        if (job.b2) { b0 += __ldg(&job.b2[c0]); b1v += __ldg(&job.b2[c0 + 1]); }
        int r = node0 + r0 + qr;
        *(float2*)&job.C[(size_t)r * HH + c0] =
            make_float2(acc[ct][0] + b0, acc[ct][1] + b1v);
        *(float2*)&job.C[(size_t)(r + 8) * HH + c0] =
            make_float2(acc[ct][2] + b0, acc[ct][3] + b1v);
    }
}

// ---------------- kernel 4: f1/f2 per head -----------------------------------
__global__ void k_f1f2(const float* __restrict__ uP, const float* __restrict__ vP,
                       const float* __restrict__ uN, const float* __restrict__ vN) {
    const float* sup; const float* u; const float* v; float* f1; float* f2;
    if (blockIdx.y == 0) { sup = g_supP; u = uP; v = vP; f1 = g_f1P; f2 = g_f2P; }
    else                 { sup = g_supN; u = uN; v = vN; f1 = g_f1N; f2 = g_f2N; }
    int n = blockIdx.x * 8 + (threadIdx.x >> 5);
    int lane = threadIdx.x & 31;
#pragma unroll
    for (int h = 0; h < NHD; h++) {
        float s = sup[(size_t)n * HH + h * DOD + lane];
        float a = s * u[h * DOD + lane];
        float b = s * v[h * DOD + lane];
        a = warpsum(a); b = warpsum(b);
        if (lane == 0) { f1[h * NN + n] = a; f2[h * NN + n] = b; }
    }
}

// ---------------- kernel 5: GAT masked-attention aggregation -----------------
__global__ void __launch_bounds__(128) k_gat(const float* __restrict__ adjP,
                                             const float* __restrict__ adjN) {
    __shared__ int s_cnt;
    __shared__ int s_list[512];
    __shared__ float s_a[512];
    const float* adj; const float* sup; const float* f1; const float* f2;
    const float* resid; float* outp;
    if (blockIdx.y == 0) { adj = adjP; sup = g_supP; f1 = g_f1P; f2 = g_f2P; resid = g_residP; outp = g_gatP; }
    else                 { adj = adjN; sup = g_supN; f1 = g_f1N; f2 = g_f2N; resid = g_residN; outp = g_gatN; }
    int i = blockIdx.x, tid = threadIdx.x;
    int h = tid >> 5;
    float f2i = f2[h * NN + i];
    float num = 0.f, den = 0.f;

    for (int c0 = 0; c0 < NN; c0 += 16384) {
        if (tid == 0) s_cnt = 0;
        __syncthreads();
        int cend = c0 + 16384; if (cend > NN) cend = NN;
        for (int j = c0 + tid; j < cend; j += 128) {
            float a = adj[(size_t)i * NN + j];
            if (a != 0.f) {
                int p = atomicAdd(&s_cnt, 1);
                s_list[p] = j;
                s_a[p] = a;
            }
        }
        __syncthreads();
        int cnt = s_cnt;
        for (int t = 0; t < cnt; t++) {
            int j = s_list[t];
            float w = f1[h * NN + j] + f2i;
            w = (w > 0.f) ? w : 0.2f * w;
            w *= s_a[t];
            den += w;
            num += w * sup[(size_t)j * HH + tid];
        }
        __syncthreads();
    }
    float d = (den == 0.f) ? 1.f : den;
    outp[(size_t)i * HH + tid] = num / d + resid[(size_t)i * HH + tid];
}

// ---------------- kernel 6: zero colsum --------------------------------------
__global__ void k_zero() { if (threadIdx.x < HH) g_colsum[threadIdx.x] = 0.f; }

// ---------------- kernel 7: semantic attention, warp-per-node ----------------
__global__ void __launch_bounds__(256) k_sem(const float* __restrict__ W1,
                                             const float* __restrict__ b1,
                                             const float* __restrict__ W2) {
    __shared__ float W1s[128 * 65];
    __shared__ float W2s[SEMD], b1s[SEMD];
    __shared__ float semb[8][3][128];
    int tid = threadIdx.x;
    for (int i = tid; i < 128 * 64; i += 256) {
        int k = i >> 6, s = i & 63;
        W1s[k * 65 + s] = W1[i];
    }
    if (tid < SEMD) { W2s[tid] = W2[tid]; b1s[tid] = b1[tid]; }
    __syncthreads();

    int w = tid >> 5, lane = tid & 31;
    float csum[4] = {0.f, 0.f, 0.f, 0.f};
    int nbase = (blockIdx.x * 8 + w) * 8;

    for (int i = 0; i < 8; i++) {
        int n = nbase + i;
        float4 ev[3];
        ev[0] = *(const float4*)&g_selfE[(size_t)n * HH + lane * 4];
        ev[1] = *(const float4*)&g_posE[(size_t)n * HH + lane * 4];
        ev[2] = *(const float4*)&g_negE[(size_t)n * HH + lane * 4];
        __syncwarp();
        *(float4*)&semb[w][0][lane * 4] = ev[0];
        *(float4*)&semb[w][1][lane * 4] = ev[1];
        *(float4*)&semb[w][2][lane * 4] = ev[2];
        __syncwarp();

        float acc[3][2];
#pragma unroll
        for (int e = 0; e < 3; e++) { acc[e][0] = b1s[lane]; acc[e][1] = b1s[lane + 32]; }
#pragma unroll 4
        for (int k = 0; k < HH; k++) {
            float w1a = W1s[k * 65 + lane];
            float w1b = W1s[k * 65 + lane + 32];
            float x0 = semb[w][0][k], x1 = semb[w][1][k], x2 = semb[w][2][k];
            acc[0][0] += x0 * w1a; acc[0][1] += x0 * w1b;
            acc[1][0] += x1 * w1a; acc[1][1] += x1 * w1b;
            acc[2][0] += x2 * w1a; acc[2][1] += x2 * w1b;
        }
        float wv[3];
#pragma unroll
        for (int e = 0; e < 3; e++) {
            float tsum = tanh_fast(acc[e][0]) * W2s[lane] +
                         tanh_fast(acc[e][1]) * W2s[lane + 32];
            wv[e] = warpsum_bfly(tsum);
        }
        float m = fmaxf(wv[0], fmaxf(wv[1], wv[2]));
        float e0 = __expf(wv[0] - m), e1 = __expf(wv[1] - m), e2 = __expf(wv[2] - m);
        float inv = __fdividef(1.f, e0 + e1 + e2);
        float be0 = e0 * inv, be1 = e1 * inv, be2 = e2 * inv;
        float4 f;
        f.x = be0 * ev[0].x + be1 * ev[1].x + be2 * ev[2].x;
        f.y = be0 * ev[0].y + be1 * ev[1].y + be2 * ev[2].y;
        f.z = be0 * ev[0].z + be1 * ev[1].z + be2 * ev[2].z;
        f.w = be0 * ev[0].w + be1 * ev[1].w + be2 * ev[2].w;
        *(float4*)&g_fused[(size_t)n * HH + lane * 4] = f;
        csum[0] += f.x; csum[1] += f.y; csum[2] += f.z; csum[3] += f.w;
    }
    atomicAdd(&g_colsum[lane * 4 + 0], csum[0]);
    atomicAdd(&g_colsum[lane * 4 + 1], csum[1]);
    atomicAdd(&g_colsum[lane * 4 + 2], csum[2]);
    atomicAdd(&g_colsum[lane * 4 + 3], csum[3]);
}

// ---------------- kernel 8: pairnorm + predictor -----------------------------
__global__ void __launch_bounds__(256) k_pred(const float* __restrict__ W1,
                                              const float* __restrict__ b1,
                                              const float* __restrict__ W2,
                                              const float* __restrict__ b2,
                                              float* __restrict__ out) {
    __shared__ float W1s[HH * PHD];
    __shared__ float xns[8][HH];
    int tid = threadIdx.x;
    for (int i = tid; i < HH * PHD; i += 256) W1s[i] = W1[i];
    int w = tid >> 5, lane = tid & 31;
    int n = blockIdx.x * 8 + w;
    float xv[4]; float ss = 0.f;
    const float invN = 1.f / (float)NN;
#pragma unroll
    for (int j = 0; j < 4; j++) {
        int d = lane + j * 32;
        float x = g_fused[(size_t)n * HH + d] - g_colsum[d] * invN;
        xv[j] = x; ss += x * x;
    }
    ss = warpsum(ss);
    ss = __shfl_sync(0xffffffffu, ss, 0);
    float rinv = rsqrtf(1e-6f + ss);
#pragma unroll
    for (int j = 0; j < 4; j++) xns[w][lane + j * 32] = xv[j] * rinv;
    __syncthreads();

    float acc = b1[lane];
#pragma unroll 4
    for (int k = 0; k < HH; k++) acc += xns[w][k] * W1s[k * PHD + lane];
    float hgt = acc > 0.f ? acc : 0.f;
    float o = warpsum(hgt * W2[lane]);
    if (lane == 0) out[n] = sigmoid_fast(o + b2[0]);
}

// ---------------- launch -----------------------------------------------------
extern "C" void kernel_launch(void* const* d_in, const int* in_sizes, int n_in,
                              void* d_out, int out_size) {
    const float* features = (const float*)d_in[0];
    const float* pos_adj  = (const float*)d_in[1];
    const float* neg_adj  = (const float*)d_in[2];
    const float* gru_Wih  = (const float*)d_in[3];
    const float* gru_Whh  = (const float*)d_in[4];
    const float* gru_bih  = (const float*)d_in[5];
    const float* gru_bhh  = (const float*)d_in[6];
    const float* pos_W    = (const float*)d_in[7];
    const float* pos_u    = (const float*)d_in[8];
    const float* pos_v    = (const float*)d_in[9];
    const float* pos_b    = (const float*)d_in[10];
    const float* pos_pW   = (const float*)d_in[11];
    const float* pos_pb   = (const float*)d_in[12];
    const float* neg_W    = (const float*)d_in[13];
    const float* neg_u    = (const float*)d_in[14];
    const float* neg_v    = (const float*)d_in[15];
    const float* neg_b    = (const float*)d_in[16];
    const float* neg_pW   = (const float*)d_in[17];
    const float* neg_pb   = (const float*)d_in[18];
    const float* self_W   = (const float*)d_in[19];
    const float* self_b   = (const float*)d_in[20];
    const float* mpos_W   = (const float*)d_in[21];
    const float* mpos_b   = (const float*)d_in[22];
    const float* mneg_W   = (const float*)d_in[23];
    const float* mneg_b   = (const float*)d_in[24];
    const float* sem_W1   = (const float*)d_in[25];
    const float* sem_b1   = (const float*)d_in[26];
    const float* sem_W2   = (const float*)d_in[27];
    const float* pred_W1  = (const float*)d_in[28];
    const float* pred_b1  = (const float*)d_in[29];
    const float* pred_W2  = (const float*)d_in[30];
    const float* pred_b2  = (const float*)d_in[31];
    float* out = (float*)d_out;

    static bool attr_done = false;
    if (!attr_done) {
        cudaFuncSetAttribute(k_gru, cudaFuncAttributeMaxDynamicSharedMemorySize, GRU_SMEM);
        cudaFuncSetAttribute(k_gemm, cudaFuncAttributeMaxDynamicSharedMemorySize, GEMM_SMEM);
        attr_done = true;
    }

    float *p_support, *p_gatP, *p_gatN, *p_supP, *p_supN;
    float *p_residP, *p_residN, *p_selfE, *p_posE, *p_negE;
    cudaGetSymbolAddress((void**)&p_support, g_support);
    cudaGetSymbolAddress((void**)&p_supP, g_supP);
    cudaGetSymbolAddress((void**)&p_supN, g_supN);
    cudaGetSymbolAddress((void**)&p_residP, g_residP);
    cudaGetSymbolAddress((void**)&p_residN, g_residN);
    cudaGetSymbolAddress((void**)&p_selfE, g_selfE);
    cudaGetSymbolAddress((void**)&p_gatP, g_gatP);
    cudaGetSymbolAddress((void**)&p_gatN, g_gatN);
    cudaGetSymbolAddress((void**)&p_posE, g_posE);
    cudaGetSymbolAddress((void**)&p_negE, g_negE);

    k_prep<<<96, 256>>>(gru_Whh);                                   // 1
    k_prep_wih<<<12, 256>>>(gru_Wih);                               // 2
    k_zero<<<1, 128>>>();                                           // 3
    k_gru<<<NN / 32, 256, GRU_SMEM>>>(features, gru_bih, gru_bhh);  // 4
    {
        GemmJobs jb;
        jb.j[0] = { p_support, pos_W,  nullptr, nullptr, p_supP };
        jb.j[1] = { p_support, neg_W,  nullptr, nullptr, p_supN };
        jb.j[2] = { p_support, pos_pW, pos_b,   pos_pb,  p_residP };
        jb.j[3] = { p_support, neg_pW, neg_b,   neg_pb,  p_residN };
        jb.j[4] = { p_support, self_W, self_b,  nullptr, p_selfE };
        dim3 grid(NN / 128, 5);
        k_gemm<<<grid, 256, GEMM_SMEM>>>(jb);                       // 5
    }
    {
        dim3 grid(NN / 8, 2);
        k_f1f2<<<grid, 256>>>(pos_u, pos_v, neg_u, neg_v);          // 6
    }
    {
        dim3 grid(NN, 2);
        k_gat<<<grid, 128>>>(pos_adj, neg_adj);                     // 7
    }
    {
        GemmJobs jb;
        jb.j[0] = { p_gatP, mpos_W, mpos_b, nullptr, p_posE };
        jb.j[1] = { p_gatN, mneg_W, mneg_b, nullptr, p_negE };
        jb.j[2] = jb.j[0]; jb.j[3] = jb.j[0]; jb.j[4] = jb.j[0];
        dim3 grid(NN / 128, 2);
        k_gemm<<<grid, 256, GEMM_SMEM>>>(jb);                       // 8
    }
    k_sem<<<NN / 64, 256>>>(sem_W1, sem_b1, sem_W2);                // 9
    k_pred<<<NN / 8, 256>>>(pred_W1, pred_b1, pred_W2, pred_b2, out); // 10
}

// round 7
// speedup vs baseline: 6.7151x; 1.0268x over previous
#include <cuda_runtime.h>
#include <cuda_bf16.h>
#include <cstdint>
#include <cstddef>

#define NN 4096
#define TT 24
#define FF 16
#define HH 128
#define GG 384
#define NHD 4
#define DOD 32
#define SEMD 64
#define PHD 32

// ---------------- scratch (static device globals; no runtime allocation) ----
__device__ float g_support[NN * HH];
__device__ float g_supP[NN * HH];
__device__ float g_supN[NN * HH];
__device__ float g_residP[NN * HH];
__device__ float g_residN[NN * HH];
__device__ float g_selfE[NN * HH];
__device__ float g_f1P[NHD * NN];
__device__ float g_f2P[NHD * NN];
__device__ float g_f1N[NHD * NN];
__device__ float g_f2N[NHD * NN];
__device__ float g_gatP[NN * HH];
__device__ float g_gatN[NN * HH];
__device__ float g_posE[NN * HH];
__device__ float g_negE[NN * HH];
__device__ float g_fused[NN * HH];
__device__ float g_colsum[HH];
// fragment-ordered Whh: hi tf32 (smem-staged), lo bf16 (uint4-per-warp layout)
__device__ __align__(16) float    g_Bhi[16 * 8 * 6 * 32 * 2];        // 49152 floats
__device__ __align__(16) uint32_t g_Blo[16 * 8 * 2 * 32 * 4];        // [kt][w8][s][lane][g(3)+pad]
// fragment-ordered Wih (k=16 -> 2 k-tiles)
__device__ __align__(16) float    g_WihHi[2 * 8 * 6 * 32 * 2];
__device__ __align__(16) uint32_t g_WihLo[2 * 8 * 2 * 32 * 4];

__device__ __forceinline__ float warpsum(float v) {
#pragma unroll
    for (int o = 16; o >= 1; o >>= 1) v += __shfl_down_sync(0xffffffffu, v, o);
    return v;
}
__device__ __forceinline__ float warpsum_bfly(float v) {
#pragma unroll
    for (int o = 16; o >= 1; o >>= 1) v += __shfl_xor_sync(0xffffffffu, v, o);
    return v;
}
__device__ __forceinline__ float sigmoid_fast(float x) {
    return __fdividef(1.f, 1.f + __expf(-x));
}
__device__ __forceinline__ float tanh_fast(float x) {
    float e = __expf(-2.f * x);
    return __fdividef(2.f, 1.f + e) - 1.f;
}
__device__ __forceinline__ uint32_t f2tf32(float f) {
    uint32_t u; asm("cvt.rna.tf32.f32 %0, %1;" : "=r"(u) : "f"(f)); return u;
}
__device__ __forceinline__ void mma_tf32(float d[4], const uint32_t a[4],
                                         uint32_t b0, uint32_t b1) {
    asm volatile("mma.sync.aligned.m16n8k8.row.col.f32.tf32.tf32.f32 "
                 "{%0,%1,%2,%3}, {%4,%5,%6,%7}, {%8,%9}, {%0,%1,%2,%3};"
                 : "+f"(d[0]), "+f"(d[1]), "+f"(d[2]), "+f"(d[3])
                 : "r"(a[0]), "r"(a[1]), "r"(a[2]), "r"(a[3]), "r"(b0), "r"(b1));
}

// ---------------- kernel 0a: fragment-ordered Whh (hi tf32 / lo bf16) -------
__global__ void k_prep(const float* __restrict__ Whh) {
    int idx = blockIdx.x * 256 + threadIdx.x;       // 24576 = 16*8*6*32
    if (idx >= 16 * 8 * 6 * 32) return;
    int lane = idx & 31; int r = idx >> 5;
    int nt = r % 6; r /= 6;
    int w8 = r & 7; int kt = r >> 3;
    int g = nt >> 1, s = nt & 1;
    int n = g * 128 + w8 * 16 + s * 8 + (lane >> 2);
    float b0 = Whh[n * 128 + kt * 8 + (lane & 3)];
    float b1 = Whh[n * 128 + kt * 8 + (lane & 3) + 4];
    uint32_t h0 = f2tf32(b0), h1 = f2tf32(b1);
    g_Bhi[idx * 2 + 0] = __uint_as_float(h0);
    g_Bhi[idx * 2 + 1] = __uint_as_float(h1);
    __nv_bfloat16 l0 = __float2bfloat16(b0 - __uint_as_float(h0));
    __nv_bfloat16 l1 = __float2bfloat16(b1 - __uint_as_float(h1));
    uint32_t word = (uint32_t)__bfloat16_as_ushort(l0) |
                    ((uint32_t)__bfloat16_as_ushort(l1) << 16);
    g_Blo[((((kt * 8 + w8) * 2 + s) * 32) + lane) * 4 + g] = word;
}

// ---------------- kernel 0b: fragment-ordered Wih (k=16) --------------------
__global__ void k_prep_wih(const float* __restrict__ Wih) {
    int idx = blockIdx.x * 256 + threadIdx.x;       // 3072 = 2*8*6*32
    if (idx >= 2 * 8 * 6 * 32) return;
    int lane = idx & 31; int r = idx >> 5;
    int nt = r % 6; r /= 6;
    int w8 = r & 7; int kt = r >> 3;                 // kt in {0,1}
    int g = nt >> 1, s = nt & 1;
    int n = g * 128 + w8 * 16 + s * 8 + (lane >> 2);
    float b0 = Wih[n * FF + kt * 8 + (lane & 3)];
    float b1 = Wih[n * FF + kt * 8 + (lane & 3) + 4];
    uint32_t h0 = f2tf32(b0), h1 = f2tf32(b1);
    g_WihHi[idx * 2 + 0] = __uint_as_float(h0);
    g_WihHi[idx * 2 + 1] = __uint_as_float(h1);
    __nv_bfloat16 l0 = __float2bfloat16(b0 - __uint_as_float(h0));
    __nv_bfloat16 l1 = __float2bfloat16(b1 - __uint_as_float(h1));
    uint32_t word = (uint32_t)__bfloat16_as_ushort(l0) |
                    ((uint32_t)__bfloat16_as_ushort(l1) << 16);
    g_WihLo[((((kt * 8 + w8) * 2 + s) * 32) + lane) * 4 + g] = word;
}

// ---------------- kernel 2: fused GRU scan, 512 threads ----------------------
#define GRU_SMEM ((49152 + 2 * 32 * 132) * 4)

__global__ void __launch_bounds__(512, 1) k_gru(const float* __restrict__ feat,
                                                const float* __restrict__ bih,
                                                const float* __restrict__ bhh) {
    extern __shared__ float sm[];
    float* Bhi_s = sm;
    float* h_hi  = sm + 49152;
    float* h_lo  = h_hi + 32 * 132;
    int tid = threadIdx.x;
    int w = tid >> 5, lane = tid & 31;
    int w8 = w >> 1, s = w & 1;
    int qr = lane >> 2, qc = lane & 3;
    int hc = w * 8;                       // 8 output columns per warp
    int node0 = blockIdx.x * 32;

    {
        const float4* src = (const float4*)g_Bhi;
        float4* dst = (float4*)Bhi_s;
        for (int i = tid; i < 49152 / 4; i += 512) dst[i] = src[i];
        for (int i = tid; i < 2 * 32 * 132; i += 512) h_hi[i] = 0.f;
    }
    // biases: r/z merged (bih+bhh); n-gate split (bih outside r*, bhh inside)
    float bRr[2], bRz[2], biN[2], bhN[2];
#pragma unroll
    for (int jj = 0; jj < 2; jj++) {
        int c = hc + 2 * qc + jj;
        bRr[jj] = __ldg(&bih[c]) + __ldg(&bhh[c]);
        bRz[jj] = __ldg(&bih[128 + c]) + __ldg(&bhh[128 + c]);
        biN[jj] = __ldg(&bih[256 + c]);
        bhN[jj] = __ldg(&bhh[256 + c]);
    }
    __syncthreads();

    const float2* Bhi2 = (const float2*)Bhi_s;
    const float2* WihHi2 = (const float2*)g_WihHi;

    for (int t = 0; t < TT; t++) {
        // ---- x loads (fp32) issued early ----
        float xv[2][2][4];
#pragma unroll
        for (int m = 0; m < 2; m++)
#pragma unroll
            for (int kt = 0; kt < 2; kt++) {
                const float* base = feat + (size_t)(node0 + m * 16) * (TT * FF) + t * FF;
                int k0 = kt * 8 + qc;
                xv[m][kt][0] = __ldg(base + (size_t)qr * (TT * FF) + k0);
                xv[m][kt][1] = __ldg(base + (size_t)(qr + 8) * (TT * FF) + k0);
                xv[m][kt][2] = __ldg(base + (size_t)qr * (TT * FF) + k0 + 4);
                xv[m][kt][3] = __ldg(base + (size_t)(qr + 8) * (TT * FF) + k0 + 4);
            }

        float d[2][3][4];   // h-part accumulators (r,z,n) for this warp's 8 cols
        float dx[2][4];     // x-part of n-gate
#pragma unroll
        for (int m = 0; m < 2; m++) {
#pragma unroll
            for (int g = 0; g < 3; g++)
#pragma unroll
                for (int j = 0; j < 4; j++) d[m][g][j] = 0.f;
#pragma unroll
            for (int j = 0; j < 4; j++) dx[m][j] = 0.f;
        }

        // ---- h @ Whh^T (tensor cores, 3-term tf32 split) ----
        if (t) {
            uint4 blw, nw;
            blw = *(const uint4*)&g_Blo[((((0 * 8 + w8) * 2 + s) * 32) + lane) * 4];
#pragma unroll 2
            for (int kt = 0; kt < 16; kt++) {
                if (kt < 15)
                    nw = *(const uint4*)&g_Blo[(((((kt + 1) * 8 + w8) * 2 + s) * 32) + lane) * 4];
                int kc = kt * 8 + qc;
                uint32_t ah[2][4], al[2][4];
#pragma unroll
                for (int m = 0; m < 2; m++) {
                    int r0 = m * 16 + qr;
                    ah[m][0] = __float_as_uint(h_hi[r0 * 132 + kc]);
                    ah[m][1] = __float_as_uint(h_hi[(r0 + 8) * 132 + kc]);
                    ah[m][2] = __float_as_uint(h_hi[r0 * 132 + kc + 4]);
                    ah[m][3] = __float_as_uint(h_hi[(r0 + 8) * 132 + kc + 4]);
                    al[m][0] = __float_as_uint(h_lo[r0 * 132 + kc]);
                    al[m][1] = __float_as_uint(h_lo[(r0 + 8) * 132 + kc]);
                    al[m][2] = __float_as_uint(h_lo[r0 * 132 + kc + 4]);
                    al[m][3] = __float_as_uint(h_lo[(r0 + 8) * 132 + kc + 4]);
                }
                uint32_t lw[3] = {blw.x, blw.y, blw.z};
#pragma unroll
                for (int g = 0; g < 3; g++) {
                    float2 bh = Bhi2[((kt * 8 + w8) * 6 + g * 2 + s) * 32 + lane];
                    uint32_t bh0 = __float_as_uint(bh.x);
                    uint32_t bh1 = __float_as_uint(bh.y);
                    uint32_t bl0 = lw[g] << 16;
                    uint32_t bl1 = lw[g] & 0xFFFF0000u;
#pragma unroll
                    for (int m = 0; m < 2; m++) {
                        mma_tf32(d[m][g], ah[m], bh0, bh1);
                        mma_tf32(d[m][g], al[m], bh0, bh1);
                        mma_tf32(d[m][g], ah[m], bl0, bl1);
                    }
                }
                blw = nw;
            }
        }

        // ---- x @ Wih^T fused ----
#pragma unroll
        for (int kt = 0; kt < 2; kt++) {
            uint32_t xh[2][4], xl[2][4];
#pragma unroll
            for (int m = 0; m < 2; m++)
#pragma unroll
                for (int j = 0; j < 4; j++) {
                    float v = xv[m][kt][j];
                    uint32_t hi = f2tf32(v);
                    xh[m][j] = hi;
                    xl[m][j] = f2tf32(v - __uint_as_float(hi));
                }
            uint4 lv = *(const uint4*)&g_WihLo[((((kt * 8 + w8) * 2 + s) * 32) + lane) * 4];
            uint32_t lw[3] = {lv.x, lv.y, lv.z};
#pragma unroll
            for (int g = 0; g < 3; g++) {
                float2 bh = WihHi2[((kt * 8 + w8) * 6 + g * 2 + s) * 32 + lane];
                uint32_t bh0 = __float_as_uint(bh.x);
                uint32_t bh1 = __float_as_uint(bh.y);
                uint32_t bl0 = lw[g] << 16;
                uint32_t bl1 = lw[g] & 0xFFFF0000u;
#pragma unroll
                for (int m = 0; m < 2; m++) {
                    float* D = (g == 2) ? dx[m] : d[m][g];
                    mma_tf32(D, xh[m], bh0, bh1);
                    mma_tf32(D, xl[m], bh0, bh1);
                    mma_tf32(D, xh[m], bl0, bl1);
                }
            }
        }

        // ---- gate math ----
        float hn[2][2][2];
#pragma unroll
        for (int m = 0; m < 2; m++)
#pragma unroll
            for (int rg = 0; rg < 2; rg++) {
                int row = m * 16 + qr + rg * 8;
                int col = hc + 2 * qc;
                float2 hh = *(const float2*)&h_hi[row * 132 + col];
                float2 hl = *(const float2*)&h_lo[row * 132 + col];
#pragma unroll
                for (int jj = 0; jj < 2; jj++) {
                    float hold = jj ? (hh.y + hl.y) : (hh.x + hl.x);
                    int di = rg * 2 + jj;
                    float rr = sigmoid_fast(d[m][0][di] + bRr[jj]);
                    float zz = sigmoid_fast(d[m][1][di] + bRz[jj]);
                    float nv = tanh_fast(dx[m][di] + biN[jj] +
                                         rr * (d[m][2][di] + bhN[jj]));
                    hn[m][rg][jj] = (1.f - zz) * nv + zz * hold;
                }
            }
        __syncthreads();
#pragma unroll
        for (int m = 0; m < 2; m++)
#pragma unroll
            for (int rg = 0; rg < 2; rg++) {
                int row = m * 16 + qr + rg * 8;
                int col = hc + 2 * qc;
                float h0 = hn[m][rg][0], h1 = hn[m][rg][1];
                uint32_t u0 = f2tf32(h0), u1 = f2tf32(h1);
                float l0 = h0 - __uint_as_float(u0);
                float l1 = h1 - __uint_as_float(u1);
                *(float2*)&h_hi[row * 132 + col] =
                    make_float2(__uint_as_float(u0), __uint_as_float(u1));
                *(float2*)&h_lo[row * 132 + col] =
                    make_float2(__uint_as_float(f2tf32(l0)), __uint_as_float(f2tf32(l1)));
            }
        __syncthreads();
    }

    for (int i = tid; i < 32 * HH; i += 512) {
        int row = i >> 7, col = i & 127;
        g_support[(size_t)(node0 + row) * HH + col] =
            h_hi[row * 132 + col] + h_lo[row * 132 + col];
    }
}

// ---------------- kernel 3: tensor-core GEMM C[4096,128] = A @ B (+b1+b2) ---
struct GemmJob { const float* A; const float* B; const float* b1; const float* b2; float* C; };
struct GemmJobs { GemmJob j[5]; };

#define GEMM_SMEM 204800

__global__ void __launch_bounds__(256) k_gemm(GemmJobs jobs) {
    GemmJob job = jobs.j[blockIdx.y];
    extern __shared__ char smc[];
    float* As_hi = (float*)smc;                               // [128][132]
    float* Bs_hi = As_hi + 128 * 132;                         // [128][132]
    uint16_t* As_lo = (uint16_t*)(Bs_hi + 128 * 132);         // [128][136]
    uint16_t* Bs_lo = As_lo + 128 * 136;                      // [128][136]
    int tid = threadIdx.x;
    int node0 = blockIdx.x * 128;

    for (int idx = tid; idx < 128 * 128; idx += 256) {
        int r = idx >> 7, c = idx & 127;
        float a = job.A[(size_t)(node0 + r) * HH + c];
        uint32_t ha = f2tf32(a);
        As_hi[r * 132 + c] = __uint_as_float(ha);
        As_lo[r * 136 + c] =
            __bfloat16_as_ushort(__float2bfloat16(a - __uint_as_float(ha)));
        float b = job.B[idx];
        uint32_t hb = f2tf32(b);
        Bs_hi[r * 132 + c] = __uint_as_float(hb);
        Bs_lo[r * 136 + c] =
            __bfloat16_as_ushort(__float2bfloat16(b - __uint_as_float(hb)));
    }
    __syncthreads();

    int w = tid >> 5, lane = tid & 31;
    int qr = lane >> 2, qc = lane & 3;
    int r0 = w * 16;
    float acc[16][4];
#pragma unroll
    for (int ct = 0; ct < 16; ct++)
#pragma unroll
        for (int j = 0; j < 4; j++) acc[ct][j] = 0.f;

#pragma unroll 1
    for (int kt = 0; kt < 16; kt++) {
        int kc = kt * 8 + qc;
        uint32_t ah[4], al[4];
        ah[0] = __float_as_uint(As_hi[(r0 + qr) * 132 + kc]);
        ah[1] = __float_as_uint(As_hi[(r0 + qr + 8) * 132 + kc]);
        ah[2] = __float_as_uint(As_hi[(r0 + qr) * 132 + kc + 4]);
        ah[3] = __float_as_uint(As_hi[(r0 + qr + 8) * 132 + kc + 4]);
        al[0] = (uint32_t)As_lo[(r0 + qr) * 136 + kc] << 16;
        al[1] = (uint32_t)As_lo[(r0 + qr + 8) * 136 + kc] << 16;
        al[2] = (uint32_t)As_lo[(r0 + qr) * 136 + kc + 4] << 16;
        al[3] = (uint32_t)As_lo[(r0 + qr + 8) * 136 + kc + 4] << 16;
#pragma unroll
        for (int ct = 0; ct < 16; ct++) {
            int n0 = ct * 8;
            uint32_t bh0 = __float_as_uint(Bs_hi[kc * 132 + n0 + qr]);
            uint32_t bh1 = __float_as_uint(Bs_hi[(kc + 4) * 132 + n0 + qr]);
            uint32_t bl0 = (uint32_t)Bs_lo[kc * 136 + n0 + qr] << 16;
            uint32_t bl1 = (uint32_t)Bs_lo[(kc + 4) * 136 + n0 + qr] << 16;
            mma_tf32(acc[ct], ah, bh0, bh1);
            mma_tf32(acc[ct], al, bh0, bh1);
            mma_tf32(acc[ct], ah, bl0, bl1);
        }
    }

#pragma unroll
    for (int ct = 0; ct < 16; ct++) {
        int c0 = ct * 8 + 2 * qc;
        float b0 = 0.f, b1v = 0.f;
        if (job.b1) { b0 += __ldg(&job.b1[c0]); b1v += __ldg(&job.b1[c0 + 1]); }
        if (job.b2) { b0 += __ldg(&job.b2[c0]); b1v += __ldg(&job.b2[c0 + 1]); }
        int r = node0 + r0 + qr;
        *(float2*)&job.C[(size_t)r * HH + c0] =
            make_float2(acc[ct][0] + b0, acc[ct][1] + b1v);
        *(float2*)&job.C[(size_t)(r + 8) * HH + c0] =
            make_float2(acc[ct][2] + b0, acc[ct][3] + b1v);
    }
}

// ---------------- kernel 4: f1/f2 per head -----------------------------------
__global__ void k_f1f2(const float* __restrict__ uP, const float* __restrict__ vP,
                       const float* __restrict__ uN, const float* __restrict__ vN) {
    const float* sup; const float* u; const float* v; float* f1; float* f2;
    if (blockIdx.y == 0) { sup = g_supP; u = uP; v = vP; f1 = g_f1P; f2 = g_f2P; }
    else                 { sup = g_supN; u = uN; v = vN; f1 = g_f1N; f2 = g_f2N; }
    int n = blockIdx.x * 8 + (threadIdx.x >> 5);
    int lane = threadIdx.x & 31;
#pragma unroll
    for (int h = 0; h < NHD; h++) {
        float s = sup[(size_t)n * HH + h * DOD + lane];
        float a = s * u[h * DOD + lane];
        float b = s * v[h * DOD + lane];
        a = warpsum(a); b = warpsum(b);
        if (lane == 0) { f1[h * NN + n] = a; f2[h * NN + n] = b; }
    }
}

// ---------------- kernel 5: GAT masked-attention aggregation -----------------
__global__ void __launch_bounds__(128) k_gat(const float* __restrict__ adjP,
                                             const float* __restrict__ adjN) {
    __shared__ int s_cnt;
    __shared__ int s_list[512];
    __shared__ float s_a[512];
    const float* adj; const float* sup; const float* f1; const float* f2;
    const float* resid; float* outp;
    if (blockIdx.y == 0) { adj = adjP; sup = g_supP; f1 = g_f1P; f2 = g_f2P; resid = g_residP; outp = g_gatP; }
    else                 { adj = adjN; sup = g_supN; f1 = g_f1N; f2 = g_f2N; resid = g_residN; outp = g_gatN; }
    int i = blockIdx.x, tid = threadIdx.x;
    int h = tid >> 5;
    float f2i = f2[h * NN + i];
    float num = 0.f, den = 0.f;

    for (int c0 = 0; c0 < NN; c0 += 16384) {
        if (tid == 0) s_cnt = 0;
        __syncthreads();
        int cend = c0 + 16384; if (cend > NN) cend = NN;
        for (int j = c0 + tid; j < cend; j += 128) {
            float a = adj[(size_t)i * NN + j];
            if (a != 0.f) {
                int p = atomicAdd(&s_cnt, 1);
                s_list[p] = j;
                s_a[p] = a;
            }
        }
        __syncthreads();
        int cnt = s_cnt;
        for (int t = 0; t < cnt; t++) {
            int j = s_list[t];
            float w = f1[h * NN + j] + f2i;
            w = (w > 0.f) ? w : 0.2f * w;
            w *= s_a[t];
            den += w;
            num += w * sup[(size_t)j * HH + tid];
        }
        __syncthreads();
    }
    float d = (den == 0.f) ? 1.f : den;
    outp[(size_t)i * HH + tid] = num / d + resid[(size_t)i * HH + tid];
}

// ---------------- kernel 6: zero colsum --------------------------------------
__global__ void k_zero() { if (threadIdx.x < HH) g_colsum[threadIdx.x] = 0.f; }

// ---------------- kernel 7: semantic attention, warp-per-node ----------------
__global__ void __launch_bounds__(256) k_sem(const float* __restrict__ W1,
                                             const float* __restrict__ b1,
                                             const float* __restrict__ W2) {
    __shared__ float W1s[128 * 65];
    __shared__ float W2s[SEMD], b1s[SEMD];
    __shared__ float semb[8][3][128];
    int tid = threadIdx.x;
    for (int i = tid; i < 128 * 64; i += 256) {
        int k = i >> 6, s = i & 63;
        W1s[k * 65 + s] = W1[i];
    }
    if (tid < SEMD) { W2s[tid] = W2[tid]; b1s[tid] = b1[tid]; }
    __syncthreads();

    int w = tid >> 5, lane = tid & 31;
    float csum[4] = {0.f, 0.f, 0.f, 0.f};
    int nbase = (blockIdx.x * 8 + w) * 8;

    for (int i = 0; i < 8; i++) {
        int n = nbase + i;
        float4 ev[3];
        ev[0] = *(const float4*)&g_selfE[(size_t)n * HH + lane * 4];
        ev[1] = *(const float4*)&g_posE[(size_t)n * HH + lane * 4];
        ev[2] = *(const float4*)&g_negE[(size_t)n * HH + lane * 4];
        __syncwarp();
        *(float4*)&semb[w][0][lane * 4] = ev[0];
        *(float4*)&semb[w][1][lane * 4] = ev[1];
        *(float4*)&semb[w][2][lane * 4] = ev[2];
        __syncwarp();

        float acc[3][2];
#pragma unroll
        for (int e = 0; e < 3; e++) { acc[e][0] = b1s[lane]; acc[e][1] = b1s[lane + 32]; }
#pragma unroll 4
        for (int k = 0; k < HH; k++) {
            float w1a = W1s[k * 65 + lane];
            float w1b = W1s[k * 65 + lane + 32];
            float x0 = semb[w][0][k], x1 = semb[w][1][k], x2 = semb[w][2][k];
            acc[0][0] += x0 * w1a; acc[0][1] += x0 * w1b;
            acc[1][0] += x1 * w1a; acc[1][1] += x1 * w1b;
            acc[2][0] += x2 * w1a; acc[2][1] += x2 * w1b;
        }
        float wv[3];
#pragma unroll
        for (int e = 0; e < 3; e++) {
            float tsum = tanh_fast(acc[e][0]) * W2s[lane] +
                         tanh_fast(acc[e][1]) * W2s[lane + 32];
            wv[e] = warpsum_bfly(tsum);
        }
        float m = fmaxf(wv[0], fmaxf(wv[1], wv[2]));
        float e0 = __expf(wv[0] - m), e1 = __expf(wv[1] - m), e2 = __expf(wv[2] - m);
        float inv = __fdividef(1.f, e0 + e1 + e2);
        float be0 = e0 * inv, be1 = e1 * inv, be2 = e2 * inv;
        float4 f;
        f.x = be0 * ev[0].x + be1 * ev[1].x + be2 * ev[2].x;
        f.y = be0 * ev[0].y + be1 * ev[1].y + be2 * ev[2].y;
        f.z = be0 * ev[0].z + be1 * ev[1].z + be2 * ev[2].z;
        f.w = be0 * ev[0].w + be1 * ev[1].w + be2 * ev[2].w;
        *(float4*)&g_fused[(size_t)n * HH + lane * 4] = f;
        csum[0] += f.x; csum[1] += f.y; csum[2] += f.z; csum[3] += f.w;
    }
    atomicAdd(&g_colsum[lane * 4 + 0], csum[0]);
    atomicAdd(&g_colsum[lane * 4 + 1], csum[1]);
    atomicAdd(&g_colsum[lane * 4 + 2], csum[2]);
    atomicAdd(&g_colsum[lane * 4 + 3], csum[3]);
}

// ---------------- kernel 8: pairnorm + predictor -----------------------------
__global__ void __launch_bounds__(256) k_pred(const float* __restrict__ W1,
                                              const float* __restrict__ b1,
                                              const float* __restrict__ W2,
                                              const float* __restrict__ b2,
                                              float* __restrict__ out) {
    __shared__ float W1s[HH * PHD];
    __shared__ float xns[8][HH];
    int tid = threadIdx.x;
    for (int i = tid; i < HH * PHD; i += 256) W1s[i] = W1[i];
    int w = tid >> 5, lane = tid & 31;
    int n = blockIdx.x * 8 + w;
    float xv[4]; float ss = 0.f;
    const float invN = 1.f / (float)NN;
#pragma unroll
    for (int j = 0; j < 4; j++) {
        int d = lane + j * 32;
        float x = g_fused[(size_t)n * HH + d] - g_colsum[d] * invN;
        xv[j] = x; ss += x * x;
    }
    ss = warpsum(ss);
    ss = __shfl_sync(0xffffffffu, ss, 0);
    float rinv = rsqrtf(1e-6f + ss);
#pragma unroll
    for (int j = 0; j < 4; j++) xns[w][lane + j * 32] = xv[j] * rinv;
    __syncthreads();

    float acc = b1[lane];
#pragma unroll 4
    for (int k = 0; k < HH; k++) acc += xns[w][k] * W1s[k * PHD + lane];
    float hgt = acc > 0.f ? acc : 0.f;
    float o = warpsum(hgt * W2[lane]);
    if (lane == 0) out[n] = sigmoid_fast(o + b2[0]);
}

// ---------------- launch -----------------------------------------------------
extern "C" void kernel_launch(void* const* d_in, const int* in_sizes, int n_in,
                              void* d_out, int out_size) {
    const float* features = (const float*)d_in[0];
    const float* pos_adj  = (const float*)d_in[1];
    const float* neg_adj  = (const float*)d_in[2];
    const float* gru_Wih  = (const float*)d_in[3];
    const float* gru_Whh  = (const float*)d_in[4];
    const float* gru_bih  = (const float*)d_in[5];
    const float* gru_bhh  = (const float*)d_in[6];
    const float* pos_W    = (const float*)d_in[7];
    const float* pos_u    = (const float*)d_in[8];
    const float* pos_v    = (const float*)d_in[9];
    const float* pos_b    = (const float*)d_in[10];
    const float* pos_pW   = (const float*)d_in[11];
    const float* pos_pb   = (const float*)d_in[12];
    const float* neg_W    = (const float*)d_in[13];
    const float* neg_u    = (const float*)d_in[14];
    const float* neg_v    = (const float*)d_in[15];
    const float* neg_b    = (const float*)d_in[16];
    const float* neg_pW   = (const float*)d_in[17];
    const float* neg_pb   = (const float*)d_in[18];
    const float* self_W   = (const float*)d_in[19];
    const float* self_b   = (const float*)d_in[20];
    const float* mpos_W   = (const float*)d_in[21];
    const float* mpos_b   = (const float*)d_in[22];
    const float* mneg_W   = (const float*)d_in[23];
    const float* mneg_b   = (const float*)d_in[24];
    const float* sem_W1   = (const float*)d_in[25];
    const float* sem_b1   = (const float*)d_in[26];
    const float* sem_W2   = (const float*)d_in[27];
    const float* pred_W1  = (const float*)d_in[28];
    const float* pred_b1  = (const float*)d_in[29];
    const float* pred_W2  = (const float*)d_in[30];
    const float* pred_b2  = (const float*)d_in[31];
    float* out = (float*)d_out;

    static bool attr_done = false;
    if (!attr_done) {
        cudaFuncSetAttribute(k_gru, cudaFuncAttributeMaxDynamicSharedMemorySize, GRU_SMEM);
        cudaFuncSetAttribute(k_gemm, cudaFuncAttributeMaxDynamicSharedMemorySize, GEMM_SMEM);
        attr_done = true;
    }

    float *p_support, *p_gatP, *p_gatN, *p_supP, *p_supN;
    float *p_residP, *p_residN, *p_selfE, *p_posE, *p_negE;
    cudaGetSymbolAddress((void**)&p_support, g_support);
    cudaGetSymbolAddress((void**)&p_supP, g_supP);
    cudaGetSymbolAddress((void**)&p_supN, g_supN);
    cudaGetSymbolAddress((void**)&p_residP, g_residP);
    cudaGetSymbolAddress((void**)&p_residN, g_residN);
    cudaGetSymbolAddress((void**)&p_selfE, g_selfE);
    cudaGetSymbolAddress((void**)&p_gatP, g_gatP);
    cudaGetSymbolAddress((void**)&p_gatN, g_gatN);
    cudaGetSymbolAddress((void**)&p_posE, g_posE);
    cudaGetSymbolAddress((void**)&p_negE, g_negE);

    k_prep<<<96, 256>>>(gru_Whh);                                   // 1
    k_prep_wih<<<12, 256>>>(gru_Wih);                               // 2
    k_zero<<<1, 128>>>();                                           // 3
    k_gru<<<NN / 32, 512, GRU_SMEM>>>(features, gru_bih, gru_bhh);  // 4
    {
        GemmJobs jb;
        jb.j[0] = { p_support, pos_W,  nullptr, nullptr, p_supP };
        jb.j[1] = { p_support, neg_W,  nullptr, nullptr, p_supN };
        jb.j[2] = { p_support, pos_pW, pos_b,   pos_pb,  p_residP };
        jb.j[3] = { p_support, neg_pW, neg_b,   neg_pb,  p_residN };
        jb.j[4] = { p_support, self_W, self_b,  nullptr, p_selfE };
        dim3 grid(NN / 128, 5);
        k_gemm<<<grid, 256, GEMM_SMEM>>>(jb);                       // 5
    }
    {
        dim3 grid(NN / 8, 2);
        k_f1f2<<<grid, 256>>>(pos_u, pos_v, neg_u, neg_v);          // 6
    }
    {
        dim3 grid(NN, 2);
        k_gat<<<grid, 128>>>(pos_adj, neg_adj);                     // 7
    }
    {
        GemmJobs jb;
        jb.j[0] = { p_gatP, mpos_W, mpos_b, nullptr, p_posE };
        jb.j[1] = { p_gatN, mneg_W, mneg_b, nullptr, p_negE };
        jb.j[2] = jb.j[0]; jb.j[3] = jb.j[0]; jb.j[4] = jb.j[0];
        dim3 grid(NN / 128, 2);
        k_gemm<<<grid, 256, GEMM_SMEM>>>(jb);                       // 8
    }
    k_sem<<<NN / 64, 256>>>(sem_W1, sem_b1, sem_W2);                // 9
    k_pred<<<NN / 8, 256>>>(pred_W1, pred_b1, pred_W2, pred_b2, out); // 10
}

// round 8
// speedup vs baseline: 8.2978x; 1.2357x over previous
#include <cuda_runtime.h>
#include <cuda_bf16.h>
#include <cstdint>
#include <cstddef>

#define NN 4096
#define TT 24
#define FF 16
#define HH 128
#define GG 384
#define NHD 4
#define DOD 32
#define SEMD 64
#define PHD 32

// ---------------- scratch (static device globals; no runtime allocation) ----
__device__ float g_support[NN * HH];
__device__ float g_supP[NN * HH];
__device__ float g_supN[NN * HH];
__device__ float g_residP[NN * HH];
__device__ float g_residN[NN * HH];
__device__ float g_selfE[NN * HH];
__device__ float g_f1P[NHD * NN];
__device__ float g_f2P[NHD * NN];
__device__ float g_f1N[NHD * NN];
__device__ float g_f2N[NHD * NN];
__device__ float g_gatP[NN * HH];
__device__ float g_gatN[NN * HH];
__device__ float g_posE[NN * HH];
__device__ float g_negE[NN * HH];
__device__ float g_fused[NN * HH];
__device__ float g_colsum[HH];
// bf16 fragment-ordered Whh: hi (smem-staged), lo (streamed, uint4+uint2/warp)
__device__ __align__(16) uint32_t g_Bhi[8 * 8 * 6 * 32 * 2];   // 24576 words (96 KB)
__device__ __align__(16) uint32_t g_Blo[8 * 8 * 2 * 32 * 8];   // 32768 words
// bf16 fragment-ordered Wih (k=16 -> one k-chunk)
__device__ __align__(16) uint32_t g_WihHi[8 * 6 * 32 * 2];
__device__ __align__(16) uint32_t g_WihLo[8 * 2 * 32 * 8];

__device__ __forceinline__ float warpsum(float v) {
#pragma unroll
    for (int o = 16; o >= 1; o >>= 1) v += __shfl_down_sync(0xffffffffu, v, o);
    return v;
}
__device__ __forceinline__ float warpsum_bfly(float v) {
#pragma unroll
    for (int o = 16; o >= 1; o >>= 1) v += __shfl_xor_sync(0xffffffffu, v, o);
    return v;
}
__device__ __forceinline__ float sigmoid_fast(float x) {
    return __fdividef(1.f, 1.f + __expf(-x));
}
__device__ __forceinline__ float tanh_fast(float x) {
    float e = __expf(-2.f * x);
    return __fdividef(2.f, 1.f + e) - 1.f;
}
__device__ __forceinline__ uint32_t f2tf32(float f) {
    uint32_t u; asm("cvt.rna.tf32.f32 %0, %1;" : "=r"(u) : "f"(f)); return u;
}
__device__ __forceinline__ uint32_t packbf2(float x0, float x1) {
    __nv_bfloat162 v = __floats2bfloat162_rn(x0, x1);
    return *(uint32_t*)&v;
}
__device__ __forceinline__ void mma_tf32(float d[4], const uint32_t a[4],
                                         uint32_t b0, uint32_t b1) {
    asm volatile("mma.sync.aligned.m16n8k8.row.col.f32.tf32.tf32.f32 "
                 "{%0,%1,%2,%3}, {%4,%5,%6,%7}, {%8,%9}, {%0,%1,%2,%3};"
                 : "+f"(d[0]), "+f"(d[1]), "+f"(d[2]), "+f"(d[3])
                 : "r"(a[0]), "r"(a[1]), "r"(a[2]), "r"(a[3]), "r"(b0), "r"(b1));
}
__device__ __forceinline__ void mma_bf16(float d[4], const uint32_t a[4],
                                         uint32_t b0, uint32_t b1) {
    asm volatile("mma.sync.aligned.m16n8k16.row.col.f32.bf16.bf16.f32 "
                 "{%0,%1,%2,%3}, {%4,%5,%6,%7}, {%8,%9}, {%0,%1,%2,%3};"
                 : "+f"(d[0]), "+f"(d[1]), "+f"(d[2]), "+f"(d[3])
                 : "r"(a[0]), "r"(a[1]), "r"(a[2]), "r"(a[3]), "r"(b0), "r"(b1));
}

// ---------------- kernel 0a: bf16 fragment-ordered Whh -----------------------
__global__ void k_prep(const float* __restrict__ Whh) {
    int idx = blockIdx.x * 256 + threadIdx.x;       // 12288 = 8*8*6*32
    if (idx >= 8 * 8 * 6 * 32) return;
    int lane = idx & 31; int r = idx >> 5;
    int nt = r % 6; r /= 6;
    int w8 = r & 7; int kt = r >> 3;                 // kt in [0,8)
    int g = nt >> 1, s = nt & 1;
    int n = g * 128 + w8 * 16 + s * 8 + (lane >> 2);
    int kb = kt * 16 + (lane & 3) * 2;
    float w0 = Whh[n * 128 + kb],     w1 = Whh[n * 128 + kb + 1];
    float w2 = Whh[n * 128 + kb + 8], w3 = Whh[n * 128 + kb + 9];
    __nv_bfloat16 h0 = __float2bfloat16(w0), h1 = __float2bfloat16(w1);
    __nv_bfloat16 h2 = __float2bfloat16(w2), h3 = __float2bfloat16(w3);
    g_Bhi[idx * 2 + 0] = packbf2(__bfloat162float(h0), 0.f) & 0xFFFFu |
                         (packbf2(__bfloat162float(h1), 0.f) << 16);
    // simpler exact packing:
    {
        __nv_bfloat162 v; v.x = h0; v.y = h1;
        g_Bhi[idx * 2 + 0] = *(uint32_t*)&v;
        v.x = h2; v.y = h3;
        g_Bhi[idx * 2 + 1] = *(uint32_t*)&v;
    }
    __nv_bfloat162 l01, l23;
    l01.x = __float2bfloat16(w0 - __bfloat162float(h0));
    l01.y = __float2bfloat16(w1 - __bfloat162float(h1));
    l23.x = __float2bfloat16(w2 - __bfloat162float(h2));
    l23.y = __float2bfloat16(w3 - __bfloat162float(h3));
    uint32_t* lo = &g_Blo[(((kt * 8 + w8) * 2 + s) * 32 + lane) * 8 + g * 2];
    lo[0] = *(uint32_t*)&l01;
    lo[1] = *(uint32_t*)&l23;
}

// ---------------- kernel 0b: bf16 fragment-ordered Wih (k=16) ---------------
__global__ void k_prep_wih(const float* __restrict__ Wih) {
    int idx = blockIdx.x * 256 + threadIdx.x;       // 1536 = 8*6*32
    if (idx >= 8 * 6 * 32) return;
    int lane = idx & 31; int r = idx >> 5;
    int nt = r % 6; int w8 = r / 6;
    int g = nt >> 1, s = nt & 1;
    int n = g * 128 + w8 * 16 + s * 8 + (lane >> 2);
    int kb = (lane & 3) * 2;
    float w0 = Wih[n * FF + kb],     w1 = Wih[n * FF + kb + 1];
    float w2 = Wih[n * FF + kb + 8], w3 = Wih[n * FF + kb + 9];
    __nv_bfloat16 h0 = __float2bfloat16(w0), h1 = __float2bfloat16(w1);
    __nv_bfloat16 h2 = __float2bfloat16(w2), h3 = __float2bfloat16(w3);
    {
        __nv_bfloat162 v; v.x = h0; v.y = h1;
        g_WihHi[idx * 2 + 0] = *(uint32_t*)&v;
        v.x = h2; v.y = h3;
        g_WihHi[idx * 2 + 1] = *(uint32_t*)&v;
    }
    __nv_bfloat162 l01, l23;
    l01.x = __float2bfloat16(w0 - __bfloat162float(h0));
    l01.y = __float2bfloat16(w1 - __bfloat162float(h1));
    l23.x = __float2bfloat16(w2 - __bfloat162float(h2));
    l23.y = __float2bfloat16(w3 - __bfloat162float(h3));
    uint32_t* lo = &g_WihLo[((w8 * 2 + s) * 32 + lane) * 8 + g * 2];
    lo[0] = *(uint32_t*)&l01;
    lo[1] = *(uint32_t*)&l23;
}

// ---------------- kernel 2: fused GRU scan, bf16x3 split, 512 threads -------
// smem: Bhi 24576 words (96 KB) + h_hi/h_lo bf16 [32][136] each (17408 B)
#define GRU_SMEM (24576 * 4 + 2 * 32 * 136 * 2)

__global__ void __launch_bounds__(512, 1) k_gru(const float* __restrict__ feat,
                                                const float* __restrict__ bih,
                                                const float* __restrict__ bhh) {
    extern __shared__ float sm[];
    uint32_t* Bhi_s = (uint32_t*)sm;                 // 24576 words
    uint32_t* h_hi_w = Bhi_s + 24576;                // 32*68 words (bf16 [32][136])
    uint32_t* h_lo_w = h_hi_w + 32 * 68;
    int tid = threadIdx.x;
    int w = tid >> 5, lane = tid & 31;
    int w8 = w >> 1, s = w & 1;
    int qr = lane >> 2, qc = lane & 3;
    int hc = w * 8;                                  // 8 output cols per warp
    int node0 = blockIdx.x * 32;

    {
        const uint4* src = (const uint4*)g_Bhi;
        uint4* dst = (uint4*)Bhi_s;
        for (int i = tid; i < 24576 / 4; i += 512) dst[i] = src[i];
        for (int i = tid; i < 2 * 32 * 68; i += 512) h_hi_w[i] = 0u;
    }
    // biases: r/z merged (bih+bhh); n-gate split (bih outside r*, bhh inside)
    float bRr[2], bRz[2], biN[2], bhN[2];
#pragma unroll
    for (int jj = 0; jj < 2; jj++) {
        int c = hc + 2 * qc + jj;
        bRr[jj] = __ldg(&bih[c]) + __ldg(&bhh[c]);
        bRz[jj] = __ldg(&bih[128 + c]) + __ldg(&bhh[128 + c]);
        biN[jj] = __ldg(&bih[256 + c]);
        bhN[jj] = __ldg(&bhh[256 + c]);
    }
    __syncthreads();

    const uint2* Bhi2 = (const uint2*)Bhi_s;
    const uint2* WihHi2 = (const uint2*)g_WihHi;

    for (int t = 0; t < TT; t++) {
        // ---- x loads (fp32 pairs) issued early ----
        float2 xr[2][4];
#pragma unroll
        for (int m = 0; m < 2; m++) {
            const float* base = feat + (size_t)(node0 + m * 16) * (TT * FF) + t * FF;
            xr[m][0] = __ldg((const float2*)(base + (size_t)qr * (TT * FF) + 2 * qc));
            xr[m][1] = __ldg((const float2*)(base + (size_t)(qr + 8) * (TT * FF) + 2 * qc));
            xr[m][2] = __ldg((const float2*)(base + (size_t)qr * (TT * FF) + 2 * qc + 8));
            xr[m][3] = __ldg((const float2*)(base + (size_t)(qr + 8) * (TT * FF) + 2 * qc + 8));
        }

        float d[2][3][4];   // h-part accumulators (r,z,n)
        float dx[2][4];     // x-part of n-gate
#pragma unroll
        for (int m = 0; m < 2; m++) {
#pragma unroll
            for (int g = 0; g < 3; g++)
#pragma unroll
                for (int j = 0; j < 4; j++) d[m][g][j] = 0.f;
#pragma unroll
            for (int j = 0; j < 4; j++) dx[m][j] = 0.f;
        }

        // ---- h @ Whh^T (bf16 m16n8k16, 3-term split) ----
        if (t) {
            uint4 blwA, nwA; uint2 blwB, nwB;
            {
                const uint32_t* p = &g_Blo[(((0 * 8 + w8) * 2 + s) * 32 + lane) * 8];
                blwA = *(const uint4*)p; blwB = *(const uint2*)(p + 4);
            }
#pragma unroll 2
            for (int kt = 0; kt < 8; kt++) {
                if (kt < 7) {
                    const uint32_t* p = &g_Blo[((((kt + 1) * 8 + w8) * 2 + s) * 32 + lane) * 8];
                    nwA = *(const uint4*)p; nwB = *(const uint2*)(p + 4);
                }
                uint32_t ah[2][4], al[2][4];
#pragma unroll
                for (int m = 0; m < 2; m++) {
                    int r0 = (m * 16 + qr) * 68 + kt * 8 + qc;
                    ah[m][0] = h_hi_w[r0];
                    ah[m][1] = h_hi_w[r0 + 8 * 68];
                    ah[m][2] = h_hi_w[r0 + 4];
                    ah[m][3] = h_hi_w[r0 + 8 * 68 + 4];
                    al[m][0] = h_lo_w[r0];
                    al[m][1] = h_lo_w[r0 + 8 * 68];
                    al[m][2] = h_lo_w[r0 + 4];
                    al[m][3] = h_lo_w[r0 + 8 * 68 + 4];
                }
                uint32_t lw[6] = {blwA.x, blwA.y, blwA.z, blwA.w, blwB.x, blwB.y};
#pragma unroll
                for (int g = 0; g < 3; g++) {
                    uint2 bh = Bhi2[((kt * 8 + w8) * 6 + g * 2 + s) * 32 + lane];
                    uint32_t bl0 = lw[g * 2], bl1 = lw[g * 2 + 1];
#pragma unroll
                    for (int m = 0; m < 2; m++) {
                        mma_bf16(d[m][g], ah[m], bh.x, bh.y);
                        mma_bf16(d[m][g], al[m], bh.x, bh.y);
                        mma_bf16(d[m][g], ah[m], bl0, bl1);
                    }
                }
                blwA = nwA; blwB = nwB;
            }
        }

        // ---- x @ Wih^T fused (k=16, one chunk) ----
        {
            uint32_t xh[2][4], xl[2][4];
#pragma unroll
            for (int m = 0; m < 2; m++)
#pragma unroll
                for (int j = 0; j < 4; j++) {
                    float v0 = xr[m][j].x, v1 = xr[m][j].y;
                    __nv_bfloat162 hv; hv.x = __float2bfloat16(v0); hv.y = __float2bfloat16(v1);
                    xh[m][j] = *(uint32_t*)&hv;
                    __nv_bfloat162 lv;
                    lv.x = __float2bfloat16(v0 - __bfloat162float(hv.x));
                    lv.y = __float2bfloat16(v1 - __bfloat162float(hv.y));
                    xl[m][j] = *(uint32_t*)&lv;
                }
            const uint32_t* p = &g_WihLo[((w8 * 2 + s) * 32 + lane) * 8];
            uint4 wlA = *(const uint4*)p; uint2 wlB = *(const uint2*)(p + 4);
            uint32_t wlw[6] = {wlA.x, wlA.y, wlA.z, wlA.w, wlB.x, wlB.y};
#pragma unroll
            for (int g = 0; g < 3; g++) {
                uint2 bh = __ldg(&WihHi2[(w8 * 6 + g * 2 + s) * 32 + lane]);
#pragma unroll
                for (int m = 0; m < 2; m++) {
                    float* D = (g == 2) ? dx[m] : d[m][g];
                    mma_bf16(D, xh[m], bh.x, bh.y);
                    mma_bf16(D, xl[m], bh.x, bh.y);
                    mma_bf16(D, xh[m], wlw[g * 2], wlw[g * 2 + 1]);
                }
            }
        }

        // ---- gate math ----
        float hn[2][2][2];
#pragma unroll
        for (int m = 0; m < 2; m++)
#pragma unroll
            for (int rg = 0; rg < 2; rg++) {
                int row = m * 16 + qr + rg * 8;
                int wi = row * 68 + w * 4 + qc;
                float2 hhf = __bfloat1622float2(*(__nv_bfloat162*)&h_hi_w[wi]);
                float2 hlf = __bfloat1622float2(*(__nv_bfloat162*)&h_lo_w[wi]);
#pragma unroll
                for (int jj = 0; jj < 2; jj++) {
                    float hold = jj ? (hhf.y + hlf.y) : (hhf.x + hlf.x);
                    int di = rg * 2 + jj;
                    float rr = sigmoid_fast(d[m][0][di] + bRr[jj]);
                    float zz = sigmoid_fast(d[m][1][di] + bRz[jj]);
                    float nv = tanh_fast(dx[m][di] + biN[jj] +
                                         rr * (d[m][2][di] + bhN[jj]));
                    hn[m][rg][jj] = (1.f - zz) * nv + zz * hold;
                }
            }
        __syncthreads();
#pragma unroll
        for (int m = 0; m < 2; m++)
#pragma unroll
            for (int rg = 0; rg < 2; rg++) {
                int row = m * 16 + qr + rg * 8;
                int wi = row * 68 + w * 4 + qc;
                float h0 = hn[m][rg][0], h1 = hn[m][rg][1];
                __nv_bfloat162 hv; hv.x = __float2bfloat16(h0); hv.y = __float2bfloat16(h1);
                __nv_bfloat162 lv;
                lv.x = __float2bfloat16(h0 - __bfloat162float(hv.x));
                lv.y = __float2bfloat16(h1 - __bfloat162float(hv.y));
                h_hi_w[wi] = *(uint32_t*)&hv;
                h_lo_w[wi] = *(uint32_t*)&lv;
            }
        __syncthreads();
    }

    const __nv_bfloat16* h_hi = (const __nv_bfloat16*)h_hi_w;
    const __nv_bfloat16* h_lo = (const __nv_bfloat16*)h_lo_w;
    for (int i = tid; i < 32 * HH; i += 512) {
        int row = i >> 7, col = i & 127;
        g_support[(size_t)(node0 + row) * HH + col] =
            __bfloat162float(h_hi[row * 136 + col]) +
            __bfloat162float(h_lo[row * 136 + col]);
    }
}

// ---------------- kernel 3: tensor-core GEMM C[4096,128] = A @ B (+b1+b2) ---
struct GemmJob { const float* A; const float* B; const float* b1; const float* b2; float* C; };
struct GemmJobs { GemmJob j[5]; };

#define GEMM_SMEM 204800

__global__ void __launch_bounds__(256) k_gemm(GemmJobs jobs) {
    GemmJob job = jobs.j[blockIdx.y];
    extern __shared__ char smc[];
    float* As_hi = (float*)smc;                               // [128][132]
    float* Bs_hi = As_hi + 128 * 132;                         // [128][132]
    uint16_t* As_lo = (uint16_t*)(Bs_hi + 128 * 132);         // [128][136]
    uint16_t* Bs_lo = As_lo + 128 * 136;                      // [128][136]
    int tid = threadIdx.x;
    int node0 = blockIdx.x * 128;

    for (int idx = tid; idx < 128 * 128; idx += 256) {
        int r = idx >> 7, c = idx & 127;
        float a = job.A[(size_t)(node0 + r) * HH + c];
        uint32_t ha = f2tf32(a);
        As_hi[r * 132 + c] = __uint_as_float(ha);
        As_lo[r * 136 + c] =
            __bfloat16_as_ushort(__float2bfloat16(a - __uint_as_float(ha)));
        float b = job.B[idx];
        uint32_t hb = f2tf32(b);
        Bs_hi[r * 132 + c] = __uint_as_float(hb);
        Bs_lo[r * 136 + c] =
            __bfloat16_as_ushort(__float2bfloat16(b - __uint_as_float(hb)));
    }
    __syncthreads();

    int w = tid >> 5, lane = tid & 31;
    int qr = lane >> 2, qc = lane & 3;
    int r0 = w * 16;
    float acc[16][4];
#pragma unroll
    for (int ct = 0; ct < 16; ct++)
#pragma unroll
        for (int j = 0; j < 4; j++) acc[ct][j] = 0.f;

#pragma unroll 1
    for (int kt = 0; kt < 16; kt++) {
        int kc = kt * 8 + qc;
        uint32_t ah[4], al[4];
        ah[0] = __float_as_uint(As_hi[(r0 + qr) * 132 + kc]);
        ah[1] = __float_as_uint(As_hi[(r0 + qr + 8) * 132 + kc]);
        ah[2] = __float_as_uint(As_hi[(r0 + qr) * 132 + kc + 4]);
        ah[3] = __float_as_uint(As_hi[(r0 + qr + 8) * 132 + kc + 4]);
        al[0] = (uint32_t)As_lo[(r0 + qr) * 136 + kc] << 16;
        al[1] = (uint32_t)As_lo[(r0 + qr + 8) * 136 + kc] << 16;
        al[2] = (uint32_t)As_lo[(r0 + qr) * 136 + kc + 4] << 16;
        al[3] = (uint32_t)As_lo[(r0 + qr + 8) * 136 + kc + 4] << 16;
#pragma unroll
        for (int ct = 0; ct < 16; ct++) {
            int n0 = ct * 8;
            uint32_t bh0 = __float_as_uint(Bs_hi[kc * 132 + n0 + qr]);
            uint32_t bh1 = __float_as_uint(Bs_hi[(kc + 4) * 132 + n0 + qr]);
            uint32_t bl0 = (uint32_t)Bs_lo[kc * 136 + n0 + qr] << 16;
            uint32_t bl1 = (uint32_t)Bs_lo[(kc + 4) * 136 + n0 + qr] << 16;
            mma_tf32(acc[ct], ah, bh0, bh1);
            mma_tf32(acc[ct], al, bh0, bh1);
            mma_tf32(acc[ct], ah, bl0, bl1);
        }
    }

#pragma unroll
    for (int ct = 0; ct < 16; ct++) {
        int c0 = ct * 8 + 2 * qc;
        float b0 = 0.f, b1v = 0.f;
        if (job.b1) { b0 += __ldg(&job.b1[c0]); b1v += __ldg(&job.b1[c0 + 1]); }
        if (job.b2) { b0 += __ldg(&job.b2[c0]); b1v += __ldg(&job.b2[c0 + 1]); }
        int r = node0 + r0 + qr;
        *(float2*)&job.C[(size_t)r * HH + c0] =
            make_float2(acc[ct][0] + b0, acc[ct][1] + b1v);
        *(float2*)&job.C[(size_t)(r + 8) * HH + c0] =
            make_float2(acc[ct][2] + b0, acc[ct][3] + b1v);
    }
}

// ---------------- kernel 4: f1/f2 per head -----------------------------------
__global__ void k_f1f2(const float* __restrict__ uP, const float* __restrict__ vP,
                       const float* __restrict__ uN, const float* __restrict__ vN) {
    const float* sup; const float* u; const float* v; float* f1; float* f2;
    if (blockIdx.y == 0) { sup = g_supP; u = uP; v = vP; f1 = g_f1P; f2 = g_f2P; }
    else                 { sup = g_supN; u = uN; v = vN; f1 = g_f1N; f2 = g_f2N; }
    int n = blockIdx.x * 8 + (threadIdx.x >> 5);
    int lane = threadIdx.x & 31;
#pragma unroll
    for (int h = 0; h < NHD; h++) {
        float s = sup[(size_t)n * HH + h * DOD + lane];
        float a = s * u[h * DOD + lane];
        float b = s * v[h * DOD + lane];
        a = warpsum(a); b = warpsum(b);
        if (lane == 0) { f1[h * NN + n] = a; f2[h * NN + n] = b; }
    }
}

// ---------------- kernel 5: GAT masked-attention aggregation -----------------
__global__ void __launch_bounds__(128) k_gat(const float* __restrict__ adjP,
                                             const float* __restrict__ adjN) {
    __shared__ int s_cnt;
    __shared__ int s_list[512];
    __shared__ float s_a[512];
    const float* adj; const float* sup; const float* f1; const float* f2;
    const float* resid; float* outp;
    if (blockIdx.y == 0) { adj = adjP; sup = g_supP; f1 = g_f1P; f2 = g_f2P; resid = g_residP; outp = g_gatP; }
    else                 { adj = adjN; sup = g_supN; f1 = g_f1N; f2 = g_f2N; resid = g_residN; outp = g_gatN; }
    int i = blockIdx.x, tid = threadIdx.x;
    int h = tid >> 5;
    float f2i = f2[h * NN + i];
    float num = 0.f, den = 0.f;

    for (int c0 = 0; c0 < NN; c0 += 16384) {
        if (tid == 0) s_cnt = 0;
        __syncthreads();
        int cend = c0 + 16384; if (cend > NN) cend = NN;
        for (int j = c0 + tid; j < cend; j += 128) {
            float a = adj[(size_t)i * NN + j];
            if (a != 0.f) {
                int p = atomicAdd(&s_cnt, 1);
                s_list[p] = j;
                s_a[p] = a;
            }
        }
        __syncthreads();
        int cnt = s_cnt;
        for (int t = 0; t < cnt; t++) {
            int j = s_list[t];
            float w = f1[h * NN + j] + f2i;
            w = (w > 0.f) ? w : 0.2f * w;
            w *= s_a[t];
            den += w;
            num += w * sup[(size_t)j * HH + tid];
        }
        __syncthreads();
    }
    float d = (den == 0.f) ? 1.f : den;
    outp[(size_t)i * HH + tid] = num / d + resid[(size_t)i * HH + tid];
}

// ---------------- kernel 6: zero colsum --------------------------------------
__global__ void k_zero() { if (threadIdx.x < HH) g_colsum[threadIdx.x] = 0.f; }

// ---------------- kernel 7: semantic attention, warp-per-node ----------------
__global__ void __launch_bounds__(256) k_sem(const float* __restrict__ W1,
                                             const float* __restrict__ b1,
                                             const float* __restrict__ W2) {
    __shared__ float W1s[128 * 65];
    __shared__ float W2s[SEMD], b1s[SEMD];
    __shared__ float semb[8][3][128];
    int tid = threadIdx.x;
    for (int i = tid; i < 128 * 64; i += 256) {
        int k = i >> 6, s = i & 63;
        W1s[k * 65 + s] = W1[i];
    }
    if (tid < SEMD) { W2s[tid] = W2[tid]; b1s[tid] = b1[tid]; }
    __syncthreads();

    int w = tid >> 5, lane = tid & 31;
    float csum[4] = {0.f, 0.f, 0.f, 0.f};
    int nbase = (blockIdx.x * 8 + w) * 8;

    for (int i = 0; i < 8; i++) {
        int n = nbase + i;
        float4 ev[3];
        ev[0] = *(const float4*)&g_selfE[(size_t)n * HH + lane * 4];
        ev[1] = *(const float4*)&g_posE[(size_t)n * HH + lane * 4];
        ev[2] = *(const float4*)&g_negE[(size_t)n * HH + lane * 4];
        __syncwarp();
        *(float4*)&semb[w][0][lane * 4] = ev[0];
        *(float4*)&semb[w][1][lane * 4] = ev[1];
        *(float4*)&semb[w][2][lane * 4] = ev[2];
        __syncwarp();

        float acc[3][2];
#pragma unroll
        for (int e = 0; e < 3; e++) { acc[e][0] = b1s[lane]; acc[e][1] = b1s[lane + 32]; }
#pragma unroll 4
        for (int k = 0; k < HH; k++) {
            float w1a = W1s[k * 65 + lane];
            float w1b = W1s[k * 65 + lane + 32];
            float x0 = semb[w][0][k], x1 = semb[w][1][k], x2 = semb[w][2][k];
            acc[0][0] += x0 * w1a; acc[0][1] += x0 * w1b;
            acc[1][0] += x1 * w1a; acc[1][1] += x1 * w1b;
            acc[2][0] += x2 * w1a; acc[2][1] += x2 * w1b;
        }
        float wv[3];
#pragma unroll
        for (int e = 0; e < 3; e++) {
            float tsum = tanh_fast(acc[e][0]) * W2s[lane] +
                         tanh_fast(acc[e][1]) * W2s[lane + 32];
            wv[e] = warpsum_bfly(tsum);
        }
        float m = fmaxf(wv[0], fmaxf(wv[1], wv[2]));
        float e0 = __expf(wv[0] - m), e1 = __expf(wv[1] - m), e2 = __expf(wv[2] - m);
        float inv = __fdividef(1.f, e0 + e1 + e2);
        float be0 = e0 * inv, be1 = e1 * inv, be2 = e2 * inv;
        float4 f;
        f.x = be0 * ev[0].x + be1 * ev[1].x + be2 * ev[2].x;
        f.y = be0 * ev[0].y + be1 * ev[1].y + be2 * ev[2].y;
        f.z = be0 * ev[0].z + be1 * ev[1].z + be2 * ev[2].z;
        f.w = be0 * ev[0].w + be1 * ev[1].w + be2 * ev[2].w;
        *(float4*)&g_fused[(size_t)n * HH + lane * 4] = f;
        csum[0] += f.x; csum[1] += f.y; csum[2] += f.z; csum[3] += f.w;
    }
    atomicAdd(&g_colsum[lane * 4 + 0], csum[0]);
    atomicAdd(&g_colsum[lane * 4 + 1], csum[1]);
    atomicAdd(&g_colsum[lane * 4 + 2], csum[2]);
    atomicAdd(&g_colsum[lane * 4 + 3], csum[3]);
}

// ---------------- kernel 8: pairnorm + predictor -----------------------------
__global__ void __launch_bounds__(256) k_pred(const float* __restrict__ W1,
                                              const float* __restrict__ b1,
                                              const float* __restrict__ W2,
                                              const float* __restrict__ b2,
                                              float* __restrict__ out) {
    __shared__ float W1s[HH * PHD];
    __shared__ float xns[8][HH];
    int tid = threadIdx.x;
    for (int i = tid; i < HH * PHD; i += 256) W1s[i] = W1[i];
    int w = tid >> 5, lane = tid & 31;
    int n = blockIdx.x * 8 + w;
    float xv[4]; float ss = 0.f;
    const float invN = 1.f / (float)NN;
#pragma unroll
    for (int j = 0; j < 4; j++) {
        int d = lane + j * 32;
        float x = g_fused[(size_t)n * HH + d] - g_colsum[d] * invN;
        xv[j] = x; ss += x * x;
    }
    ss = warpsum(ss);
    ss = __shfl_sync(0xffffffffu, ss, 0);
    float rinv = rsqrtf(1e-6f + ss);
#pragma unroll
    for (int j = 0; j < 4; j++) xns[w][lane + j * 32] = xv[j] * rinv;
    __syncthreads();

    float acc = b1[lane];
#pragma unroll 4
    for (int k = 0; k < HH; k++) acc += xns[w][k] * W1s[k * PHD + lane];
    float hgt = acc > 0.f ? acc : 0.f;
    float o = warpsum(hgt * W2[lane]);
    if (lane == 0) out[n] = sigmoid_fast(o + b2[0]);
}

// ---------------- launch -----------------------------------------------------
extern "C" void kernel_launch(void* const* d_in, const int* in_sizes, int n_in,
                              void* d_out, int out_size) {
    const float* features = (const float*)d_in[0];
    const float* pos_adj  = (const float*)d_in[1];
    const float* neg_adj  = (const float*)d_in[2];
    const float* gru_Wih  = (const float*)d_in[3];
    const float* gru_Whh  = (const float*)d_in[4];
    const float* gru_bih  = (const float*)d_in[5];
    const float* gru_bhh  = (const float*)d_in[6];
    const float* pos_W    = (const float*)d_in[7];
    const float* pos_u    = (const float*)d_in[8];
    const float* pos_v    = (const float*)d_in[9];
    const float* pos_b    = (const float*)d_in[10];
    const float* pos_pW   = (const float*)d_in[11];
    const float* pos_pb   = (const float*)d_in[12];
    const float* neg_W    = (const float*)d_in[13];
    const float* neg_u    = (const float*)d_in[14];
    const float* neg_v    = (const float*)d_in[15];
    const float* neg_b    = (const float*)d_in[16];
    const float* neg_pW   = (const float*)d_in[17];
    const float* neg_pb   = (const float*)d_in[18];
    const float* self_W   = (const float*)d_in[19];
    const float* self_b   = (const float*)d_in[20];
    const float* mpos_W   = (const float*)d_in[21];
    const float* mpos_b   = (const float*)d_in[22];
    const float* mneg_W   = (const float*)d_in[23];
    const float* mneg_b   = (const float*)d_in[24];
    const float* sem_W1   = (const float*)d_in[25];
    const float* sem_b1   = (const float*)d_in[26];
    const float* sem_W2   = (const float*)d_in[27];
    const float* pred_W1  = (const float*)d_in[28];
    const float* pred_b1  = (const float*)d_in[29];
    const float* pred_W2  = (const float*)d_in[30];
    const float* pred_b2  = (const float*)d_in[31];
    float* out = (float*)d_out;

    static bool attr_done = false;
    if (!attr_done) {
        cudaFuncSetAttribute(k_gru, cudaFuncAttributeMaxDynamicSharedMemorySize, GRU_SMEM);
        cudaFuncSetAttribute(k_gemm, cudaFuncAttributeMaxDynamicSharedMemorySize, GEMM_SMEM);
        attr_done = true;
    }

    float *p_support, *p_gatP, *p_gatN, *p_supP, *p_supN;
    float *p_residP, *p_residN, *p_selfE, *p_posE, *p_negE;
    cudaGetSymbolAddress((void**)&p_support, g_support);
    cudaGetSymbolAddress((void**)&p_supP, g_supP);
    cudaGetSymbolAddress((void**)&p_supN, g_supN);
    cudaGetSymbolAddress((void**)&p_residP, g_residP);
    cudaGetSymbolAddress((void**)&p_residN, g_residN);
    cudaGetSymbolAddress((void**)&p_selfE, g_selfE);
    cudaGetSymbolAddress((void**)&p_gatP, g_gatP);
    cudaGetSymbolAddress((void**)&p_gatN, g_gatN);
    cudaGetSymbolAddress((void**)&p_posE, g_posE);
    cudaGetSymbolAddress((void**)&p_negE, g_negE);

    k_prep<<<48, 256>>>(gru_Whh);                                   // 1
    k_prep_wih<<<6, 256>>>(gru_Wih);                                // 2
    k_zero<<<1, 128>>>();                                           // 3
    k_gru<<<NN / 32, 512, GRU_SMEM>>>(features, gru_bih, gru_bhh);  // 4
    {
        GemmJobs jb;
        jb.j[0] = { p_support, pos_W,  nullptr, nullptr, p_supP };
        jb.j[1] = { p_support, neg_W,  nullptr, nullptr, p_supN };
        jb.j[2] = { p_support, pos_pW, pos_b,   pos_pb,  p_residP };
        jb.j[3] = { p_support, neg_pW, neg_b,   neg_pb,  p_residN };
        jb.j[4] = { p_support, self_W, self_b,  nullptr, p_selfE };
        dim3 grid(NN / 128, 5);
        k_gemm<<<grid, 256, GEMM_SMEM>>>(jb);                       // 5
    }
    {
        dim3 grid(NN / 8, 2);
        k_f1f2<<<grid, 256>>>(pos_u, pos_v, neg_u, neg_v);          // 6
    }
    {
        dim3 grid(NN, 2);
        k_gat<<<grid, 128>>>(pos_adj, neg_adj);                     // 7
    }
    {
        GemmJobs jb;
        jb.j[0] = { p_gatP, mpos_W, mpos_b, nullptr, p_posE };
        jb.j[1] = { p_gatN, mneg_W, mneg_b, nullptr, p_negE };
        jb.j[2] = jb.j[0]; jb.j[3] = jb.j[0]; jb.j[4] = jb.j[0];
        dim3 grid(NN / 128, 2);
        k_gemm<<<grid, 256, GEMM_SMEM>>>(jb);                       // 8
    }
    k_sem<<<NN / 64, 256>>>(sem_W1, sem_b1, sem_W2);                // 9
    k_pred<<<NN / 8, 256>>>(pred_W1, pred_b1, pred_W2, pred_b2, out); // 10
}

// round 9
// speedup vs baseline: 8.3048x; 1.0008x over previous
#include <cuda_runtime.h>
#include <cuda_bf16.h>
#include <cstdint>
#include <cstddef>

#define NN 4096
#define TT 24
#define FF 16
#define HH 128
#define GG 384
#define NHD 4
#define DOD 32
#define SEMD 64
#define PHD 32

// ---------------- scratch (static device globals; no runtime allocation) ----
__device__ float g_support[NN * HH];
__device__ float g_supP[NN * HH];
__device__ float g_supN[NN * HH];
__device__ float g_residP[NN * HH];
__device__ float g_residN[NN * HH];
__device__ float g_selfE[NN * HH];
__device__ float g_f1P[NHD * NN];
__device__ float g_f2P[NHD * NN];
__device__ float g_f1N[NHD * NN];
__device__ float g_f2N[NHD * NN];
__device__ float g_gatP[NN * HH];
__device__ float g_gatN[NN * HH];
__device__ float g_posE[NN * HH];
__device__ float g_negE[NN * HH];
__device__ float g_fused[NN * HH];
__device__ float g_colsum[HH];
// bf16 fragment-ordered Whh: hi (smem-staged), lo (streamed, uint4+uint2/warp)
__device__ __align__(16) uint32_t g_Bhi[8 * 8 * 6 * 32 * 2];   // 24576 words (96 KB)
__device__ __align__(16) uint32_t g_Blo[8 * 8 * 2 * 32 * 8];   // 32768 words
// bf16 fragment-ordered Wih (k=16 -> one k-chunk)
__device__ __align__(16) uint32_t g_WihHi[8 * 6 * 32 * 2];
__device__ __align__(16) uint32_t g_WihLo[8 * 2 * 32 * 8];

__device__ __forceinline__ float warpsum(float v) {
#pragma unroll
    for (int o = 16; o >= 1; o >>= 1) v += __shfl_down_sync(0xffffffffu, v, o);
    return v;
}
__device__ __forceinline__ float warpsum_bfly(float v) {
#pragma unroll
    for (int o = 16; o >= 1; o >>= 1) v += __shfl_xor_sync(0xffffffffu, v, o);
    return v;
}
__device__ __forceinline__ float sigmoid_fast(float x) {
    return __fdividef(1.f, 1.f + __expf(-x));
}
__device__ __forceinline__ float tanh_fast(float x) {
    float e = __expf(-2.f * x);
    return __fdividef(2.f, 1.f + e) - 1.f;
}
__device__ __forceinline__ uint32_t f2tf32(float f) {
    uint32_t u; asm("cvt.rna.tf32.f32 %0, %1;" : "=r"(u) : "f"(f)); return u;
}
__device__ __forceinline__ void mma_tf32(float d[4], const uint32_t a[4],
                                         uint32_t b0, uint32_t b1) {
    asm volatile("mma.sync.aligned.m16n8k8.row.col.f32.tf32.tf32.f32 "
                 "{%0,%1,%2,%3}, {%4,%5,%6,%7}, {%8,%9}, {%0,%1,%2,%3};"
                 : "+f"(d[0]), "+f"(d[1]), "+f"(d[2]), "+f"(d[3])
                 : "r"(a[0]), "r"(a[1]), "r"(a[2]), "r"(a[3]), "r"(b0), "r"(b1));
}
__device__ __forceinline__ void mma_bf16(float d[4], const uint32_t a[4],
                                         uint32_t b0, uint32_t b1) {
    asm volatile("mma.sync.aligned.m16n8k16.row.col.f32.bf16.bf16.f32 "
                 "{%0,%1,%2,%3}, {%4,%5,%6,%7}, {%8,%9}, {%0,%1,%2,%3};"
                 : "+f"(d[0]), "+f"(d[1]), "+f"(d[2]), "+f"(d[3])
                 : "r"(a[0]), "r"(a[1]), "r"(a[2]), "r"(a[3]), "r"(b0), "r"(b1));
}

// ---------------- kernel 0a: bf16 fragment-ordered Whh -----------------------
__global__ void k_prep(const float* __restrict__ Whh) {
    int idx = blockIdx.x * 256 + threadIdx.x;       // 12288 = 8*8*6*32
    if (idx >= 8 * 8 * 6 * 32) return;
    int lane = idx & 31; int r = idx >> 5;
    int nt = r % 6; r /= 6;
    int w8 = r & 7; int kt = r >> 3;                 // kt in [0,8)
    int g = nt >> 1, s = nt & 1;
    int n = g * 128 + w8 * 16 + s * 8 + (lane >> 2);
    int kb = kt * 16 + (lane & 3) * 2;
    float w0 = Whh[n * 128 + kb],     w1 = Whh[n * 128 + kb + 1];
    float w2 = Whh[n * 128 + kb + 8], w3 = Whh[n * 128 + kb + 9];
    __nv_bfloat16 h0 = __float2bfloat16(w0), h1 = __float2bfloat16(w1);
    __nv_bfloat16 h2 = __float2bfloat16(w2), h3 = __float2bfloat16(w3);
    {
        __nv_bfloat162 v; v.x = h0; v.y = h1;
        g_Bhi[idx * 2 + 0] = *(uint32_t*)&v;
        v.x = h2; v.y = h3;
        g_Bhi[idx * 2 + 1] = *(uint32_t*)&v;
    }
    __nv_bfloat162 l01, l23;
    l01.x = __float2bfloat16(w0 - __bfloat162float(h0));
    l01.y = __float2bfloat16(w1 - __bfloat162float(h1));
    l23.x = __float2bfloat16(w2 - __bfloat162float(h2));
    l23.y = __float2bfloat16(w3 - __bfloat162float(h3));
    uint32_t* lo = &g_Blo[(((kt * 8 + w8) * 2 + s) * 32 + lane) * 8 + g * 2];
    lo[0] = *(uint32_t*)&l01;
    lo[1] = *(uint32_t*)&l23;
}

// ---------------- kernel 0b: bf16 fragment-ordered Wih (k=16) ---------------
__global__ void k_prep_wih(const float* __restrict__ Wih) {
    int idx = blockIdx.x * 256 + threadIdx.x;       // 1536 = 8*6*32
    if (idx >= 8 * 6 * 32) return;
    int lane = idx & 31; int r = idx >> 5;
    int nt = r % 6; int w8 = r / 6;
    int g = nt >> 1, s = nt & 1;
    int n = g * 128 + w8 * 16 + s * 8 + (lane >> 2);
    int kb = (lane & 3) * 2;
    float w0 = Wih[n * FF + kb],     w1 = Wih[n * FF + kb + 1];
    float w2 = Wih[n * FF + kb + 8], w3 = Wih[n * FF + kb + 9];
    __nv_bfloat16 h0 = __float2bfloat16(w0), h1 = __float2bfloat16(w1);
    __nv_bfloat16 h2 = __float2bfloat16(w2), h3 = __float2bfloat16(w3);
    {
        __nv_bfloat162 v; v.x = h0; v.y = h1;
        g_WihHi[idx * 2 + 0] = *(uint32_t*)&v;
        v.x = h2; v.y = h3;
        g_WihHi[idx * 2 + 1] = *(uint32_t*)&v;
    }
    __nv_bfloat162 l01, l23;
    l01.x = __float2bfloat16(w0 - __bfloat162float(h0));
    l01.y = __float2bfloat16(w1 - __bfloat162float(h1));
    l23.x = __float2bfloat16(w2 - __bfloat162float(h2));
    l23.y = __float2bfloat16(w3 - __bfloat162float(h3));
    uint32_t* lo = &g_WihLo[((w8 * 2 + s) * 32 + lane) * 8 + g * 2];
    lo[0] = *(uint32_t*)&l01;
    lo[1] = *(uint32_t*)&l23;
}

// ---------------- kernel 2: fused GRU scan, bf16x3 split, 512 threads -------
// smem: Bhi 24576 words (96 KB) + h_hi/h_lo bf16 [32][136] each (17408 B)
#define GRU_SMEM (24576 * 4 + 2 * 32 * 136 * 2)

__global__ void __launch_bounds__(512, 1) k_gru(const float* __restrict__ feat,
                                                const float* __restrict__ bih,
                                                const float* __restrict__ bhh) {
    extern __shared__ float sm[];
    uint32_t* Bhi_s = (uint32_t*)sm;                 // 24576 words
    uint32_t* h_hi_w = Bhi_s + 24576;                // 32*68 words (bf16 [32][136])
    uint32_t* h_lo_w = h_hi_w + 32 * 68;
    int tid = threadIdx.x;
    int w = tid >> 5, lane = tid & 31;
    int w8 = w >> 1, s = w & 1;
    int qr = lane >> 2, qc = lane & 3;
    int hc = w * 8;                                  // 8 output cols per warp
    int node0 = blockIdx.x * 32;

    {
        const uint4* src = (const uint4*)g_Bhi;
        uint4* dst = (uint4*)Bhi_s;
        for (int i = tid; i < 24576 / 4; i += 512) dst[i] = src[i];
        for (int i = tid; i < 2 * 32 * 68; i += 512) h_hi_w[i] = 0u;
    }
    // biases: r/z merged (bih+bhh); n-gate split (bih outside r*, bhh inside)
    float bRr[2], bRz[2], biN[2], bhN[2];
#pragma unroll
    for (int jj = 0; jj < 2; jj++) {
        int c = hc + 2 * qc + jj;
        bRr[jj] = __ldg(&bih[c]) + __ldg(&bhh[c]);
        bRz[jj] = __ldg(&bih[128 + c]) + __ldg(&bhh[128 + c]);
        biN[jj] = __ldg(&bih[256 + c]);
        bhN[jj] = __ldg(&bhh[256 + c]);
    }
    __syncthreads();

    const uint2* Bhi2 = (const uint2*)Bhi_s;
    const uint2* WihHi2 = (const uint2*)g_WihHi;

    for (int t = 0; t < TT; t++) {
        // ---- x loads (fp32 pairs) issued early ----
        float2 xr[2][4];
#pragma unroll
        for (int m = 0; m < 2; m++) {
            const float* base = feat + (size_t)(node0 + m * 16) * (TT * FF) + t * FF;
            xr[m][0] = __ldg((const float2*)(base + (size_t)qr * (TT * FF) + 2 * qc));
            xr[m][1] = __ldg((const float2*)(base + (size_t)(qr + 8) * (TT * FF) + 2 * qc));
            xr[m][2] = __ldg((const float2*)(base + (size_t)qr * (TT * FF) + 2 * qc + 8));
            xr[m][3] = __ldg((const float2*)(base + (size_t)(qr + 8) * (TT * FF) + 2 * qc + 8));
        }

        float d[2][3][4];   // h-part accumulators (r,z,n)
        float dx[2][4];     // x-part of n-gate
#pragma unroll
        for (int m = 0; m < 2; m++) {
#pragma unroll
            for (int g = 0; g < 3; g++)
#pragma unroll
                for (int j = 0; j < 4; j++) d[m][g][j] = 0.f;
#pragma unroll
            for (int j = 0; j < 4; j++) dx[m][j] = 0.f;
        }

        // ---- h @ Whh^T (bf16 m16n8k16, 3-term split, term-interleaved) ----
        if (t) {
            uint4 blwA, nwA; uint2 blwB, nwB;
            {
                const uint32_t* p = &g_Blo[(((0 * 8 + w8) * 2 + s) * 32 + lane) * 8];
                blwA = *(const uint4*)p; blwB = *(const uint2*)(p + 4);
            }
#pragma unroll 2
            for (int kt = 0; kt < 8; kt++) {
                if (kt < 7) {
                    const uint32_t* p = &g_Blo[((((kt + 1) * 8 + w8) * 2 + s) * 32 + lane) * 8];
                    nwA = *(const uint4*)p; nwB = *(const uint2*)(p + 4);
                }
                uint32_t ah[2][4], al[2][4];
#pragma unroll
                for (int m = 0; m < 2; m++) {
                    int r0 = (m * 16 + qr) * 68 + kt * 8 + qc;
                    ah[m][0] = h_hi_w[r0];
                    ah[m][1] = h_hi_w[r0 + 8 * 68];
                    ah[m][2] = h_hi_w[r0 + 4];
                    ah[m][3] = h_hi_w[r0 + 8 * 68 + 4];
                    al[m][0] = h_lo_w[r0];
                    al[m][1] = h_lo_w[r0 + 8 * 68];
                    al[m][2] = h_lo_w[r0 + 4];
                    al[m][3] = h_lo_w[r0 + 8 * 68 + 4];
                }
                uint32_t lw[6] = {blwA.x, blwA.y, blwA.z, blwA.w, blwB.x, blwB.y};
                uint2 bh[3];
#pragma unroll
                for (int g = 0; g < 3; g++)
                    bh[g] = Bhi2[((kt * 8 + w8) * 6 + g * 2 + s) * 32 + lane];
                // term 0: ah x bh   (6 independent accumulators in a row)
#pragma unroll
                for (int g = 0; g < 3; g++)
#pragma unroll
                    for (int m = 0; m < 2; m++)
                        mma_bf16(d[m][g], ah[m], bh[g].x, bh[g].y);
                // term 1: al x bh
#pragma unroll
                for (int g = 0; g < 3; g++)
#pragma unroll
                    for (int m = 0; m < 2; m++)
                        mma_bf16(d[m][g], al[m], bh[g].x, bh[g].y);
                // term 2: ah x bl
#pragma unroll
                for (int g = 0; g < 3; g++)
#pragma unroll
                    for (int m = 0; m < 2; m++)
                        mma_bf16(d[m][g], ah[m], lw[g * 2], lw[g * 2 + 1]);
                blwA = nwA; blwB = nwB;
            }
        }

        // ---- x @ Wih^T fused (k=16, one chunk, term-interleaved) ----
        {
            uint32_t xh[2][4], xl[2][4];
#pragma unroll
            for (int m = 0; m < 2; m++)
#pragma unroll
                for (int j = 0; j < 4; j++) {
                    float v0 = xr[m][j].x, v1 = xr[m][j].y;
                    __nv_bfloat162 hv; hv.x = __float2bfloat16(v0); hv.y = __float2bfloat16(v1);
                    xh[m][j] = *(uint32_t*)&hv;
                    __nv_bfloat162 lv;
                    lv.x = __float2bfloat16(v0 - __bfloat162float(hv.x));
                    lv.y = __float2bfloat16(v1 - __bfloat162float(hv.y));
                    xl[m][j] = *(uint32_t*)&lv;
                }
            const uint32_t* p = &g_WihLo[((w8 * 2 + s) * 32 + lane) * 8];
            uint4 wlA = *(const uint4*)p; uint2 wlB = *(const uint2*)(p + 4);
            uint32_t wlw[6] = {wlA.x, wlA.y, wlA.z, wlA.w, wlB.x, wlB.y};
            uint2 bh[3];
#pragma unroll
            for (int g = 0; g < 3; g++)
                bh[g] = __ldg(&WihHi2[(w8 * 6 + g * 2 + s) * 32 + lane]);
#pragma unroll
            for (int g = 0; g < 3; g++)
#pragma unroll
                for (int m = 0; m < 2; m++) {
                    float* D = (g == 2) ? dx[m] : d[m][g];
                    mma_bf16(D, xh[m], bh[g].x, bh[g].y);
                }
#pragma unroll
            for (int g = 0; g < 3; g++)
#pragma unroll
                for (int m = 0; m < 2; m++) {
                    float* D = (g == 2) ? dx[m] : d[m][g];
                    mma_bf16(D, xl[m], bh[g].x, bh[g].y);
                }
#pragma unroll
            for (int g = 0; g < 3; g++)
#pragma unroll
                for (int m = 0; m < 2; m++) {
                    float* D = (g == 2) ? dx[m] : d[m][g];
                    mma_bf16(D, xh[m], wlw[g * 2], wlw[g * 2 + 1]);
                }
        }

        // ---- gate math ----
        float hn[2][2][2];
#pragma unroll
        for (int m = 0; m < 2; m++)
#pragma unroll
            for (int rg = 0; rg < 2; rg++) {
                int row = m * 16 + qr + rg * 8;
                int wi = row * 68 + w * 4 + qc;
                float2 hhf = __bfloat1622float2(*(__nv_bfloat162*)&h_hi_w[wi]);
                float2 hlf = __bfloat1622float2(*(__nv_bfloat162*)&h_lo_w[wi]);
#pragma unroll
                for (int jj = 0; jj < 2; jj++) {
                    float hold = jj ? (hhf.y + hlf.y) : (hhf.x + hlf.x);
                    int di = rg * 2 + jj;
                    float rr = sigmoid_fast(d[m][0][di] + bRr[jj]);
                    float zz = sigmoid_fast(d[m][1][di] + bRz[jj]);
                    float nv = tanh_fast(dx[m][di] + biN[jj] +
                                         rr * (d[m][2][di] + bhN[jj]));
                    hn[m][rg][jj] = (1.f - zz) * nv + zz * hold;
                }
            }
        __syncthreads();
#pragma unroll
        for (int m = 0; m < 2; m++)
#pragma unroll
            for (int rg = 0; rg < 2; rg++) {
                int row = m * 16 + qr + rg * 8;
                int wi = row * 68 + w * 4 + qc;
                float h0 = hn[m][rg][0], h1 = hn[m][rg][1];
                __nv_bfloat162 hv; hv.x = __float2bfloat16(h0); hv.y = __float2bfloat16(h1);
                __nv_bfloat162 lv;
                lv.x = __float2bfloat16(h0 - __bfloat162float(hv.x));
                lv.y = __float2bfloat16(h1 - __bfloat162float(hv.y));
                h_hi_w[wi] = *(uint32_t*)&hv;
                h_lo_w[wi] = *(uint32_t*)&lv;
            }
        __syncthreads();
    }

    const __nv_bfloat16* h_hi = (const __nv_bfloat16*)h_hi_w;
    const __nv_bfloat16* h_lo = (const __nv_bfloat16*)h_lo_w;
    for (int i = tid; i < 32 * HH; i += 512) {
        int row = i >> 7, col = i & 127;
        g_support[(size_t)(node0 + row) * HH + col] =
            __bfloat162float(h_hi[row * 136 + col]) +
            __bfloat162float(h_lo[row * 136 + col]);
    }
}

// ---------------- kernel 3: tensor-core GEMM C[4096,128] = A @ B (+b1+b2) ---
struct GemmJob { const float* A; const float* B; const float* b1; const float* b2; float* C; };
struct GemmJobs { GemmJob j[5]; };

#define GEMM_SMEM 204800

__global__ void __launch_bounds__(256) k_gemm(GemmJobs jobs) {
    GemmJob job = jobs.j[blockIdx.y];
    extern __shared__ char smc[];
    float* As_hi = (float*)smc;                               // [128][132]
    float* Bs_hi = As_hi + 128 * 132;                         // [128][132]
    uint16_t* As_lo = (uint16_t*)(Bs_hi + 128 * 132);         // [128][136]
    uint16_t* Bs_lo = As_lo + 128 * 136;                      // [128][136]
    int tid = threadIdx.x;
    int node0 = blockIdx.x * 128;

    for (int idx = tid; idx < 128 * 128; idx += 256) {
        int r = idx >> 7, c = idx & 127;
        float a = job.A[(size_t)(node0 + r) * HH + c];
        uint32_t ha = f2tf32(a);
        As_hi[r * 132 + c] = __uint_as_float(ha);
        As_lo[r * 136 + c] =
            __bfloat16_as_ushort(__float2bfloat16(a - __uint_as_float(ha)));
        float b = job.B[idx];
        uint32_t hb = f2tf32(b);
        Bs_hi[r * 132 + c] = __uint_as_float(hb);
        Bs_lo[r * 136 + c] =
            __bfloat16_as_ushort(__float2bfloat16(b - __uint_as_float(hb)));
    }
    __syncthreads();

    int w = tid >> 5, lane = tid & 31;
    int qr = lane >> 2, qc = lane & 3;
    int r0 = w * 16;
    float acc[16][4];
#pragma unroll
    for (int ct = 0; ct < 16; ct++)
#pragma unroll
        for (int j = 0; j < 4; j++) acc[ct][j] = 0.f;

#pragma unroll 1
    for (int kt = 0; kt < 16; kt++) {
        int kc = kt * 8 + qc;
        uint32_t ah[4], al[4];
        ah[0] = __float_as_uint(As_hi[(r0 + qr) * 132 + kc]);
        ah[1] = __float_as_uint(As_hi[(r0 + qr + 8) * 132 + kc]);
        ah[2] = __float_as_uint(As_hi[(r0 + qr) * 132 + kc + 4]);
        ah[3] = __float_as_uint(As_hi[(r0 + qr + 8) * 132 + kc + 4]);
        al[0] = (uint32_t)As_lo[(r0 + qr) * 136 + kc] << 16;
        al[1] = (uint32_t)As_lo[(r0 + qr + 8) * 136 + kc] << 16;
        al[2] = (uint32_t)As_lo[(r0 + qr) * 136 + kc + 4] << 16;
        al[3] = (uint32_t)As_lo[(r0 + qr + 8) * 136 + kc + 4] << 16;
#pragma unroll
        for (int cg = 0; cg < 4; cg++) {
            uint32_t bh0[4], bh1[4], bl0[4], bl1[4];
#pragma unroll
            for (int j = 0; j < 4; j++) {
                int n0 = (cg * 4 + j) * 8;
                bh0[j] = __float_as_uint(Bs_hi[kc * 132 + n0 + qr]);
                bh1[j] = __float_as_uint(Bs_hi[(kc + 4) * 132 + n0 + qr]);
                bl0[j] = (uint32_t)Bs_lo[kc * 136 + n0 + qr] << 16;
                bl1[j] = (uint32_t)Bs_lo[(kc + 4) * 136 + n0 + qr] << 16;
            }
#pragma unroll
            for (int j = 0; j < 4; j++)
                mma_tf32(acc[cg * 4 + j], ah, bh0[j], bh1[j]);
#pragma unroll
            for (int j = 0; j < 4; j++)
                mma_tf32(acc[cg * 4 + j], al, bh0[j], bh1[j]);
#pragma unroll
            for (int j = 0; j < 4; j++)
                mma_tf32(acc[cg * 4 + j], ah, bl0[j], bl1[j]);
        }
    }

#pragma unroll
    for (int ct = 0; ct < 16; ct++) {
        int c0 = ct * 8 + 2 * qc;
        float b0 = 0.f, b1v = 0.f;
        if (job.b1) { b0 += __ldg(&job.b1[c0]); b1v += __ldg(&job.b1[c0 + 1]); }
        if (job.b2) { b0 += __ldg(&job.b2[c0]); b1v += __ldg(&job.b2[c0 + 1]); }
        int r = node0 + r0 + qr;
        *(float2*)&job.C[(size_t)r * HH + c0] =
            make_float2(acc[ct][0] + b0, acc[ct][1] + b1v);
        *(float2*)&job.C[(size_t)(r + 8) * HH + c0] =
            make_float2(acc[ct][2] + b0, acc[ct][3] + b1v);
    }
}

// ---------------- kernel 4: f1/f2 per head -----------------------------------
__global__ void k_f1f2(const float* __restrict__ uP, const float* __restrict__ vP,
                       const float* __restrict__ uN, const float* __restrict__ vN) {
    const float* sup; const float* u; const float* v; float* f1; float* f2;
    if (blockIdx.y == 0) { sup = g_supP; u = uP; v = vP; f1 = g_f1P; f2 = g_f2P; }
    else                 { sup = g_supN; u = uN; v = vN; f1 = g_f1N; f2 = g_f2N; }
    int n = blockIdx.x * 8 + (threadIdx.x >> 5);
    int lane = threadIdx.x & 31;
#pragma unroll
    for (int h = 0; h < NHD; h++) {
        float s = sup[(size_t)n * HH + h * DOD + lane];
        float a = s * u[h * DOD + lane];
        float b = s * v[h * DOD + lane];
        a = warpsum(a); b = warpsum(b);
        if (lane == 0) { f1[h * NN + n] = a; f2[h * NN + n] = b; }
    }
}

// ---------------- kernel 5: GAT masked-attention aggregation -----------------
__global__ void __launch_bounds__(128) k_gat(const float* __restrict__ adjP,
                                             const float* __restrict__ adjN) {
    __shared__ int s_cnt;
    __shared__ int s_list[512];
    __shared__ float s_a[512];
    const float* adj; const float* sup; const float* f1; const float* f2;
    const float* resid; float* outp;
    if (blockIdx.y == 0) { adj = adjP; sup = g_supP; f1 = g_f1P; f2 = g_f2P; resid = g_residP; outp = g_gatP; }
    else                 { adj = adjN; sup = g_supN; f1 = g_f1N; f2 = g_f2N; resid = g_residN; outp = g_gatN; }
    int i = blockIdx.x, tid = threadIdx.x;
    int h = tid >> 5;
    float f2i = f2[h * NN + i];
    float num = 0.f, den = 0.f;

    for (int c0 = 0; c0 < NN; c0 += 16384) {
        if (tid == 0) s_cnt = 0;
        __syncthreads();
        int cend = c0 + 16384; if (cend > NN) cend = NN;
        for (int j = c0 + tid; j < cend; j += 128) {
            float a = adj[(size_t)i * NN + j];
            if (a != 0.f) {
                int p = atomicAdd(&s_cnt, 1);
                s_list[p] = j;
                s_a[p] = a;
            }
        }
        __syncthreads();
        int cnt = s_cnt;
        for (int t = 0; t < cnt; t++) {
            int j = s_list[t];
            float w = f1[h * NN + j] + f2i;
            w = (w > 0.f) ? w : 0.2f * w;
            w *= s_a[t];
            den += w;
            num += w * sup[(size_t)j * HH + tid];
        }
        __syncthreads();
    }
    float d = (den == 0.f) ? 1.f : den;
    outp[(size_t)i * HH + tid] = num / d + resid[(size_t)i * HH + tid];
}

// ---------------- kernel 6: zero colsum --------------------------------------
__global__ void k_zero() { if (threadIdx.x < HH) g_colsum[threadIdx.x] = 0.f; }

// ---------------- kernel 7: semantic attention, warp-per-node ----------------
__global__ void __launch_bounds__(256) k_sem(const float* __restrict__ W1,
                                             const float* __restrict__ b1,
                                             const float* __restrict__ W2) {
    __shared__ float W1s[128 * 65];
    __shared__ float W2s[SEMD], b1s[SEMD];
    __shared__ float semb[8][3][128];
    int tid = threadIdx.x;
    for (int i = tid; i < 128 * 64; i += 256) {
        int k = i >> 6, s = i & 63;
        W1s[k * 65 + s] = W1[i];
    }
    if (tid < SEMD) { W2s[tid] = W2[tid]; b1s[tid] = b1[tid]; }
    __syncthreads();

    int w = tid >> 5, lane = tid & 31;
    float csum[4] = {0.f, 0.f, 0.f, 0.f};
    int nbase = (blockIdx.x * 8 + w) * 8;

    for (int i = 0; i < 8; i++) {
        int n = nbase + i;
        float4 ev[3];
        ev[0] = *(const float4*)&g_selfE[(size_t)n * HH + lane * 4];
        ev[1] = *(const float4*)&g_posE[(size_t)n * HH + lane * 4];
        ev[2] = *(const float4*)&g_negE[(size_t)n * HH + lane * 4];
        __syncwarp();
        *(float4*)&semb[w][0][lane * 4] = ev[0];
        *(float4*)&semb[w][1][lane * 4] = ev[1];
        *(float4*)&semb[w][2][lane * 4] = ev[2];
        __syncwarp();

        float acc[3][2];
#pragma unroll
        for (int e = 0; e < 3; e++) { acc[e][0] = b1s[lane]; acc[e][1] = b1s[lane + 32]; }
#pragma unroll 4
        for (int k = 0; k < HH; k++) {
            float w1a = W1s[k * 65 + lane];
            float w1b = W1s[k * 65 + lane + 32];
            float x0 = semb[w][0][k], x1 = semb[w][1][k], x2 = semb[w][2][k];
            acc[0][0] += x0 * w1a; acc[0][1] += x0 * w1b;
            acc[1][0] += x1 * w1a; acc[1][1] += x1 * w1b;
            acc[2][0] += x2 * w1a; acc[2][1] += x2 * w1b;
        }
        float wv[3];
#pragma unroll
        for (int e = 0; e < 3; e++) {
            float tsum = tanh_fast(acc[e][0]) * W2s[lane] +
                         tanh_fast(acc[e][1]) * W2s[lane + 32];
            wv[e] = warpsum_bfly(tsum);
        }
        float m = fmaxf(wv[0], fmaxf(wv[1], wv[2]));
        float e0 = __expf(wv[0] - m), e1 = __expf(wv[1] - m), e2 = __expf(wv[2] - m);
        float inv = __fdividef(1.f, e0 + e1 + e2);
        float be0 = e0 * inv, be1 = e1 * inv, be2 = e2 * inv;
        float4 f;
        f.x = be0 * ev[0].x + be1 * ev[1].x + be2 * ev[2].x;
        f.y = be0 * ev[0].y + be1 * ev[1].y + be2 * ev[2].y;
        f.z = be0 * ev[0].z + be1 * ev[1].z + be2 * ev[2].z;
        f.w = be0 * ev[0].w + be1 * ev[1].w + be2 * ev[2].w;
        *(float4*)&g_fused[(size_t)n * HH + lane * 4] = f;
        csum[0] += f.x; csum[1] += f.y; csum[2] += f.z; csum[3] += f.w;
    }
    atomicAdd(&g_colsum[lane * 4 + 0], csum[0]);
    atomicAdd(&g_colsum[lane * 4 + 1], csum[1]);
    atomicAdd(&g_colsum[lane * 4 + 2], csum[2]);
    atomicAdd(&g_colsum[lane * 4 + 3], csum[3]);
}

// ---------------- kernel 8: pairnorm + predictor -----------------------------
__global__ void __launch_bounds__(256) k_pred(const float* __restrict__ W1,
                                              const float* __restrict__ b1,
                                              const float* __restrict__ W2,
                                              const float* __restrict__ b2,
                                              float* __restrict__ out) {
    __shared__ float W1s[HH * PHD];
    __shared__ float xns[8][HH];
    int tid = threadIdx.x;
    for (int i = tid; i < HH * PHD; i += 256) W1s[i] = W1[i];
    int w = tid >> 5, lane = tid & 31;
    int n = blockIdx.x * 8 + w;
    float xv[4]; float ss = 0.f;
    const float invN = 1.f / (float)NN;
#pragma unroll
    for (int j = 0; j < 4; j++) {
        int d = lane + j * 32;
        float x = g_fused[(size_t)n * HH + d] - g_colsum[d] * invN;
        xv[j] = x; ss += x * x;
    }
    ss = warpsum(ss);
    ss = __shfl_sync(0xffffffffu, ss, 0);
    float rinv = rsqrtf(1e-6f + ss);
#pragma unroll
    for (int j = 0; j < 4; j++) xns[w][lane + j * 32] = xv[j] * rinv;
    __syncthreads();

    float acc = b1[lane];
#pragma unroll 4
    for (int k = 0; k < HH; k++) acc += xns[w][k] * W1s[k * PHD + lane];
    float hgt = acc > 0.f ? acc : 0.f;
    float o = warpsum(hgt * W2[lane]);
    if (lane == 0) out[n] = sigmoid_fast(o + b2[0]);
}

// ---------------- launch -----------------------------------------------------
extern "C" void kernel_launch(void* const* d_in, const int* in_sizes, int n_in,
                              void* d_out, int out_size) {
    const float* features = (const float*)d_in[0];
    const float* pos_adj  = (const float*)d_in[1];
    const float* neg_adj  = (const float*)d_in[2];
    const float* gru_Wih  = (const float*)d_in[3];
    const float* gru_Whh  = (const float*)d_in[4];
    const float* gru_bih  = (const float*)d_in[5];
    const float* gru_bhh  = (const float*)d_in[6];
    const float* pos_W    = (const float*)d_in[7];
    const float* pos_u    = (const float*)d_in[8];
    const float* pos_v    = (const float*)d_in[9];
    const float* pos_b    = (const float*)d_in[10];
    const float* pos_pW   = (const float*)d_in[11];
    const float* pos_pb   = (const float*)d_in[12];
    const float* neg_W    = (const float*)d_in[13];
    const float* neg_u    = (const float*)d_in[14];
    const float* neg_v    = (const float*)d_in[15];
    const float* neg_b    = (const float*)d_in[16];
    const float* neg_pW   = (const float*)d_in[17];
    const float* neg_pb   = (const float*)d_in[18];
    const float* self_W   = (const float*)d_in[19];
    const float* self_b   = (const float*)d_in[20];
    const float* mpos_W   = (const float*)d_in[21];
    const float* mpos_b   = (const float*)d_in[22];
    const float* mneg_W   = (const float*)d_in[23];
    const float* mneg_b   = (const float*)d_in[24];
    const float* sem_W1   = (const float*)d_in[25];
    const float* sem_b1   = (const float*)d_in[26];
    const float* sem_W2   = (const float*)d_in[27];
    const float* pred_W1  = (const float*)d_in[28];
    const float* pred_b1  = (const float*)d_in[29];
    const float* pred_W2  = (const float*)d_in[30];
    const float* pred_b2  = (const float*)d_in[31];
    float* out = (float*)d_out;

    static bool attr_done = false;
    if (!attr_done) {
        cudaFuncSetAttribute(k_gru, cudaFuncAttributeMaxDynamicSharedMemorySize, GRU_SMEM);
        cudaFuncSetAttribute(k_gemm, cudaFuncAttributeMaxDynamicSharedMemorySize, GEMM_SMEM);
        attr_done = true;
    }

    float *p_support, *p_gatP, *p_gatN, *p_supP, *p_supN;
    float *p_residP, *p_residN, *p_selfE, *p_posE, *p_negE;
    cudaGetSymbolAddress((void**)&p_support, g_support);
    cudaGetSymbolAddress((void**)&p_supP, g_supP);
    cudaGetSymbolAddress((void**)&p_supN, g_supN);
    cudaGetSymbolAddress((void**)&p_residP, g_residP);
    cudaGetSymbolAddress((void**)&p_residN, g_residN);
    cudaGetSymbolAddress((void**)&p_selfE, g_selfE);
    cudaGetSymbolAddress((void**)&p_gatP, g_gatP);
    cudaGetSymbolAddress((void**)&p_gatN, g_gatN);
    cudaGetSymbolAddress((void**)&p_posE, g_posE);
    cudaGetSymbolAddress((void**)&p_negE, g_negE);

    k_prep<<<48, 256>>>(gru_Whh);                                   // 1
    k_prep_wih<<<6, 256>>>(gru_Wih);                                // 2
    k_zero<<<1, 128>>>();                                           // 3
    k_gru<<<NN / 32, 512, GRU_SMEM>>>(features, gru_bih, gru_bhh);  // 4
    {
        GemmJobs jb;
        jb.j[0] = { p_support, pos_W,  nullptr, nullptr, p_supP };
        jb.j[1] = { p_support, neg_W,  nullptr, nullptr, p_supN };
        jb.j[2] = { p_support, pos_pW, pos_b,   pos_pb,  p_residP };
        jb.j[3] = { p_support, neg_pW, neg_b,   neg_pb,  p_residN };
        jb.j[4] = { p_support, self_W, self_b,  nullptr, p_selfE };
        dim3 grid(NN / 128, 5);
        k_gemm<<<grid, 256, GEMM_SMEM>>>(jb);                       // 5
    }
    {
        dim3 grid(NN / 8, 2);
        k_f1f2<<<grid, 256>>>(pos_u, pos_v, neg_u, neg_v);          // 6
    }
    {
        dim3 grid(NN, 2);
        k_gat<<<grid, 128>>>(pos_adj, neg_adj);                     // 7
    }
    {
        GemmJobs jb;
        jb.j[0] = { p_gatP, mpos_W, mpos_b, nullptr, p_posE };
        jb.j[1] = { p_gatN, mneg_W, mneg_b, nullptr, p_negE };
        jb.j[2] = jb.j[0]; jb.j[3] = jb.j[0]; jb.j[4] = jb.j[0];
        dim3 grid(NN / 128, 2);
        k_gemm<<<grid, 256, GEMM_SMEM>>>(jb);                       // 8
    }
    k_sem<<<NN / 64, 256>>>(sem_W1, sem_b1, sem_W2);                // 9
    k_pred<<<NN / 8, 256>>>(pred_W1, pred_b1, pred_W2, pred_b2, out); // 10
}

// round 10
// speedup vs baseline: 8.3559x; 1.0062x over previous
#include <cuda_runtime.h>
#include <cuda_bf16.h>
#include <cstdint>
#include <cstddef>

#define NN 4096
#define TT 24
#define FF 16
#define HH 128
#define GG 384
#define NHD 4
#define DOD 32
#define SEMD 64
#define PHD 32

// ---------------- scratch (static device globals; no runtime allocation) ----
__device__ float g_support[NN * HH];
__device__ float g_supP[NN * HH];
__device__ float g_supN[NN * HH];
__device__ float g_residP[NN * HH];
__device__ float g_residN[NN * HH];
__device__ float g_selfE[NN * HH];
__device__ float g_f1P[NHD * NN];
__device__ float g_f2P[NHD * NN];
__device__ float g_f1N[NHD * NN];
__device__ float g_f2N[NHD * NN];
__device__ float g_gatP[NN * HH];
__device__ float g_gatN[NN * HH];
__device__ float g_posE[NN * HH];
__device__ float g_negE[NN * HH];
__device__ float g_fused[NN * HH];
__device__ float g_colsum[HH];
// bf16 fragment-ordered Whh: hi (smem-staged), lo (streamed, uint4+uint2/warp)
__device__ __align__(16) uint32_t g_Bhi[8 * 8 * 6 * 32 * 2];   // 24576 words (96 KB)
__device__ __align__(16) uint32_t g_Blo[8 * 8 * 2 * 32 * 8];   // 32768 words
// bf16 fragment-ordered Wih (k=16 -> one k-chunk)
__device__ __align__(16) uint32_t g_WihHi[8 * 6 * 32 * 2];
__device__ __align__(16) uint32_t g_WihLo[8 * 2 * 32 * 8];

__device__ __forceinline__ float warpsum(float v) {
#pragma unroll
    for (int o = 16; o >= 1; o >>= 1) v += __shfl_down_sync(0xffffffffu, v, o);
    return v;
}
__device__ __forceinline__ float warpsum_bfly(float v) {
#pragma unroll
    for (int o = 16; o >= 1; o >>= 1) v += __shfl_xor_sync(0xffffffffu, v, o);
    return v;
}
__device__ __forceinline__ float sigmoid_fast(float x) {
    return __fdividef(1.f, 1.f + __expf(-x));
}
__device__ __forceinline__ float tanh_fast(float x) {
    float e = __expf(-2.f * x);
    return __fdividef(2.f, 1.f + e) - 1.f;
}
__device__ __forceinline__ uint32_t f2tf32(float f) {
    uint32_t u; asm("cvt.rna.tf32.f32 %0, %1;" : "=r"(u) : "f"(f)); return u;
}
__device__ __forceinline__ void mma_tf32(float d[4], const uint32_t a[4],
                                         uint32_t b0, uint32_t b1) {
    asm volatile("mma.sync.aligned.m16n8k8.row.col.f32.tf32.tf32.f32 "
                 "{%0,%1,%2,%3}, {%4,%5,%6,%7}, {%8,%9}, {%0,%1,%2,%3};"
                 : "+f"(d[0]), "+f"(d[1]), "+f"(d[2]), "+f"(d[3])
                 : "r"(a[0]), "r"(a[1]), "r"(a[2]), "r"(a[3]), "r"(b0), "r"(b1));
}
__device__ __forceinline__ void mma_bf16(float d[4], const uint32_t a[4],
                                         uint32_t b0, uint32_t b1) {
    asm volatile("mma.sync.aligned.m16n8k16.row.col.f32.bf16.bf16.f32 "
                 "{%0,%1,%2,%3}, {%4,%5,%6,%7}, {%8,%9}, {%0,%1,%2,%3};"
                 : "+f"(d[0]), "+f"(d[1]), "+f"(d[2]), "+f"(d[3])
                 : "r"(a[0]), "r"(a[1]), "r"(a[2]), "r"(a[3]), "r"(b0), "r"(b1));
}

// ---------------- kernel 0a: bf16 fragment-ordered Whh -----------------------
__global__ void k_prep(const float* __restrict__ Whh) {
    int idx = blockIdx.x * 256 + threadIdx.x;       // 12288 = 8*8*6*32
    if (idx >= 8 * 8 * 6 * 32) return;
    int lane = idx & 31; int r = idx >> 5;
    int nt = r % 6; r /= 6;
    int w8 = r & 7; int kt = r >> 3;                 // kt in [0,8)
    int g = nt >> 1, s = nt & 1;
    int n = g * 128 + w8 * 16 + s * 8 + (lane >> 2);
    int kb = kt * 16 + (lane & 3) * 2;
    float w0 = Whh[n * 128 + kb],     w1 = Whh[n * 128 + kb + 1];
    float w2 = Whh[n * 128 + kb + 8], w3 = Whh[n * 128 + kb + 9];
    __nv_bfloat16 h0 = __float2bfloat16(w0), h1 = __float2bfloat16(w1);
    __nv_bfloat16 h2 = __float2bfloat16(w2), h3 = __float2bfloat16(w3);
    {
        __nv_bfloat162 v; v.x = h0; v.y = h1;
        g_Bhi[idx * 2 + 0] = *(uint32_t*)&v;
        v.x = h2; v.y = h3;
        g_Bhi[idx * 2 + 1] = *(uint32_t*)&v;
    }
    __nv_bfloat162 l01, l23;
    l01.x = __float2bfloat16(w0 - __bfloat162float(h0));
    l01.y = __float2bfloat16(w1 - __bfloat162float(h1));
    l23.x = __float2bfloat16(w2 - __bfloat162float(h2));
    l23.y = __float2bfloat16(w3 - __bfloat162float(h3));
    uint32_t* lo = &g_Blo[(((kt * 8 + w8) * 2 + s) * 32 + lane) * 8 + g * 2];
    lo[0] = *(uint32_t*)&l01;
    lo[1] = *(uint32_t*)&l23;
}

// ---------------- kernel 0b: bf16 fragment-ordered Wih (k=16) ---------------
__global__ void k_prep_wih(const float* __restrict__ Wih) {
    int idx = blockIdx.x * 256 + threadIdx.x;       // 1536 = 8*6*32
    if (idx >= 8 * 6 * 32) return;
    int lane = idx & 31; int r = idx >> 5;
    int nt = r % 6; int w8 = r / 6;
    int g = nt >> 1, s = nt & 1;
    int n = g * 128 + w8 * 16 + s * 8 + (lane >> 2);
    int kb = (lane & 3) * 2;
    float w0 = Wih[n * FF + kb],     w1 = Wih[n * FF + kb + 1];
    float w2 = Wih[n * FF + kb + 8], w3 = Wih[n * FF + kb + 9];
    __nv_bfloat16 h0 = __float2bfloat16(w0), h1 = __float2bfloat16(w1);
    __nv_bfloat16 h2 = __float2bfloat16(w2), h3 = __float2bfloat16(w3);
    {
        __nv_bfloat162 v; v.x = h0; v.y = h1;
        g_WihHi[idx * 2 + 0] = *(uint32_t*)&v;
        v.x = h2; v.y = h3;
        g_WihHi[idx * 2 + 1] = *(uint32_t*)&v;
    }
    __nv_bfloat162 l01, l23;
    l01.x = __float2bfloat16(w0 - __bfloat162float(h0));
    l01.y = __float2bfloat16(w1 - __bfloat162float(h1));
    l23.x = __float2bfloat16(w2 - __bfloat162float(h2));
    l23.y = __float2bfloat16(w3 - __bfloat162float(h3));
    uint32_t* lo = &g_WihLo[((w8 * 2 + s) * 32 + lane) * 8 + g * 2];
    lo[0] = *(uint32_t*)&l01;
    lo[1] = *(uint32_t*)&l23;
}

// ---------------- kernel 2: fused GRU scan, bf16x3 split, 512 threads -------
// smem: Bhi 24576 words (96 KB) + h_hi/h_lo bf16 [32][136] each (17408 B)
#define GRU_SMEM (24576 * 4 + 2 * 32 * 136 * 2)

__global__ void __launch_bounds__(512, 1) k_gru(const float* __restrict__ feat,
                                                const float* __restrict__ bih,
                                                const float* __restrict__ bhh) {
    extern __shared__ float sm[];
    uint32_t* Bhi_s = (uint32_t*)sm;                 // 24576 words
    uint32_t* h_hi_w = Bhi_s + 24576;                // 32*68 words (bf16 [32][136])
    uint32_t* h_lo_w = h_hi_w + 32 * 68;
    int tid = threadIdx.x;
    int w = tid >> 5, lane = tid & 31;
    int w8 = w >> 1, s = w & 1;
    int qr = lane >> 2, qc = lane & 3;
    int hc = w * 8;                                  // 8 output cols per warp
    int node0 = blockIdx.x * 32;

    {
        const uint4* src = (const uint4*)g_Bhi;
        uint4* dst = (uint4*)Bhi_s;
        for (int i = tid; i < 24576 / 4; i += 512) dst[i] = src[i];
        for (int i = tid; i < 2 * 32 * 68; i += 512) h_hi_w[i] = 0u;
    }
    // biases: r/z merged (bih+bhh); n-gate split (bih outside r*, bhh inside)
    float bRr[2], bRz[2], biN[2], bhN[2];
#pragma unroll
    for (int jj = 0; jj < 2; jj++) {
        int c = hc + 2 * qc + jj;
        bRr[jj] = __ldg(&bih[c]) + __ldg(&bhh[c]);
        bRz[jj] = __ldg(&bih[128 + c]) + __ldg(&bhh[128 + c]);
        biN[jj] = __ldg(&bih[256 + c]);
        bhN[jj] = __ldg(&bhh[256 + c]);
    }
    __syncthreads();

    const uint2* Bhi2 = (const uint2*)Bhi_s;
    const uint2* WihHi2 = (const uint2*)g_WihHi;

    for (int t = 0; t < TT; t++) {
        // ---- x loads (fp32 pairs) issued early ----
        float2 xr[2][4];
#pragma unroll
        for (int m = 0; m < 2; m++) {
            const float* base = feat + (size_t)(node0 + m * 16) * (TT * FF) + t * FF;
            xr[m][0] = __ldg((const float2*)(base + (size_t)qr * (TT * FF) + 2 * qc));
            xr[m][1] = __ldg((const float2*)(base + (size_t)(qr + 8) * (TT * FF) + 2 * qc));
            xr[m][2] = __ldg((const float2*)(base + (size_t)qr * (TT * FF) + 2 * qc + 8));
            xr[m][3] = __ldg((const float2*)(base + (size_t)(qr + 8) * (TT * FF) + 2 * qc + 8));
        }

        float d[2][3][4];   // h-part accumulators (r,z,n)
        float dx[2][4];     // x-part of n-gate
#pragma unroll
        for (int m = 0; m < 2; m++) {
#pragma unroll
            for (int g = 0; g < 3; g++)
#pragma unroll
                for (int j = 0; j < 4; j++) d[m][g][j] = 0.f;
#pragma unroll
            for (int j = 0; j < 4; j++) dx[m][j] = 0.f;
        }

        // ---- h @ Whh^T (bf16 m16n8k16, 3-term split, term-interleaved) ----
        if (t) {
            uint4 blwA, nwA; uint2 blwB, nwB;
            {
                const uint32_t* p = &g_Blo[(((0 * 8 + w8) * 2 + s) * 32 + lane) * 8];
                blwA = *(const uint4*)p; blwB = *(const uint2*)(p + 4);
            }
#pragma unroll 2
            for (int kt = 0; kt < 8; kt++) {
                if (kt < 7) {
                    const uint32_t* p = &g_Blo[((((kt + 1) * 8 + w8) * 2 + s) * 32 + lane) * 8];
                    nwA = *(const uint4*)p; nwB = *(const uint2*)(p + 4);
                }
                uint32_t ah[2][4], al[2][4];
#pragma unroll
                for (int m = 0; m < 2; m++) {
                    int r0 = (m * 16 + qr) * 68 + kt * 8 + qc;
                    ah[m][0] = h_hi_w[r0];
                    ah[m][1] = h_hi_w[r0 + 8 * 68];
                    ah[m][2] = h_hi_w[r0 + 4];
                    ah[m][3] = h_hi_w[r0 + 8 * 68 + 4];
                    al[m][0] = h_lo_w[r0];
                    al[m][1] = h_lo_w[r0 + 8 * 68];
                    al[m][2] = h_lo_w[r0 + 4];
                    al[m][3] = h_lo_w[r0 + 8 * 68 + 4];
                }
                uint32_t lw[6] = {blwA.x, blwA.y, blwA.z, blwA.w, blwB.x, blwB.y};
                uint2 bh[3];
#pragma unroll
                for (int g = 0; g < 3; g++)
                    bh[g] = Bhi2[((kt * 8 + w8) * 6 + g * 2 + s) * 32 + lane];
                // term 0: ah x bh   (6 independent accumulators in a row)
#pragma unroll
                for (int g = 0; g < 3; g++)
#pragma unroll
                    for (int m = 0; m < 2; m++)
                        mma_bf16(d[m][g], ah[m], bh[g].x, bh[g].y);
                // term 1: al x bh
#pragma unroll
                for (int g = 0; g < 3; g++)
#pragma unroll
                    for (int m = 0; m < 2; m++)
                        mma_bf16(d[m][g], al[m], bh[g].x, bh[g].y);
                // term 2: ah x bl
#pragma unroll
                for (int g = 0; g < 3; g++)
#pragma unroll
                    for (int m = 0; m < 2; m++)
                        mma_bf16(d[m][g], ah[m], lw[g * 2], lw[g * 2 + 1]);
                blwA = nwA; blwB = nwB;
            }
        }

        // ---- x @ Wih^T fused (k=16, one chunk, term-interleaved) ----
        {
            uint32_t xh[2][4], xl[2][4];
#pragma unroll
            for (int m = 0; m < 2; m++)
#pragma unroll
                for (int j = 0; j < 4; j++) {
                    float v0 = xr[m][j].x, v1 = xr[m][j].y;
                    __nv_bfloat162 hv; hv.x = __float2bfloat16(v0); hv.y = __float2bfloat16(v1);
                    xh[m][j] = *(uint32_t*)&hv;
                    __nv_bfloat162 lv;
                    lv.x = __float2bfloat16(v0 - __bfloat162float(hv.x));
                    lv.y = __float2bfloat16(v1 - __bfloat162float(hv.y));
                    xl[m][j] = *(uint32_t*)&lv;
                }
            const uint32_t* p = &g_WihLo[((w8 * 2 + s) * 32 + lane) * 8];
            uint4 wlA = *(const uint4*)p; uint2 wlB = *(const uint2*)(p + 4);
            uint32_t wlw[6] = {wlA.x, wlA.y, wlA.z, wlA.w, wlB.x, wlB.y};
            uint2 bh[3];
#pragma unroll
            for (int g = 0; g < 3; g++)
                bh[g] = __ldg(&WihHi2[(w8 * 6 + g * 2 + s) * 32 + lane]);
#pragma unroll
            for (int g = 0; g < 3; g++)
#pragma unroll
                for (int m = 0; m < 2; m++) {
                    float* D = (g == 2) ? dx[m] : d[m][g];
                    mma_bf16(D, xh[m], bh[g].x, bh[g].y);
                }
#pragma unroll
            for (int g = 0; g < 3; g++)
#pragma unroll
                for (int m = 0; m < 2; m++) {
                    float* D = (g == 2) ? dx[m] : d[m][g];
                    mma_bf16(D, xl[m], bh[g].x, bh[g].y);
                }
#pragma unroll
            for (int g = 0; g < 3; g++)
#pragma unroll
                for (int m = 0; m < 2; m++) {
                    float* D = (g == 2) ? dx[m] : d[m][g];
                    mma_bf16(D, xh[m], wlw[g * 2], wlw[g * 2 + 1]);
                }
        }

        // ---- gate math ----
        float hn[2][2][2];
#pragma unroll
        for (int m = 0; m < 2; m++)
#pragma unroll
            for (int rg = 0; rg < 2; rg++) {
                int row = m * 16 + qr + rg * 8;
                int wi = row * 68 + w * 4 + qc;
                float2 hhf = __bfloat1622float2(*(__nv_bfloat162*)&h_hi_w[wi]);
                float2 hlf = __bfloat1622float2(*(__nv_bfloat162*)&h_lo_w[wi]);
#pragma unroll
                for (int jj = 0; jj < 2; jj++) {
                    float hold = jj ? (hhf.y + hlf.y) : (hhf.x + hlf.x);
                    int di = rg * 2 + jj;
                    float rr = sigmoid_fast(d[m][0][di] + bRr[jj]);
                    float zz = sigmoid_fast(d[m][1][di] + bRz[jj]);
                    float nv = tanh_fast(dx[m][di] + biN[jj] +
                                         rr * (d[m][2][di] + bhN[jj]));
                    hn[m][rg][jj] = (1.f - zz) * nv + zz * hold;
                }
            }
        __syncthreads();
#pragma unroll
        for (int m = 0; m < 2; m++)
#pragma unroll
            for (int rg = 0; rg < 2; rg++) {
                int row = m * 16 + qr + rg * 8;
                int wi = row * 68 + w * 4 + qc;
                float h0 = hn[m][rg][0], h1 = hn[m][rg][1];
                __nv_bfloat162 hv; hv.x = __float2bfloat16(h0); hv.y = __float2bfloat16(h1);
                __nv_bfloat162 lv;
                lv.x = __float2bfloat16(h0 - __bfloat162float(hv.x));
                lv.y = __float2bfloat16(h1 - __bfloat162float(hv.y));
                h_hi_w[wi] = *(uint32_t*)&hv;
                h_lo_w[wi] = *(uint32_t*)&lv;
            }
        __syncthreads();
    }

    const __nv_bfloat16* h_hi = (const __nv_bfloat16*)h_hi_w;
    const __nv_bfloat16* h_lo = (const __nv_bfloat16*)h_lo_w;
    for (int i = tid; i < 32 * HH; i += 512) {
        int row = i >> 7, col = i & 127;
        g_support[(size_t)(node0 + row) * HH + col] =
            __bfloat162float(h_hi[row * 136 + col]) +
            __bfloat162float(h_lo[row * 136 + col]);
    }
}

// ---------------- kernel 3: tensor-core GEMM C[4096,128] = A @ B (+b1+b2) ---
struct GemmJob { const float* A; const float* B; const float* b1; const float* b2; float* C; };
struct GemmJobs { GemmJob j[5]; };

#define GEMM_SMEM 204800

__global__ void __launch_bounds__(256) k_gemm(GemmJobs jobs) {
    GemmJob job = jobs.j[blockIdx.y];
    extern __shared__ char smc[];
    float* As_hi = (float*)smc;                               // [128][132]
    float* Bs_hi = As_hi + 128 * 132;                         // [128][132]
    uint16_t* As_lo = (uint16_t*)(Bs_hi + 128 * 132);         // [128][136]
    uint16_t* Bs_lo = As_lo + 128 * 136;                      // [128][136]
    int tid = threadIdx.x;
    int node0 = blockIdx.x * 128;

    for (int idx = tid; idx < 128 * 128; idx += 256) {
        int r = idx >> 7, c = idx & 127;
        float a = job.A[(size_t)(node0 + r) * HH + c];
        uint32_t ha = f2tf32(a);
        As_hi[r * 132 + c] = __uint_as_float(ha);
        As_lo[r * 136 + c] =
            __bfloat16_as_ushort(__float2bfloat16(a - __uint_as_float(ha)));
        float b = job.B[idx];
        uint32_t hb = f2tf32(b);
        Bs_hi[r * 132 + c] = __uint_as_float(hb);
        Bs_lo[r * 136 + c] =
            __bfloat16_as_ushort(__float2bfloat16(b - __uint_as_float(hb)));
    }
    __syncthreads();

    int w = tid >> 5, lane = tid & 31;
    int qr = lane >> 2, qc = lane & 3;
    int r0 = w * 16;
    float acc[16][4];
#pragma unroll
    for (int ct = 0; ct < 16; ct++)
#pragma unroll
        for (int j = 0; j < 4; j++) acc[ct][j] = 0.f;

#pragma unroll 1
    for (int kt = 0; kt < 16; kt++) {
        int kc = kt * 8 + qc;
        uint32_t ah[4], al[4];
        ah[0] = __float_as_uint(As_hi[(r0 + qr) * 132 + kc]);
        ah[1] = __float_as_uint(As_hi[(r0 + qr + 8) * 132 + kc]);
        ah[2] = __float_as_uint(As_hi[(r0 + qr) * 132 + kc + 4]);
        ah[3] = __float_as_uint(As_hi[(r0 + qr + 8) * 132 + kc + 4]);
        al[0] = (uint32_t)As_lo[(r0 + qr) * 136 + kc] << 16;
        al[1] = (uint32_t)As_lo[(r0 + qr + 8) * 136 + kc] << 16;
        al[2] = (uint32_t)As_lo[(r0 + qr) * 136 + kc + 4] << 16;
        al[3] = (uint32_t)As_lo[(r0 + qr + 8) * 136 + kc + 4] << 16;
#pragma unroll
        for (int cg = 0; cg < 4; cg++) {
            uint32_t bh0[4], bh1[4], bl0[4], bl1[4];
#pragma unroll
            for (int j = 0; j < 4; j++) {
                int n0 = (cg * 4 + j) * 8;
                bh0[j] = __float_as_uint(Bs_hi[kc * 132 + n0 + qr]);
                bh1[j] = __float_as_uint(Bs_hi[(kc + 4) * 132 + n0 + qr]);
                bl0[j] = (uint32_t)Bs_lo[kc * 136 + n0 + qr] << 16;
                bl1[j] = (uint32_t)Bs_lo[(kc + 4) * 136 + n0 + qr] << 16;
            }
#pragma unroll
            for (int j = 0; j < 4; j++)
                mma_tf32(acc[cg * 4 + j], ah, bh0[j], bh1[j]);
#pragma unroll
            for (int j = 0; j < 4; j++)
                mma_tf32(acc[cg * 4 + j], al, bh0[j], bh1[j]);
#pragma unroll
            for (int j = 0; j < 4; j++)
                mma_tf32(acc[cg * 4 + j], ah, bl0[j], bl1[j]);
        }
    }

#pragma unroll
    for (int ct = 0; ct < 16; ct++) {
        int c0 = ct * 8 + 2 * qc;
        float b0 = 0.f, b1v = 0.f;
        if (job.b1) { b0 += __ldg(&job.b1[c0]); b1v += __ldg(&job.b1[c0 + 1]); }
        if (job.b2) { b0 += __ldg(&job.b2[c0]); b1v += __ldg(&job.b2[c0 + 1]); }
        int r = node0 + r0 + qr;
        *(float2*)&job.C[(size_t)r * HH + c0] =
            make_float2(acc[ct][0] + b0, acc[ct][1] + b1v);
        *(float2*)&job.C[(size_t)(r + 8) * HH + c0] =
            make_float2(acc[ct][2] + b0, acc[ct][3] + b1v);
    }
}

// ---------------- kernel 4: f1/f2 per head -----------------------------------
__global__ void k_f1f2(const float* __restrict__ uP, const float* __restrict__ vP,
                       const float* __restrict__ uN, const float* __restrict__ vN) {
    const float* sup; const float* u; const float* v; float* f1; float* f2;
    if (blockIdx.y == 0) { sup = g_supP; u = uP; v = vP; f1 = g_f1P; f2 = g_f2P; }
    else                 { sup = g_supN; u = uN; v = vN; f1 = g_f1N; f2 = g_f2N; }
    int n = blockIdx.x * 8 + (threadIdx.x >> 5);
    int lane = threadIdx.x & 31;
#pragma unroll
    for (int h = 0; h < NHD; h++) {
        float s = sup[(size_t)n * HH + h * DOD + lane];
        float a = s * u[h * DOD + lane];
        float b = s * v[h * DOD + lane];
        a = warpsum(a); b = warpsum(b);
        if (lane == 0) { f1[h * NN + n] = a; f2[h * NN + n] = b; }
    }
}

// ---------------- kernel 5: GAT masked-attention aggregation -----------------
__global__ void __launch_bounds__(128) k_gat(const float* __restrict__ adjP,
                                             const float* __restrict__ adjN) {
    __shared__ int s_cnt;
    __shared__ int s_list[512];
    __shared__ float s_a[512];
    const float* adj; const float* sup; const float* f1; const float* f2;
    const float* resid; float* outp;
    if (blockIdx.y == 0) { adj = adjP; sup = g_supP; f1 = g_f1P; f2 = g_f2P; resid = g_residP; outp = g_gatP; }
    else                 { adj = adjN; sup = g_supN; f1 = g_f1N; f2 = g_f2N; resid = g_residN; outp = g_gatN; }
    int i = blockIdx.x, tid = threadIdx.x;
    int h = tid >> 5;
    float f2i = f2[h * NN + i];
    float num = 0.f, den = 0.f;

    for (int c0 = 0; c0 < NN; c0 += 16384) {
        if (tid == 0) s_cnt = 0;
        __syncthreads();
        int cend = c0 + 16384; if (cend > NN) cend = NN;
        for (int j = c0 + tid; j < cend; j += 128) {
            float a = adj[(size_t)i * NN + j];
            if (a != 0.f) {
                int p = atomicAdd(&s_cnt, 1);
                s_list[p] = j;
                s_a[p] = a;
            }
        }
        __syncthreads();
        int cnt = s_cnt;
        for (int t = 0; t < cnt; t++) {
            int j = s_list[t];
            float w = f1[h * NN + j] + f2i;
            w = (w > 0.f) ? w : 0.2f * w;
            w *= s_a[t];
            den += w;
            num += w * sup[(size_t)j * HH + tid];
        }
        __syncthreads();
    }
    float d = (den == 0.f) ? 1.f : den;
    outp[(size_t)i * HH + tid] = num / d + resid[(size_t)i * HH + tid];
}

// ---------------- kernel 6: zero colsum --------------------------------------
__global__ void k_zero() { if (threadIdx.x < HH) g_colsum[threadIdx.x] = 0.f; }

// ---------------- kernel 7: semantic attention, warp-per-node ----------------
__global__ void __launch_bounds__(256) k_sem(const float* __restrict__ W1,
                                             const float* __restrict__ b1,
                                             const float* __restrict__ W2) {
    __shared__ float W1s[128 * 65];
    __shared__ float W2s[SEMD], b1s[SEMD];
    __shared__ float semb[8][3][128];
    int tid = threadIdx.x;
    for (int i = tid; i < 128 * 64; i += 256) {
        int k = i >> 6, s = i & 63;
        W1s[k * 65 + s] = W1[i];
    }
    if (tid < SEMD) { W2s[tid] = W2[tid]; b1s[tid] = b1[tid]; }
    __syncthreads();

    int w = tid >> 5, lane = tid & 31;
    float csum[4] = {0.f, 0.f, 0.f, 0.f};
    int nbase = (blockIdx.x * 8 + w) * 8;

    for (int i = 0; i < 8; i++) {
        int n = nbase + i;
        float4 ev[3];
        ev[0] = *(const float4*)&g_selfE[(size_t)n * HH + lane * 4];
        ev[1] = *(const float4*)&g_posE[(size_t)n * HH + lane * 4];
        ev[2] = *(const float4*)&g_negE[(size_t)n * HH + lane * 4];
        __syncwarp();
        *(float4*)&semb[w][0][lane * 4] = ev[0];
        *(float4*)&semb[w][1][lane * 4] = ev[1];
        *(float4*)&semb[w][2][lane * 4] = ev[2];
        __syncwarp();

        float acc[3][2];
#pragma unroll
        for (int e = 0; e < 3; e++) { acc[e][0] = b1s[lane]; acc[e][1] = b1s[lane + 32]; }
#pragma unroll 4
        for (int k = 0; k < HH; k++) {
            float w1a = W1s[k * 65 + lane];
            float w1b = W1s[k * 65 + lane + 32];
            float x0 = semb[w][0][k], x1 = semb[w][1][k], x2 = semb[w][2][k];
            acc[0][0] += x0 * w1a; acc[0][1] += x0 * w1b;
            acc[1][0] += x1 * w1a; acc[1][1] += x1 * w1b;
            acc[2][0] += x2 * w1a; acc[2][1] += x2 * w1b;
        }
        float wv[3];
#pragma unroll
        for (int e = 0; e < 3; e++) {
            float tsum = tanh_fast(acc[e][0]) * W2s[lane] +
                         tanh_fast(acc[e][1]) * W2s[lane + 32];
            wv[e] = warpsum_bfly(tsum);
        }
        float m = fmaxf(wv[0], fmaxf(wv[1], wv[2]));
        float e0 = __expf(wv[0] - m), e1 = __expf(wv[1] - m), e2 = __expf(wv[2] - m);
        float inv = __fdividef(1.f, e0 + e1 + e2);
        float be0 = e0 * inv, be1 = e1 * inv, be2 = e2 * inv;
        float4 f;
        f.x = be0 * ev[0].x + be1 * ev[1].x + be2 * ev[2].x;
        f.y = be0 * ev[0].y + be1 * ev[1].y + be2 * ev[2].y;
        f.z = be0 * ev[0].z + be1 * ev[1].z + be2 * ev[2].z;
        f.w = be0 * ev[0].w + be1 * ev[1].w + be2 * ev[2].w;
        *(float4*)&g_fused[(size_t)n * HH + lane * 4] = f;
        csum[0] += f.x; csum[1] += f.y; csum[2] += f.z; csum[3] += f.w;
    }
    atomicAdd(&g_colsum[lane * 4 + 0], csum[0]);
    atomicAdd(&g_colsum[lane * 4 + 1], csum[1]);
    atomicAdd(&g_colsum[lane * 4 + 2], csum[2]);
    atomicAdd(&g_colsum[lane * 4 + 3], csum[3]);
}

// ---------------- kernel 8: pairnorm + predictor -----------------------------
__global__ void __launch_bounds__(256) k_pred(const float* __restrict__ W1,
                                              const float* __restrict__ b1,
                                              const float* __restrict__ W2,
                                              const float* __restrict__ b2,
                                              float* __restrict__ out) {
    __shared__ float W1s[HH * PHD];
    __shared__ float xns[8][HH];
    int tid = threadIdx.x;
    for (int i = tid; i < HH * PHD; i += 256) W1s[i] = W1[i];
    int w = tid >> 5, lane = tid & 31;
    int n = blockIdx.x * 8 + w;
    float xv[4]; float ss = 0.f;
    const float invN = 1.f / (float)NN;
#pragma unroll
    for (int j = 0; j < 4; j++) {
        int d = lane + j * 32;
        float x = g_fused[(size_t)n * HH + d] - g_colsum[d] * invN;
        xv[j] = x; ss += x * x;
    }
    ss = warpsum(ss);
    ss = __shfl_sync(0xffffffffu, ss, 0);
    float rinv = rsqrtf(1e-6f + ss);
#pragma unroll
    for (int j = 0; j < 4; j++) xns[w][lane + j * 32] = xv[j] * rinv;
    __syncthreads();

    float acc = b1[lane];
#pragma unroll 4
    for (int k = 0; k < HH; k++) acc += xns[w][k] * W1s[k * PHD + lane];
    float hgt = acc > 0.f ? acc : 0.f;
    float o = warpsum(hgt * W2[lane]);
    if (lane == 0) out[n] = sigmoid_fast(o + b2[0]);
}

// ---------------- launch -----------------------------------------------------
extern "C" void kernel_launch(void* const* d_in, const int* in_sizes, int n_in,
                              void* d_out, int out_size) {
    const float* features = (const float*)d_in[0];
    const float* pos_adj  = (const float*)d_in[1];
    const float* neg_adj  = (const float*)d_in[2];
    const float* gru_Wih  = (const float*)d_in[3];
    const float* gru_Whh  = (const float*)d_in[4];
    const float* gru_bih  = (const float*)d_in[5];
    const float* gru_bhh  = (const float*)d_in[6];
    const float* pos_W    = (const float*)d_in[7];
    const float* pos_u    = (const float*)d_in[8];
    const float* pos_v    = (const float*)d_in[9];
    const float* pos_b    = (const float*)d_in[10];
    const float* pos_pW   = (const float*)d_in[11];
    const float* pos_pb   = (const float*)d_in[12];
    const float* neg_W    = (const float*)d_in[13];
    const float* neg_u    = (const float*)d_in[14];
    const float* neg_v    = (const float*)d_in[15];
    const float* neg_b    = (const float*)d_in[16];
    const float* neg_pW   = (const float*)d_in[17];
    const float* neg_pb   = (const float*)d_in[18];
    const float* self_W   = (const float*)d_in[19];
    const float* self_b   = (const float*)d_in[20];
    const float* mpos_W   = (const float*)d_in[21];
    const float* mpos_b   = (const float*)d_in[22];
    const float* mneg_W   = (const float*)d_in[23];
    const float* mneg_b   = (const float*)d_in[24];
    const float* sem_W1   = (const float*)d_in[25];
    const float* sem_b1   = (const float*)d_in[26];
    const float* sem_W2   = (const float*)d_in[27];
    const float* pred_W1  = (const float*)d_in[28];
    const float* pred_b1  = (const float*)d_in[29];
    const float* pred_W2  = (const float*)d_in[30];
    const float* pred_b2  = (const float*)d_in[31];
    float* out = (float*)d_out;

    static bool attr_done = false;
    if (!attr_done) {
        cudaFuncSetAttribute(k_gru, cudaFuncAttributeMaxDynamicSharedMemorySize, GRU_SMEM);
        cudaFuncSetAttribute(k_gemm, cudaFuncAttributeMaxDynamicSharedMemorySize, GEMM_SMEM);
        attr_done = true;
    }

    float *p_support, *p_gatP, *p_gatN, *p_supP, *p_supN;
    float *p_residP, *p_residN, *p_selfE, *p_posE, *p_negE;
    cudaGetSymbolAddress((void**)&p_support, g_support);
    cudaGetSymbolAddress((void**)&p_supP, g_supP);
    cudaGetSymbolAddress((void**)&p_supN, g_supN);
    cudaGetSymbolAddress((void**)&p_residP, g_residP);
    cudaGetSymbolAddress((void**)&p_residN, g_residN);
    cudaGetSymbolAddress((void**)&p_selfE, g_selfE);
    cudaGetSymbolAddress((void**)&p_gatP, g_gatP);
    cudaGetSymbolAddress((void**)&p_gatN, g_gatN);
    cudaGetSymbolAddress((void**)&p_posE, g_posE);
    cudaGetSymbolAddress((void**)&p_negE, g_negE);

    k_prep<<<48, 256>>>(gru_Whh);                                   // 1
    k_prep_wih<<<6, 256>>>(gru_Wih);                                // 2
    k_zero<<<1, 128>>>();                                           // 3
    k_gru<<<NN / 32, 512, GRU_SMEM>>>(features, gru_bih, gru_bhh);  // 4
    {
        GemmJobs jb;
        jb.j[0] = { p_support, pos_W,  nullptr, nullptr, p_supP };
        jb.j[1] = { p_support, neg_W,  nullptr, nullptr, p_supN };
        jb.j[2] = { p_support, pos_pW, pos_b,   pos_pb,  p_residP };
        jb.j[3] = { p_support, neg_pW, neg_b,   neg_pb,  p_residN };
        jb.j[4] = { p_support, self_W, self_b,  nullptr, p_selfE };
        dim3 grid(NN / 128, 5);
        k_gemm<<<grid, 256, GEMM_SMEM>>>(jb);                       // 5
    }
    {
        dim3 grid(NN / 8, 2);
        k_f1f2<<<grid, 256>>>(pos_u, pos_v, neg_u, neg_v);          // 6
    }
    {
        dim3 grid(NN, 2);
        k_gat<<<grid, 128>>>(pos_adj, neg_adj);                     // 7
    }
    {
        GemmJobs jb;
        jb.j[0] = { p_gatP, mpos_W, mpos_b, nullptr, p_posE };
        jb.j[1] = { p_gatN, mneg_W, mneg_b, nullptr, p_negE };
        jb.j[2] = jb.j[0]; jb.j[3] = jb.j[0]; jb.j[4] = jb.j[0];
        dim3 grid(NN / 128, 2);
        k_gemm<<<grid, 256, GEMM_SMEM>>>(jb);                       // 8
    }
    k_sem<<<NN / 64, 256>>>(sem_W1, sem_b1, sem_W2);                // 9
    k_pred<<<NN / 8, 256>>>(pred_W1, pred_b1, pred_W2, pred_b2, out); // 10
}

// round 11
// speedup vs baseline: 8.9695x; 1.0734x over previous
#include <cuda_runtime.h>
#include <cuda_bf16.h>
#include <cstdint>
#include <cstddef>

#define NN 4096
#define TT 24
#define FF 16
#define HH 128
#define GG 384
#define NHD 4
#define DOD 32
#define SEMD 64
#define PHD 32

// ---------------- scratch (static device globals; no runtime allocation) ----
__device__ float g_support[NN * HH];
__device__ float g_supP[NN * HH];
__device__ float g_supN[NN * HH];
__device__ float g_residP[NN * HH];
__device__ float g_residN[NN * HH];
__device__ float g_selfE[NN * HH];
__device__ float g_f1P[NHD * NN];
__device__ float g_f2P[NHD * NN];
__device__ float g_f1N[NHD * NN];
__device__ float g_f2N[NHD * NN];
__device__ float g_gatP[NN * HH];
__device__ float g_gatN[NN * HH];
__device__ float g_posE[NN * HH];
__device__ float g_negE[NN * HH];
__device__ float g_fused[NN * HH];
__device__ float g_colsum[HH];
// bf16 fragment-ordered Whh: hi (smem-staged), lo (streamed, uint4+uint2/warp)
__device__ __align__(16) uint32_t g_Bhi[8 * 8 * 6 * 32 * 2];   // 24576 words (96 KB)
__device__ __align__(16) uint32_t g_Blo[8 * 8 * 2 * 32 * 8];   // 32768 words
// bf16 fragment-ordered Wih (k=16 -> one k-chunk)
__device__ __align__(16) uint32_t g_WihHi[8 * 6 * 32 * 2];
__device__ __align__(16) uint32_t g_WihLo[8 * 2 * 32 * 8];

__device__ __forceinline__ float warpsum(float v) {
#pragma unroll
    for (int o = 16; o >= 1; o >>= 1) v += __shfl_down_sync(0xffffffffu, v, o);
    return v;
}
__device__ __forceinline__ float warpsum_bfly(float v) {
#pragma unroll
    for (int o = 16; o >= 1; o >>= 1) v += __shfl_xor_sync(0xffffffffu, v, o);
    return v;
}
__device__ __forceinline__ float sigmoid_fast(float x) {
    return __fdividef(1.f, 1.f + __expf(-x));
}
__device__ __forceinline__ float tanh_fast(float x) {
    float e = __expf(-2.f * x);
    return __fdividef(2.f, 1.f + e) - 1.f;
}
__device__ __forceinline__ void mma_bf16(float d[4], const uint32_t a[4],
                                         uint32_t b0, uint32_t b1) {
    asm volatile("mma.sync.aligned.m16n8k16.row.col.f32.bf16.bf16.f32 "
                 "{%0,%1,%2,%3}, {%4,%5,%6,%7}, {%8,%9}, {%0,%1,%2,%3};"
                 : "+f"(d[0]), "+f"(d[1]), "+f"(d[2]), "+f"(d[3])
                 : "r"(a[0]), "r"(a[1]), "r"(a[2]), "r"(a[3]), "r"(b0), "r"(b1));
}

// ---------------- kernel 0a: bf16 fragment-ordered Whh -----------------------
__global__ void k_prep(const float* __restrict__ Whh) {
    int idx = blockIdx.x * 256 + threadIdx.x;       // 12288 = 8*8*6*32
    if (idx >= 8 * 8 * 6 * 32) return;
    int lane = idx & 31; int r = idx >> 5;
    int nt = r % 6; r /= 6;
    int w8 = r & 7; int kt = r >> 3;                 // kt in [0,8)
    int g = nt >> 1, s = nt & 1;
    int n = g * 128 + w8 * 16 + s * 8 + (lane >> 2);
    int kb = kt * 16 + (lane & 3) * 2;
    float w0 = Whh[n * 128 + kb],     w1 = Whh[n * 128 + kb + 1];
    float w2 = Whh[n * 128 + kb + 8], w3 = Whh[n * 128 + kb + 9];
    __nv_bfloat16 h0 = __float2bfloat16(w0), h1 = __float2bfloat16(w1);
    __nv_bfloat16 h2 = __float2bfloat16(w2), h3 = __float2bfloat16(w3);
    {
        __nv_bfloat162 v; v.x = h0; v.y = h1;
        g_Bhi[idx * 2 + 0] = *(uint32_t*)&v;
        v.x = h2; v.y = h3;
        g_Bhi[idx * 2 + 1] = *(uint32_t*)&v;
    }
    __nv_bfloat162 l01, l23;
    l01.x = __float2bfloat16(w0 - __bfloat162float(h0));
    l01.y = __float2bfloat16(w1 - __bfloat162float(h1));
    l23.x = __float2bfloat16(w2 - __bfloat162float(h2));
    l23.y = __float2bfloat16(w3 - __bfloat162float(h3));
    uint32_t* lo = &g_Blo[(((kt * 8 + w8) * 2 + s) * 32 + lane) * 8 + g * 2];
    lo[0] = *(uint32_t*)&l01;
    lo[1] = *(uint32_t*)&l23;
}

// ---------------- kernel 0b: bf16 fragment-ordered Wih (k=16) ---------------
__global__ void k_prep_wih(const float* __restrict__ Wih) {
    int idx = blockIdx.x * 256 + threadIdx.x;       // 1536 = 8*6*32
    if (idx >= 8 * 6 * 32) return;
    int lane = idx & 31; int r = idx >> 5;
    int nt = r % 6; int w8 = r / 6;
    int g = nt >> 1, s = nt & 1;
    int n = g * 128 + w8 * 16 + s * 8 + (lane >> 2);
    int kb = (lane & 3) * 2;
    float w0 = Wih[n * FF + kb],     w1 = Wih[n * FF + kb + 1];
    float w2 = Wih[n * FF + kb + 8], w3 = Wih[n * FF + kb + 9];
    __nv_bfloat16 h0 = __float2bfloat16(w0), h1 = __float2bfloat16(w1);
    __nv_bfloat16 h2 = __float2bfloat16(w2), h3 = __float2bfloat16(w3);
    {
        __nv_bfloat162 v; v.x = h0; v.y = h1;
        g_WihHi[idx * 2 + 0] = *(uint32_t*)&v;
        v.x = h2; v.y = h3;
        g_WihHi[idx * 2 + 1] = *(uint32_t*)&v;
    }
    __nv_bfloat162 l01, l23;
    l01.x = __float2bfloat16(w0 - __bfloat162float(h0));
    l01.y = __float2bfloat16(w1 - __bfloat162float(h1));
    l23.x = __float2bfloat16(w2 - __bfloat162float(h2));
    l23.y = __float2bfloat16(w3 - __bfloat162float(h3));
    uint32_t* lo = &g_WihLo[((w8 * 2 + s) * 32 + lane) * 8 + g * 2];
    lo[0] = *(uint32_t*)&l01;
    lo[1] = *(uint32_t*)&l23;
}

// ---------------- kernel 2: fused GRU scan, bf16x3, ping-pong h -------------
// smem: Bhi 24576 words + 2x (h_hi + h_lo) buffers, each 32*68 words
#define HBUF 2176
#define GRU_SMEM ((24576 + 4 * HBUF) * 4)

__global__ void __launch_bounds__(512, 1) k_gru(const float* __restrict__ feat,
                                                const float* __restrict__ bih,
                                                const float* __restrict__ bhh) {
    extern __shared__ float sm[];
    uint32_t* Bhi_s = (uint32_t*)sm;                 // 24576 words
    uint32_t* hbase = Bhi_s + 24576;                 // 4 buffers of 2176
    int tid = threadIdx.x;
    int w = tid >> 5, lane = tid & 31;
    int w8 = w >> 1, s = w & 1;
    int qr = lane >> 2, qc = lane & 3;
    int hc = w * 8;                                  // 8 output cols per warp
    int node0 = blockIdx.x * 32;

    {
        const uint4* src = (const uint4*)g_Bhi;
        uint4* dst = (uint4*)Bhi_s;
        for (int i = tid; i < 24576 / 4; i += 512) dst[i] = src[i];
        for (int i = tid; i < 4 * HBUF; i += 512) hbase[i] = 0u;
    }
    float bRr[2], bRz[2], biN[2], bhN[2];
#pragma unroll
    for (int jj = 0; jj < 2; jj++) {
        int c = hc + 2 * qc + jj;
        bRr[jj] = __ldg(&bih[c]) + __ldg(&bhh[c]);
        bRz[jj] = __ldg(&bih[128 + c]) + __ldg(&bhh[128 + c]);
        biN[jj] = __ldg(&bih[256 + c]);
        bhN[jj] = __ldg(&bhh[256 + c]);
    }
    __syncthreads();

    const uint2* Bhi2 = (const uint2*)Bhi_s;
    const uint2* WihHi2 = (const uint2*)g_WihHi;
    int cur = 0;

    for (int t = 0; t < TT; t++) {
        uint32_t* h_hi_w = hbase + cur * (2 * HBUF);
        uint32_t* h_lo_w = h_hi_w + HBUF;
        uint32_t* n_hi_w = hbase + (cur ^ 1) * (2 * HBUF);
        uint32_t* n_lo_w = n_hi_w + HBUF;

        // ---- x loads (fp32 pairs) issued early ----
        float2 xr[2][4];
#pragma unroll
        for (int m = 0; m < 2; m++) {
            const float* base = feat + (size_t)(node0 + m * 16) * (TT * FF) + t * FF;
            xr[m][0] = __ldg((const float2*)(base + (size_t)qr * (TT * FF) + 2 * qc));
            xr[m][1] = __ldg((const float2*)(base + (size_t)(qr + 8) * (TT * FF) + 2 * qc));
            xr[m][2] = __ldg((const float2*)(base + (size_t)qr * (TT * FF) + 2 * qc + 8));
            xr[m][3] = __ldg((const float2*)(base + (size_t)(qr + 8) * (TT * FF) + 2 * qc + 8));
        }

        float d[2][3][4];
        float dx[2][4];
#pragma unroll
        for (int m = 0; m < 2; m++) {
#pragma unroll
            for (int g = 0; g < 3; g++)
#pragma unroll
                for (int j = 0; j < 4; j++) d[m][g][j] = 0.f;
#pragma unroll
            for (int j = 0; j < 4; j++) dx[m][j] = 0.f;
        }

        // ---- x @ Wih^T (k=16, independent of h — issue first) ----
        {
            uint32_t xh[2][4], xl[2][4];
#pragma unroll
            for (int m = 0; m < 2; m++)
#pragma unroll
                for (int j = 0; j < 4; j++) {
                    float v0 = xr[m][j].x, v1 = xr[m][j].y;
                    __nv_bfloat162 hv; hv.x = __float2bfloat16(v0); hv.y = __float2bfloat16(v1);
                    xh[m][j] = *(uint32_t*)&hv;
                    __nv_bfloat162 lv;
                    lv.x = __float2bfloat16(v0 - __bfloat162float(hv.x));
                    lv.y = __float2bfloat16(v1 - __bfloat162float(hv.y));
                    xl[m][j] = *(uint32_t*)&lv;
                }
            const uint32_t* p = &g_WihLo[((w8 * 2 + s) * 32 + lane) * 8];
            uint4 wlA = *(const uint4*)p; uint2 wlB = *(const uint2*)(p + 4);
            uint32_t wlw[6] = {wlA.x, wlA.y, wlA.z, wlA.w, wlB.x, wlB.y};
            uint2 bh[3];
#pragma unroll
            for (int g = 0; g < 3; g++)
                bh[g] = __ldg(&WihHi2[(w8 * 6 + g * 2 + s) * 32 + lane]);
#pragma unroll
            for (int g = 0; g < 3; g++)
#pragma unroll
                for (int m = 0; m < 2; m++) {
                    float* D = (g == 2) ? dx[m] : d[m][g];
                    mma_bf16(D, xh[m], bh[g].x, bh[g].y);
                    mma_bf16(D, xl[m], bh[g].x, bh[g].y);
                    mma_bf16(D, xh[m], wlw[g * 2], wlw[g * 2 + 1]);
                }
        }

        // ---- h @ Whh^T (bf16 m16n8k16, 3-term split) ----
        if (t) {
            uint4 blwA, nwA; uint2 blwB, nwB;
            {
                const uint32_t* p = &g_Blo[(((0 * 8 + w8) * 2 + s) * 32 + lane) * 8];
                blwA = *(const uint4*)p; blwB = *(const uint2*)(p + 4);
            }
#pragma unroll 2
            for (int kt = 0; kt < 8; kt++) {
                if (kt < 7) {
                    const uint32_t* p = &g_Blo[((((kt + 1) * 8 + w8) * 2 + s) * 32 + lane) * 8];
                    nwA = *(const uint4*)p; nwB = *(const uint2*)(p + 4);
                }
                uint32_t ah[2][4], al[2][4];
#pragma unroll
                for (int m = 0; m < 2; m++) {
                    int r0 = (m * 16 + qr) * 68 + kt * 8 + qc;
                    ah[m][0] = h_hi_w[r0];
                    ah[m][1] = h_hi_w[r0 + 8 * 68];
                    ah[m][2] = h_hi_w[r0 + 4];
                    ah[m][3] = h_hi_w[r0 + 8 * 68 + 4];
                    al[m][0] = h_lo_w[r0];
                    al[m][1] = h_lo_w[r0 + 8 * 68];
                    al[m][2] = h_lo_w[r0 + 4];
                    al[m][3] = h_lo_w[r0 + 8 * 68 + 4];
                }
                uint32_t lw[6] = {blwA.x, blwA.y, blwA.z, blwA.w, blwB.x, blwB.y};
                uint2 bh[3];
#pragma unroll
                for (int g = 0; g < 3; g++)
                    bh[g] = Bhi2[((kt * 8 + w8) * 6 + g * 2 + s) * 32 + lane];
#pragma unroll
                for (int g = 0; g < 3; g++)
#pragma unroll
                    for (int m = 0; m < 2; m++) {
                        mma_bf16(d[m][g], ah[m], bh[g].x, bh[g].y);
                        mma_bf16(d[m][g], al[m], bh[g].x, bh[g].y);
                        mma_bf16(d[m][g], ah[m], lw[g * 2], lw[g * 2 + 1]);
                    }
                blwA = nwA; blwB = nwB;
            }
        }

        // ---- gate math: read h[cur], write h[nxt], single barrier ----
#pragma unroll
        for (int m = 0; m < 2; m++)
#pragma unroll
            for (int rg = 0; rg < 2; rg++) {
                int row = m * 16 + qr + rg * 8;
                int wi = row * 68 + w * 4 + qc;
                float2 hhf = __bfloat1622float2(*(__nv_bfloat162*)&h_hi_w[wi]);
                float2 hlf = __bfloat1622float2(*(__nv_bfloat162*)&h_lo_w[wi]);
                float hn[2];
#pragma unroll
                for (int jj = 0; jj < 2; jj++) {
                    float hold = jj ? (hhf.y + hlf.y) : (hhf.x + hlf.x);
                    int di = rg * 2 + jj;
                    float rr = sigmoid_fast(d[m][0][di] + bRr[jj]);
                    float zz = sigmoid_fast(d[m][1][di] + bRz[jj]);
                    float nv = tanh_fast(dx[m][di] + biN[jj] +
                                         rr * (d[m][2][di] + bhN[jj]));
                    hn[jj] = (1.f - zz) * nv + zz * hold;
                }
                __nv_bfloat162 hv; hv.x = __float2bfloat16(hn[0]); hv.y = __float2bfloat16(hn[1]);
                __nv_bfloat162 lv;
                lv.x = __float2bfloat16(hn[0] - __bfloat162float(hv.x));
                lv.y = __float2bfloat16(hn[1] - __bfloat162float(hv.y));
                n_hi_w[wi] = *(uint32_t*)&hv;
                n_lo_w[wi] = *(uint32_t*)&lv;
            }
        __syncthreads();
        cur ^= 1;
    }

    const __nv_bfloat16* h_hi = (const __nv_bfloat16*)(hbase + cur * (2 * HBUF));
    const __nv_bfloat16* h_lo = h_hi + 2 * HBUF;
    for (int i = tid; i < 32 * HH; i += 512) {
        int row = i >> 7, col = i & 127;
        g_support[(size_t)(node0 + row) * HH + col] =
            __bfloat162float(h_hi[row * 136 + col]) +
            __bfloat162float(h_lo[row * 136 + col]);
    }
}

// ---------------- kernel 3: bf16 tensor-core GEMM C = A @ B (+b1+b2) --------
struct GemmJob { const float* A; const float* B; const float* b1; const float* b2; float* C; };
struct GemmJobs { GemmJob j[5]; };

#define GEMM_SMEM (4 * 128 * 136 * 2)   // 139264 B

__global__ void __launch_bounds__(256) k_gemm(GemmJobs jobs) {
    GemmJob job = jobs.j[blockIdx.y];
    extern __shared__ char smc[];
    uint16_t* As_hi = (uint16_t*)smc;                 // [128][136] bf16, A[r][k]
    uint16_t* As_lo = As_hi + 128 * 136;
    uint16_t* Bs_hi = As_lo + 128 * 136;              // [128][136] bf16, B^T[n][k]
    uint16_t* Bs_lo = Bs_hi + 128 * 136;
    int tid = threadIdx.x;
    int node0 = blockIdx.x * 128;

    for (int idx = tid; idx < 128 * 128; idx += 256) {
        int r = idx >> 7, c = idx & 127;
        float a = job.A[(size_t)(node0 + r) * HH + c];
        __nv_bfloat16 ah = __float2bfloat16(a);
        As_hi[r * 136 + c] = __bfloat16_as_ushort(ah);
        As_lo[r * 136 + c] =
            __bfloat16_as_ushort(__float2bfloat16(a - __bfloat162float(ah)));
        float b = job.B[idx];                          // B[k=r][n=c]
        __nv_bfloat16 bh = __float2bfloat16(b);
        Bs_hi[c * 136 + r] = __bfloat16_as_ushort(bh); // transpose -> [n][k]
        Bs_lo[c * 136 + r] =
            __bfloat16_as_ushort(__float2bfloat16(b - __bfloat162float(bh)));
    }
    __syncthreads();

    int w = tid >> 5, lane = tid & 31;
    int qr = lane >> 2, qc = lane & 3;
    int r0 = w * 16;
    const uint32_t* Aw_hi = (const uint32_t*)As_hi;   // [128][68] words
    const uint32_t* Aw_lo = (const uint32_t*)As_lo;
    const uint32_t* Bw_hi = (const uint32_t*)Bs_hi;
    const uint32_t* Bw_lo = (const uint32_t*)Bs_lo;

    float acc[16][4];
#pragma unroll
    for (int ct = 0; ct < 16; ct++)
#pragma unroll
        for (int j = 0; j < 4; j++) acc[ct][j] = 0.f;

#pragma unroll 1
    for (int kt = 0; kt < 8; kt++) {
        int kc = kt * 8 + qc;
        uint32_t ah[4], al[4];
        ah[0] = Aw_hi[(r0 + qr) * 68 + kc];
        ah[1] = Aw_hi[(r0 + qr + 8) * 68 + kc];
        ah[2] = Aw_hi[(r0 + qr) * 68 + kc + 4];
        ah[3] = Aw_hi[(r0 + qr + 8) * 68 + kc + 4];
        al[0] = Aw_lo[(r0 + qr) * 68 + kc];
        al[1] = Aw_lo[(r0 + qr + 8) * 68 + kc];
        al[2] = Aw_lo[(r0 + qr) * 68 + kc + 4];
        al[3] = Aw_lo[(r0 + qr + 8) * 68 + kc + 4];
#pragma unroll
        for (int cg = 0; cg < 4; cg++) {
            uint32_t bh0[4], bh1[4], bl0[4], bl1[4];
#pragma unroll
            for (int j = 0; j < 4; j++) {
                int n0 = (cg * 4 + j) * 8;
                bh0[j] = Bw_hi[(n0 + qr) * 68 + kc];
                bh1[j] = Bw_hi[(n0 + qr) * 68 + kc + 4];
                bl0[j] = Bw_lo[(n0 + qr) * 68 + kc];
                bl1[j] = Bw_lo[(n0 + qr) * 68 + kc + 4];
            }
#pragma unroll
            for (int j = 0; j < 4; j++)
                mma_bf16(acc[cg * 4 + j], ah, bh0[j], bh1[j]);
#pragma unroll
            for (int j = 0; j < 4; j++)
                mma_bf16(acc[cg * 4 + j], al, bh0[j], bh1[j]);
#pragma unroll
            for (int j = 0; j < 4; j++)
                mma_bf16(acc[cg * 4 + j], ah, bl0[j], bl1[j]);
        }
    }

#pragma unroll
    for (int ct = 0; ct < 16; ct++) {
        int c0 = ct * 8 + 2 * qc;
        float b0 = 0.f, b1v = 0.f;
        if (job.b1) { b0 += __ldg(&job.b1[c0]); b1v += __ldg(&job.b1[c0 + 1]); }
        if (job.b2) { b0 += __ldg(&job.b2[c0]); b1v += __ldg(&job.b2[c0 + 1]); }
        int r = node0 + r0 + qr;
        *(float2*)&job.C[(size_t)r * HH + c0] =
            make_float2(acc[ct][0] + b0, acc[ct][1] + b1v);
        *(float2*)&job.C[(size_t)(r + 8) * HH + c0] =
            make_float2(acc[ct][2] + b0, acc[ct][3] + b1v);
    }
}

// ---------------- kernel 4: f1/f2 per head -----------------------------------
__global__ void k_f1f2(const float* __restrict__ uP, const float* __restrict__ vP,
                       const float* __restrict__ uN, const float* __restrict__ vN) {
    const float* sup; const float* u; const float* v; float* f1; float* f2;
    if (blockIdx.y == 0) { sup = g_supP; u = uP; v = vP; f1 = g_f1P; f2 = g_f2P; }
    else                 { sup = g_supN; u = uN; v = vN; f1 = g_f1N; f2 = g_f2N; }
    int n = blockIdx.x * 8 + (threadIdx.x >> 5);
    int lane = threadIdx.x & 31;
#pragma unroll
    for (int h = 0; h < NHD; h++) {
        float s = sup[(size_t)n * HH + h * DOD + lane];
        float a = s * u[h * DOD + lane];
        float b = s * v[h * DOD + lane];
        a = warpsum(a); b = warpsum(b);
        if (lane == 0) { f1[h * NN + n] = a; f2[h * NN + n] = b; }
    }
}

// ---------------- kernel 5: GAT masked-attention aggregation -----------------
__global__ void __launch_bounds__(128) k_gat(const float* __restrict__ adjP,
                                             const float* __restrict__ adjN) {
    __shared__ int s_cnt;
    __shared__ int s_list[640];
    __shared__ float s_a[640];
    const float* adj; const float* sup; const float* f1; const float* f2;
    const float* resid; float* outp;
    if (blockIdx.y == 0) { adj = adjP; sup = g_supP; f1 = g_f1P; f2 = g_f2P; resid = g_residP; outp = g_gatP; }
    else                 { adj = adjN; sup = g_supN; f1 = g_f1N; f2 = g_f2N; resid = g_residN; outp = g_gatN; }
    int i = blockIdx.x, tid = threadIdx.x;
    int h = tid >> 5;
    if (tid == 0) s_cnt = 0;
    __syncthreads();
    // float4 scan of the adjacency row (4096 floats = 1024 float4)
    const float4* row = (const float4*)(adj + (size_t)i * NN);
    for (int j4 = tid; j4 < NN / 4; j4 += 128) {
        float4 a = __ldg(&row[j4]);
        if (a.x != 0.f) { int p = atomicAdd(&s_cnt, 1); s_list[p] = j4 * 4 + 0; s_a[p] = a.x; }
        if (a.y != 0.f) { int p = atomicAdd(&s_cnt, 1); s_list[p] = j4 * 4 + 1; s_a[p] = a.y; }
        if (a.z != 0.f) { int p = atomicAdd(&s_cnt, 1); s_list[p] = j4 * 4 + 2; s_a[p] = a.z; }
        if (a.w != 0.f) { int p = atomicAdd(&s_cnt, 1); s_list[p] = j4 * 4 + 3; s_a[p] = a.w; }
    }
    __syncthreads();
    int cnt = s_cnt;
    float f2i = f2[h * NN + i];
    float num = 0.f, den = 0.f;
    for (int t = 0; t < cnt; t++) {
        int j = s_list[t];
        float w = f1[h * NN + j] + f2i;
        w = (w > 0.f) ? w : 0.2f * w;
        w *= s_a[t];
        den += w;
        num += w * sup[(size_t)j * HH + tid];
    }
    float d = (den == 0.f) ? 1.f : den;
    outp[(size_t)i * HH + tid] = num / d + resid[(size_t)i * HH + tid];
}

// ---------------- kernel 6: zero colsum --------------------------------------
__global__ void k_zero() { if (threadIdx.x < HH) g_colsum[threadIdx.x] = 0.f; }

// ---------------- kernel 7: semantic attention, warp-per-node ----------------
__global__ void __launch_bounds__(256) k_sem(const float* __restrict__ W1,
                                             const float* __restrict__ b1,
                                             const float* __restrict__ W2) {
    __shared__ float W1s[128 * 65];
    __shared__ float W2s[SEMD], b1s[SEMD];
    __shared__ float semb[8][3][128];
    int tid = threadIdx.x;
    for (int i = tid; i < 128 * 64; i += 256) {
        int k = i >> 6, s = i & 63;
        W1s[k * 65 + s] = W1[i];
    }
    if (tid < SEMD) { W2s[tid] = W2[tid]; b1s[tid] = b1[tid]; }
    __syncthreads();

    int w = tid >> 5, lane = tid & 31;
    float csum[4] = {0.f, 0.f, 0.f, 0.f};
    int nbase = (blockIdx.x * 8 + w) * 8;

    for (int i = 0; i < 8; i++) {
        int n = nbase + i;
        float4 ev[3];
        ev[0] = *(const float4*)&g_selfE[(size_t)n * HH + lane * 4];
        ev[1] = *(const float4*)&g_posE[(size_t)n * HH + lane * 4];
        ev[2] = *(const float4*)&g_negE[(size_t)n * HH + lane * 4];
        __syncwarp();
        *(float4*)&semb[w][0][lane * 4] = ev[0];
        *(float4*)&semb[w][1][lane * 4] = ev[1];
        *(float4*)&semb[w][2][lane * 4] = ev[2];
        __syncwarp();

        float acc[3][2];
#pragma unroll
        for (int e = 0; e < 3; e++) { acc[e][0] = b1s[lane]; acc[e][1] = b1s[lane + 32]; }
#pragma unroll 4
        for (int k = 0; k < HH; k++) {
            float w1a = W1s[k * 65 + lane];
            float w1b = W1s[k * 65 + lane + 32];
            float x0 = semb[w][0][k], x1 = semb[w][1][k], x2 = semb[w][2][k];
            acc[0][0] += x0 * w1a; acc[0][1] += x0 * w1b;
            acc[1][0] += x1 * w1a; acc[1][1] += x1 * w1b;
            acc[2][0] += x2 * w1a; acc[2][1] += x2 * w1b;
        }
        float wv[3];
#pragma unroll
        for (int e = 0; e < 3; e++) {
            float tsum = tanh_fast(acc[e][0]) * W2s[lane] +
                         tanh_fast(acc[e][1]) * W2s[lane + 32];
            wv[e] = warpsum_bfly(tsum);
        }
        float m = fmaxf(wv[0], fmaxf(wv[1], wv[2]));
        float e0 = __expf(wv[0] - m), e1 = __expf(wv[1] - m), e2 = __expf(wv[2] - m);
        float inv = __fdividef(1.f, e0 + e1 + e2);
        float be0 = e0 * inv, be1 = e1 * inv, be2 = e2 * inv;
        float4 f;
        f.x = be0 * ev[0].x + be1 * ev[1].x + be2 * ev[2].x;
        f.y = be0 * ev[0].y + be1 * ev[1].y + be2 * ev[2].y;
        f.z = be0 * ev[0].z + be1 * ev[1].z + be2 * ev[2].z;
        f.w = be0 * ev[0].w + be1 * ev[1].w + be2 * ev[2].w;
        *(float4*)&g_fused[(size_t)n * HH + lane * 4] = f;
        csum[0] += f.x; csum[1] += f.y; csum[2] += f.z; csum[3] += f.w;
    }
    atomicAdd(&g_colsum[lane * 4 + 0], csum[0]);
    atomicAdd(&g_colsum[lane * 4 + 1], csum[1]);
    atomicAdd(&g_colsum[lane * 4 + 2], csum[2]);
    atomicAdd(&g_colsum[lane * 4 + 3], csum[3]);
}

// ---------------- kernel 8: pairnorm + predictor -----------------------------
__global__ void __launch_bounds__(256) k_pred(const float* __restrict__ W1,
                                              const float* __restrict__ b1,
                                              const float* __restrict__ W2,
                                              const float* __restrict__ b2,
                                              float* __restrict__ out) {
    __shared__ float W1s[HH * PHD];
    __shared__ float xns[8][HH];
    int tid = threadIdx.x;
    for (int i = tid; i < HH * PHD; i += 256) W1s[i] = W1[i];
    int w = tid >> 5, lane = tid & 31;
    int n = blockIdx.x * 8 + w;
    float xv[4]; float ss = 0.f;
    const float invN = 1.f / (float)NN;
#pragma unroll
    for (int j = 0; j < 4; j++) {
        int d = lane + j * 32;
        float x = g_fused[(size_t)n * HH + d] - g_colsum[d] * invN;
        xv[j] = x; ss += x * x;
    }
    ss = warpsum(ss);
    ss = __shfl_sync(0xffffffffu, ss, 0);
    float rinv = rsqrtf(1e-6f + ss);
#pragma unroll
    for (int j = 0; j < 4; j++) xns[w][lane + j * 32] = xv[j] * rinv;
    __syncthreads();

    float acc = b1[lane];
#pragma unroll 4
    for (int k = 0; k < HH; k++) acc += xns[w][k] * W1s[k * PHD + lane];
    float hgt = acc > 0.f ? acc : 0.f;
    float o = warpsum(hgt * W2[lane]);
    if (lane == 0) out[n] = sigmoid_fast(o + b2[0]);
}

// ---------------- launch -----------------------------------------------------
extern "C" void kernel_launch(void* const* d_in, const int* in_sizes, int n_in,
                              void* d_out, int out_size) {
    const float* features = (const float*)d_in[0];
    const float* pos_adj  = (const float*)d_in[1];
    const float* neg_adj  = (const float*)d_in[2];
    const float* gru_Wih  = (const float*)d_in[3];
    const float* gru_Whh  = (const float*)d_in[4];
    const float* gru_bih  = (const float*)d_in[5];
    const float* gru_bhh  = (const float*)d_in[6];
    const float* pos_W    = (const float*)d_in[7];
    const float* pos_u    = (const float*)d_in[8];
    const float* pos_v    = (const float*)d_in[9];
    const float* pos_b    = (const float*)d_in[10];
    const float* pos_pW   = (const float*)d_in[11];
    const float* pos_pb   = (const float*)d_in[12];
    const float* neg_W    = (const float*)d_in[13];
    const float* neg_u    = (const float*)d_in[14];
    const float* neg_v    = (const float*)d_in[15];
    const float* neg_b    = (const float*)d_in[16];
    const float* neg_pW   = (const float*)d_in[17];
    const float* neg_pb   = (const float*)d_in[18];
    const float* self_W   = (const float*)d_in[19];
    const float* self_b   = (const float*)d_in[20];
    const float* mpos_W   = (const float*)d_in[21];
    const float* mpos_b   = (const float*)d_in[22];
    const float* mneg_W   = (const float*)d_in[23];
    const float* mneg_b   = (const float*)d_in[24];
    const float* sem_W1   = (const float*)d_in[25];
    const float* sem_b1   = (const float*)d_in[26];
    const float* sem_W2   = (const float*)d_in[27];
    const float* pred_W1  = (const float*)d_in[28];
    const float* pred_b1  = (const float*)d_in[29];
    const float* pred_W2  = (const float*)d_in[30];
    const float* pred_b2  = (const float*)d_in[31];
    float* out = (float*)d_out;

    static bool attr_done = false;
    if (!attr_done) {
        cudaFuncSetAttribute(k_gru, cudaFuncAttributeMaxDynamicSharedMemorySize, GRU_SMEM);
        cudaFuncSetAttribute(k_gemm, cudaFuncAttributeMaxDynamicSharedMemorySize, GEMM_SMEM);
        attr_done = true;
    }

    float *p_support, *p_gatP, *p_gatN, *p_supP, *p_supN;
    float *p_residP, *p_residN, *p_selfE, *p_posE, *p_negE;
    cudaGetSymbolAddress((void**)&p_support, g_support);
    cudaGetSymbolAddress((void**)&p_supP, g_supP);
    cudaGetSymbolAddress((void**)&p_supN, g_supN);
    cudaGetSymbolAddress((void**)&p_residP, g_residP);
    cudaGetSymbolAddress((void**)&p_residN, g_residN);
    cudaGetSymbolAddress((void**)&p_selfE, g_selfE);
    cudaGetSymbolAddress((void**)&p_gatP, g_gatP);
    cudaGetSymbolAddress((void**)&p_gatN, g_gatN);
    cudaGetSymbolAddress((void**)&p_posE, g_posE);
    cudaGetSymbolAddress((void**)&p_negE, g_negE);

    k_prep<<<48, 256>>>(gru_Whh);                                   // 1
    k_prep_wih<<<6, 256>>>(gru_Wih);                                // 2
    k_zero<<<1, 128>>>();                                           // 3
    k_gru<<<NN / 32, 512, GRU_SMEM>>>(features, gru_bih, gru_bhh);  // 4
    {
        GemmJobs jb;
        jb.j[0] = { p_support, pos_W,  nullptr, nullptr, p_supP };
        jb.j[1] = { p_support, neg_W,  nullptr, nullptr, p_supN };
        jb.j[2] = { p_support, pos_pW, pos_b,   pos_pb,  p_residP };
        jb.j[3] = { p_support, neg_pW, neg_b,   neg_pb,  p_residN };
        jb.j[4] = { p_support, self_W, self_b,  nullptr, p_selfE };
        dim3 grid(NN / 128, 5);
        k_gemm<<<grid, 256, GEMM_SMEM>>>(jb);                       // 5
    }
    {
        dim3 grid(NN / 8, 2);
        k_f1f2<<<grid, 256>>>(pos_u, pos_v, neg_u, neg_v);          // 6
    }
    {
        dim3 grid(NN, 2);
        k_gat<<<grid, 128>>>(pos_adj, neg_adj);                     // 7
    }
    {
        GemmJobs jb;
        jb.j[0] = { p_gatP, mpos_W, mpos_b, nullptr, p_posE };
        jb.j[1] = { p_gatN, mneg_W, mneg_b, nullptr, p_negE };
        jb.j[2] = jb.j[0]; jb.j[3] = jb.j[0]; jb.j[4] = jb.j[0];
        dim3 grid(NN / 128, 2);
        k_gemm<<<grid, 256, GEMM_SMEM>>>(jb);                       // 8
    }
    k_sem<<<NN / 64, 256>>>(sem_W1, sem_b1, sem_W2);                // 9
    k_pred<<<NN / 8, 256>>>(pred_W1, pred_b1, pred_W2, pred_b2, out); // 10
}

// round 12
// speedup vs baseline: 9.5779x; 1.0678x over previous
#include <cuda_runtime.h>
#include <cuda_bf16.h>
#include <cstdint>
#include <cstddef>

#define NN 4096
#define TT 24
#define FF 16
#define HH 128
#define GG 384
#define NHD 4
#define DOD 32
#define SEMD 64
#define PHD 32

// ---------------- scratch (static device globals; no runtime allocation) ----
__device__ float g_support[NN * HH];
__device__ float g_supP[NN * HH];
__device__ float g_supN[NN * HH];
__device__ float g_residP[NN * HH];
__device__ float g_residN[NN * HH];
__device__ float g_selfE[NN * HH];
__device__ float g_f1P[NHD * NN];
__device__ float g_f2P[NHD * NN];
__device__ float g_f1N[NHD * NN];
__device__ float g_f2N[NHD * NN];
__device__ float g_gatP[NN * HH];
__device__ float g_gatN[NN * HH];
__device__ float g_posE[NN * HH];
__device__ float g_negE[NN * HH];
__device__ float g_fused[NN * HH];
__device__ float g_colsum[HH];
// bf16 fragment-ordered Whh: hi (register-staged per warp), lo (streamed)
__device__ __align__(16) uint32_t g_Bhi[8 * 8 * 6 * 32 * 2];   // 24576 words
__device__ __align__(16) uint32_t g_Blo[8 * 8 * 2 * 32 * 8];   // 32768 words
// bf16 fragment-ordered Wih (k=16 -> one k-chunk)
__device__ __align__(16) uint32_t g_WihHi[8 * 6 * 32 * 2];
__device__ __align__(16) uint32_t g_WihLo[8 * 2 * 32 * 8];

__device__ __forceinline__ float warpsum(float v) {
#pragma unroll
    for (int o = 16; o >= 1; o >>= 1) v += __shfl_down_sync(0xffffffffu, v, o);
    return v;
}
__device__ __forceinline__ float warpsum_bfly(float v) {
#pragma unroll
    for (int o = 16; o >= 1; o >>= 1) v += __shfl_xor_sync(0xffffffffu, v, o);
    return v;
}
__device__ __forceinline__ float sigmoid_fast(float x) {
    return __fdividef(1.f, 1.f + __expf(-x));
}
__device__ __forceinline__ float tanh_fast(float x) {
    float e = __expf(-2.f * x);
    return __fdividef(2.f, 1.f + e) - 1.f;
}
__device__ __forceinline__ void mma_bf16(float d[4], const uint32_t a[4],
                                         uint32_t b0, uint32_t b1) {
    asm volatile("mma.sync.aligned.m16n8k16.row.col.f32.bf16.bf16.f32 "
                 "{%0,%1,%2,%3}, {%4,%5,%6,%7}, {%8,%9}, {%0,%1,%2,%3};"
                 : "+f"(d[0]), "+f"(d[1]), "+f"(d[2]), "+f"(d[3])
                 : "r"(a[0]), "r"(a[1]), "r"(a[2]), "r"(a[3]), "r"(b0), "r"(b1));
}

// ---------------- kernel 0a: bf16 fragment-ordered Whh -----------------------
__global__ void k_prep(const float* __restrict__ Whh) {
    int idx = blockIdx.x * 256 + threadIdx.x;       // 12288 = 8*8*6*32
    if (idx >= 8 * 8 * 6 * 32) return;
    int lane = idx & 31; int r = idx >> 5;
    int nt = r % 6; r /= 6;
    int w8 = r & 7; int kt = r >> 3;                 // kt in [0,8)
    int g = nt >> 1, s = nt & 1;
    int n = g * 128 + w8 * 16 + s * 8 + (lane >> 2);
    int kb = kt * 16 + (lane & 3) * 2;
    float w0 = Whh[n * 128 + kb],     w1 = Whh[n * 128 + kb + 1];
    float w2 = Whh[n * 128 + kb + 8], w3 = Whh[n * 128 + kb + 9];
    __nv_bfloat16 h0 = __float2bfloat16(w0), h1 = __float2bfloat16(w1);
    __nv_bfloat16 h2 = __float2bfloat16(w2), h3 = __float2bfloat16(w3);
    {
        __nv_bfloat162 v; v.x = h0; v.y = h1;
        g_Bhi[idx * 2 + 0] = *(uint32_t*)&v;
        v.x = h2; v.y = h3;
        g_Bhi[idx * 2 + 1] = *(uint32_t*)&v;
    }
    __nv_bfloat162 l01, l23;
    l01.x = __float2bfloat16(w0 - __bfloat162float(h0));
    l01.y = __float2bfloat16(w1 - __bfloat162float(h1));
    l23.x = __float2bfloat16(w2 - __bfloat162float(h2));
    l23.y = __float2bfloat16(w3 - __bfloat162float(h3));
    uint32_t* lo = &g_Blo[(((kt * 8 + w8) * 2 + s) * 32 + lane) * 8 + g * 2];
    lo[0] = *(uint32_t*)&l01;
    lo[1] = *(uint32_t*)&l23;
}

// ---------------- kernel 0b: bf16 fragment-ordered Wih (k=16) ---------------
__global__ void k_prep_wih(const float* __restrict__ Wih) {
    int idx = blockIdx.x * 256 + threadIdx.x;       // 1536 = 8*6*32
    if (idx >= 8 * 6 * 32) return;
    int lane = idx & 31; int r = idx >> 5;
    int nt = r % 6; int w8 = r / 6;
    int g = nt >> 1, s = nt & 1;
    int n = g * 128 + w8 * 16 + s * 8 + (lane >> 2);
    int kb = (lane & 3) * 2;
    float w0 = Wih[n * FF + kb],     w1 = Wih[n * FF + kb + 1];
    float w2 = Wih[n * FF + kb + 8], w3 = Wih[n * FF + kb + 9];
    __nv_bfloat16 h0 = __float2bfloat16(w0), h1 = __float2bfloat16(w1);
    __nv_bfloat16 h2 = __float2bfloat16(w2), h3 = __float2bfloat16(w3);
    {
        __nv_bfloat162 v; v.x = h0; v.y = h1;
        g_WihHi[idx * 2 + 0] = *(uint32_t*)&v;
        v.x = h2; v.y = h3;
        g_WihHi[idx * 2 + 1] = *(uint32_t*)&v;
    }
    __nv_bfloat162 l01, l23;
    l01.x = __float2bfloat16(w0 - __bfloat162float(h0));
    l01.y = __float2bfloat16(w1 - __bfloat162float(h1));
    l23.x = __float2bfloat16(w2 - __bfloat162float(h2));
    l23.y = __float2bfloat16(w3 - __bfloat162float(h3));
    uint32_t* lo = &g_WihLo[((w8 * 2 + s) * 32 + lane) * 8 + g * 2];
    lo[0] = *(uint32_t*)&l01;
    lo[1] = *(uint32_t*)&l23;
}

// ---------------- kernel 2: fused GRU, 256 thr, B-hi in registers -----------
#define HBUF 2176

__global__ void __launch_bounds__(256, 1) k_gru(const float* __restrict__ feat,
                                                const float* __restrict__ bih,
                                                const float* __restrict__ bhh) {
    __shared__ __align__(16) uint32_t hbase[4 * HBUF];   // 34.8 KB
    int tid = threadIdx.x;
    int w = tid >> 5, lane = tid & 31;                   // w in [0,8)
    int qr = lane >> 2, qc = lane & 3;
    int node0 = blockIdx.x * 32;

    // B-hi slice into registers: bhr[kt][g][s]
    const uint2* Bhi2g = (const uint2*)g_Bhi;
    uint2 bhr[8][3][2];
#pragma unroll
    for (int kt = 0; kt < 8; kt++)
#pragma unroll
        for (int g = 0; g < 3; g++)
#pragma unroll
            for (int s = 0; s < 2; s++)
                bhr[kt][g][s] = __ldg(&Bhi2g[((kt * 8 + w) * 6 + g * 2 + s) * 32 + lane]);

    for (int i = tid; i < 4 * HBUF; i += 256) hbase[i] = 0u;

    // biases (warp covers cols w*16 + s*8 + 2qc + jj)
    float bRr[2][2], bRz[2][2], biN[2][2], bhN[2][2];
#pragma unroll
    for (int s = 0; s < 2; s++)
#pragma unroll
        for (int jj = 0; jj < 2; jj++) {
            int c = w * 16 + s * 8 + 2 * qc + jj;
            bRr[s][jj] = __ldg(&bih[c]) + __ldg(&bhh[c]);
            bRz[s][jj] = __ldg(&bih[128 + c]) + __ldg(&bhh[128 + c]);
            biN[s][jj] = __ldg(&bih[256 + c]);
            bhN[s][jj] = __ldg(&bhh[256 + c]);
        }
    __syncthreads();

    const uint2* WihHi2 = (const uint2*)g_WihHi;
    int cur = 0;

    for (int t = 0; t < TT; t++) {
        uint32_t* h_hi_w = hbase + cur * (2 * HBUF);
        uint32_t* h_lo_w = h_hi_w + HBUF;
        uint32_t* n_hi_w = hbase + (cur ^ 1) * (2 * HBUF);
        uint32_t* n_lo_w = n_hi_w + HBUF;

        // ---- x loads -> immediate bf16 split (xr not kept) ----
        uint32_t xh[2][4], xl[2][4];
#pragma unroll
        for (int m = 0; m < 2; m++) {
            const float* base = feat + (size_t)(node0 + m * 16) * (TT * FF) + t * FF;
            float2 v[4];
            v[0] = __ldg((const float2*)(base + (size_t)qr * (TT * FF) + 2 * qc));
            v[1] = __ldg((const float2*)(base + (size_t)(qr + 8) * (TT * FF) + 2 * qc));
            v[2] = __ldg((const float2*)(base + (size_t)qr * (TT * FF) + 2 * qc + 8));
            v[3] = __ldg((const float2*)(base + (size_t)(qr + 8) * (TT * FF) + 2 * qc + 8));
#pragma unroll
            for (int j = 0; j < 4; j++) {
                __nv_bfloat162 hv; hv.x = __float2bfloat16(v[j].x); hv.y = __float2bfloat16(v[j].y);
                xh[m][j] = *(uint32_t*)&hv;
                __nv_bfloat162 lv;
                lv.x = __float2bfloat16(v[j].x - __bfloat162float(hv.x));
                lv.y = __float2bfloat16(v[j].y - __bfloat162float(hv.y));
                xl[m][j] = *(uint32_t*)&lv;
            }
        }

        float d[2][3][2][4];   // [m][g][s][4]
        float dx[2][2][4];     // [m][s][4]
#pragma unroll
        for (int m = 0; m < 2; m++) {
#pragma unroll
            for (int g = 0; g < 3; g++)
#pragma unroll
                for (int s = 0; s < 2; s++)
#pragma unroll
                    for (int j = 0; j < 4; j++) d[m][g][s][j] = 0.f;
#pragma unroll
            for (int s = 0; s < 2; s++)
#pragma unroll
                for (int j = 0; j < 4; j++) dx[m][s][j] = 0.f;
        }

        // ---- x @ Wih^T (k=16) ----
#pragma unroll
        for (int s = 0; s < 2; s++) {
            const uint32_t* p = &g_WihLo[((w * 2 + s) * 32 + lane) * 8];
            uint4 wlA = __ldg((const uint4*)p);
            uint2 wlB = __ldg((const uint2*)(p + 4));
            uint32_t wlw[6] = {wlA.x, wlA.y, wlA.z, wlA.w, wlB.x, wlB.y};
#pragma unroll
            for (int g = 0; g < 3; g++) {
                uint2 bh = __ldg(&WihHi2[(w * 6 + g * 2 + s) * 32 + lane]);
#pragma unroll
                for (int m = 0; m < 2; m++) {
                    float* D = (g == 2) ? dx[m][s] : d[m][g][s];
                    mma_bf16(D, xh[m], bh.x, bh.y);
                    mma_bf16(D, xl[m], bh.x, bh.y);
                    mma_bf16(D, xh[m], wlw[g * 2], wlw[g * 2 + 1]);
                }
            }
        }

        // ---- h @ Whh^T (bf16, B-hi from registers, lo streamed) ----
        if (t) {
#pragma unroll
            for (int kt = 0; kt < 8; kt++) {
                uint32_t ah[2][4], al[2][4];
#pragma unroll
                for (int m = 0; m < 2; m++) {
                    int r0 = (m * 16 + qr) * 68 + kt * 8 + qc;
                    ah[m][0] = h_hi_w[r0];
                    ah[m][1] = h_hi_w[r0 + 8 * 68];
                    ah[m][2] = h_hi_w[r0 + 4];
                    ah[m][3] = h_hi_w[r0 + 8 * 68 + 4];
                    al[m][0] = h_lo_w[r0];
                    al[m][1] = h_lo_w[r0 + 8 * 68];
                    al[m][2] = h_lo_w[r0 + 4];
                    al[m][3] = h_lo_w[r0 + 8 * 68 + 4];
                }
#pragma unroll
                for (int s = 0; s < 2; s++) {
                    const uint32_t* p = &g_Blo[(((kt * 8 + w) * 2 + s) * 32 + lane) * 8];
                    uint4 lA = __ldg((const uint4*)p);
                    uint2 lB = __ldg((const uint2*)(p + 4));
                    uint32_t lw[6] = {lA.x, lA.y, lA.z, lA.w, lB.x, lB.y};
#pragma unroll
                    for (int g = 0; g < 3; g++) {
                        uint2 bh = bhr[kt][g][s];
#pragma unroll
                        for (int m = 0; m < 2; m++) {
                            mma_bf16(d[m][g][s], ah[m], bh.x, bh.y);
                            mma_bf16(d[m][g][s], al[m], bh.x, bh.y);
                            mma_bf16(d[m][g][s], ah[m], lw[g * 2], lw[g * 2 + 1]);
                        }
                    }
                }
            }
        }

        // ---- gate math: read h[cur], write h[nxt], single barrier ----
#pragma unroll
        for (int m = 0; m < 2; m++)
#pragma unroll
            for (int s = 0; s < 2; s++)
#pragma unroll
                for (int rg = 0; rg < 2; rg++) {
                    int row = m * 16 + qr + rg * 8;
                    int wi = row * 68 + w * 8 + s * 4 + qc;
                    float2 hhf = __bfloat1622float2(*(__nv_bfloat162*)&h_hi_w[wi]);
                    float2 hlf = __bfloat1622float2(*(__nv_bfloat162*)&h_lo_w[wi]);
                    float hn[2];
#pragma unroll
                    for (int jj = 0; jj < 2; jj++) {
                        float hold = jj ? (hhf.y + hlf.y) : (hhf.x + hlf.x);
                        int di = rg * 2 + jj;
                        float rr = sigmoid_fast(d[m][0][s][di] + bRr[s][jj]);
                        float zz = sigmoid_fast(d[m][1][s][di] + bRz[s][jj]);
                        float nv = tanh_fast(dx[m][s][di] + biN[s][jj] +
                                             rr * (d[m][2][s][di] + bhN[s][jj]));
                        hn[jj] = (1.f - zz) * nv + zz * hold;
                    }
                    __nv_bfloat162 hv; hv.x = __float2bfloat16(hn[0]); hv.y = __float2bfloat16(hn[1]);
                    __nv_bfloat162 lv;
                    lv.x = __float2bfloat16(hn[0] - __bfloat162float(hv.x));
                    lv.y = __float2bfloat16(hn[1] - __bfloat162float(hv.y));
                    n_hi_w[wi] = *(uint32_t*)&hv;
                    n_lo_w[wi] = *(uint32_t*)&lv;
                }
        __syncthreads();
        cur ^= 1;
    }

    const __nv_bfloat16* h_hi = (const __nv_bfloat16*)(hbase + cur * (2 * HBUF));
    const __nv_bfloat16* h_lo = h_hi + 2 * HBUF;
    for (int i = tid; i < 32 * HH; i += 256) {
        int row = i >> 7, col = i & 127;
        g_support[(size_t)(node0 + row) * HH + col] =
            __bfloat162float(h_hi[row * 136 + col]) +
            __bfloat162float(h_lo[row * 136 + col]);
    }
}

// ---------------- kernel 3: bf16 tensor-core GEMM C = A @ B (+b1+b2) --------
struct GemmJob { const float* A; const float* B; const float* b1; const float* b2; float* C; };
struct GemmJobs { GemmJob j[5]; };

#define GEMM_SMEM (4 * 128 * 136 * 2)   // 139264 B

__global__ void __launch_bounds__(256) k_gemm(GemmJobs jobs) {
    GemmJob job = jobs.j[blockIdx.y];
    extern __shared__ char smc[];
    uint16_t* As_hi = (uint16_t*)smc;                 // [128][136] bf16, A[r][k]
    uint16_t* As_lo = As_hi + 128 * 136;
    uint16_t* Bs_hi = As_lo + 128 * 136;              // [128][136] bf16, B^T[n][k]
    uint16_t* Bs_lo = Bs_hi + 128 * 136;
    int tid = threadIdx.x;
    int node0 = blockIdx.x * 128;

    for (int idx = tid; idx < 128 * 128; idx += 256) {
        int r = idx >> 7, c = idx & 127;
        float a = job.A[(size_t)(node0 + r) * HH + c];
        __nv_bfloat16 ah = __float2bfloat16(a);
        As_hi[r * 136 + c] = __bfloat16_as_ushort(ah);
        As_lo[r * 136 + c] =
            __bfloat16_as_ushort(__float2bfloat16(a - __bfloat162float(ah)));
        float b = job.B[idx];                          // B[k=r][n=c]
        __nv_bfloat16 bh = __float2bfloat16(b);
        Bs_hi[c * 136 + r] = __bfloat16_as_ushort(bh); // transpose -> [n][k]
        Bs_lo[c * 136 + r] =
            __bfloat16_as_ushort(__float2bfloat16(b - __bfloat162float(bh)));
    }
    __syncthreads();

    int w = tid >> 5, lane = tid & 31;
    int qr = lane >> 2, qc = lane & 3;
    int r0 = w * 16;
    const uint32_t* Aw_hi = (const uint32_t*)As_hi;   // [128][68] words
    const uint32_t* Aw_lo = (const uint32_t*)As_lo;
    const uint32_t* Bw_hi = (const uint32_t*)Bs_hi;
    const uint32_t* Bw_lo = (const uint32_t*)Bs_lo;

    float acc[16][4];
#pragma unroll
    for (int ct = 0; ct < 16; ct++)
#pragma unroll
        for (int j = 0; j < 4; j++) acc[ct][j] = 0.f;

#pragma unroll 1
    for (int kt = 0; kt < 8; kt++) {
        int kc = kt * 8 + qc;
        uint32_t ah[4], al[4];
        ah[0] = Aw_hi[(r0 + qr) * 68 + kc];
        ah[1] = Aw_hi[(r0 + qr + 8) * 68 + kc];
        ah[2] = Aw_hi[(r0 + qr) * 68 + kc + 4];
        ah[3] = Aw_hi[(r0 + qr + 8) * 68 + kc + 4];
        al[0] = Aw_lo[(r0 + qr) * 68 + kc];
        al[1] = Aw_lo[(r0 + qr + 8) * 68 + kc];
        al[2] = Aw_lo[(r0 + qr) * 68 + kc + 4];
        al[3] = Aw_lo[(r0 + qr + 8) * 68 + kc + 4];
#pragma unroll
        for (int cg = 0; cg < 4; cg++) {
            uint32_t bh0[4], bh1[4], bl0[4], bl1[4];
#pragma unroll
            for (int j = 0; j < 4; j++) {
                int n0 = (cg * 4 + j) * 8;
                bh0[j] = Bw_hi[(n0 + qr) * 68 + kc];
                bh1[j] = Bw_hi[(n0 + qr) * 68 + kc + 4];
                bl0[j] = Bw_lo[(n0 + qr) * 68 + kc];
                bl1[j] = Bw_lo[(n0 + qr) * 68 + kc + 4];
            }
#pragma unroll
            for (int j = 0; j < 4; j++)
                mma_bf16(acc[cg * 4 + j], ah, bh0[j], bh1[j]);
#pragma unroll
            for (int j = 0; j < 4; j++)
                mma_bf16(acc[cg * 4 + j], al, bh0[j], bh1[j]);
#pragma unroll
            for (int j = 0; j < 4; j++)
                mma_bf16(acc[cg * 4 + j], ah, bl0[j], bl1[j]);
        }
    }

#pragma unroll
    for (int ct = 0; ct < 16; ct++) {
        int c0 = ct * 8 + 2 * qc;
        float b0 = 0.f, b1v = 0.f;
        if (job.b1) { b0 += __ldg(&job.b1[c0]); b1v += __ldg(&job.b1[c0 + 1]); }
        if (job.b2) { b0 += __ldg(&job.b2[c0]); b1v += __ldg(&job.b2[c0 + 1]); }
        int r = node0 + r0 + qr;
        *(float2*)&job.C[(size_t)r * HH + c0] =
            make_float2(acc[ct][0] + b0, acc[ct][1] + b1v);
        *(float2*)&job.C[(size_t)(r + 8) * HH + c0] =
            make_float2(acc[ct][2] + b0, acc[ct][3] + b1v);
    }
}

// ---------------- kernel 4: f1/f2 per head -----------------------------------
__global__ void k_f1f2(const float* __restrict__ uP, const float* __restrict__ vP,
                       const float* __restrict__ uN, const float* __restrict__ vN) {
    const float* sup; const float* u; const float* v; float* f1; float* f2;
    if (blockIdx.y == 0) { sup = g_supP; u = uP; v = vP; f1 = g_f1P; f2 = g_f2P; }
    else                 { sup = g_supN; u = uN; v = vN; f1 = g_f1N; f2 = g_f2N; }
    int n = blockIdx.x * 8 + (threadIdx.x >> 5);
    int lane = threadIdx.x & 31;
#pragma unroll
    for (int h = 0; h < NHD; h++) {
        float s = sup[(size_t)n * HH + h * DOD + lane];
        float a = s * u[h * DOD + lane];
        float b = s * v[h * DOD + lane];
        a = warpsum(a); b = warpsum(b);
        if (lane == 0) { f1[h * NN + n] = a; f2[h * NN + n] = b; }
    }
}

// ---------------- kernel 5: GAT masked-attention aggregation -----------------
__global__ void __launch_bounds__(128) k_gat(const float* __restrict__ adjP,
                                             const float* __restrict__ adjN) {
    __shared__ int s_cnt;
    __shared__ int s_list[640];
    __shared__ float s_a[640];
    const float* adj; const float* sup; const float* f1; const float* f2;
    const float* resid; float* outp;
    if (blockIdx.y == 0) { adj = adjP; sup = g_supP; f1 = g_f1P; f2 = g_f2P; resid = g_residP; outp = g_gatP; }
    else                 { adj = adjN; sup = g_supN; f1 = g_f1N; f2 = g_f2N; resid = g_residN; outp = g_gatN; }
    int i = blockIdx.x, tid = threadIdx.x;
    int h = tid >> 5;
    if (tid == 0) s_cnt = 0;
    __syncthreads();
    const float4* row = (const float4*)(adj + (size_t)i * NN);
    for (int j4 = tid; j4 < NN / 4; j4 += 128) {
        float4 a = __ldg(&row[j4]);
        if (a.x != 0.f) { int p = atomicAdd(&s_cnt, 1); s_list[p] = j4 * 4 + 0; s_a[p] = a.x; }
        if (a.y != 0.f) { int p = atomicAdd(&s_cnt, 1); s_list[p] = j4 * 4 + 1; s_a[p] = a.y; }
        if (a.z != 0.f) { int p = atomicAdd(&s_cnt, 1); s_list[p] = j4 * 4 + 2; s_a[p] = a.z; }
        if (a.w != 0.f) { int p = atomicAdd(&s_cnt, 1); s_list[p] = j4 * 4 + 3; s_a[p] = a.w; }
    }
    __syncthreads();
    int cnt = s_cnt;
    float f2i = f2[h * NN + i];
    float num = 0.f, den = 0.f;
    for (int t = 0; t < cnt; t++) {
        int j = s_list[t];
        float w = f1[h * NN + j] + f2i;
        w = (w > 0.f) ? w : 0.2f * w;
        w *= s_a[t];
        den += w;
        num += w * sup[(size_t)j * HH + tid];
    }
    float d = (den == 0.f) ? 1.f : den;
    outp[(size_t)i * HH + tid] = num / d + resid[(size_t)i * HH + tid];
}

// ---------------- kernel 6: zero colsum --------------------------------------
__global__ void k_zero() { if (threadIdx.x < HH) g_colsum[threadIdx.x] = 0.f; }

// ---------------- kernel 7: semantic attention, warp-per-node ----------------
__global__ void __launch_bounds__(256) k_sem(const float* __restrict__ W1,
                                             const float* __restrict__ b1,
                                             const float* __restrict__ W2) {
    __shared__ float W1s[128 * 65];
    __shared__ float W2s[SEMD], b1s[SEMD];
    __shared__ float semb[8][3][128];
    int tid = threadIdx.x;
    for (int i = tid; i < 128 * 64; i += 256) {
        int k = i >> 6, s = i & 63;
        W1s[k * 65 + s] = W1[i];
    }
    if (tid < SEMD) { W2s[tid] = W2[tid]; b1s[tid] = b1[tid]; }
    __syncthreads();

    int w = tid >> 5, lane = tid & 31;
    float csum[4] = {0.f, 0.f, 0.f, 0.f};
    int nbase = (blockIdx.x * 8 + w) * 8;

    for (int i = 0; i < 8; i++) {
        int n = nbase + i;
        float4 ev[3];
        ev[0] = *(const float4*)&g_selfE[(size_t)n * HH + lane * 4];
        ev[1] = *(const float4*)&g_posE[(size_t)n * HH + lane * 4];
        ev[2] = *(const float4*)&g_negE[(size_t)n * HH + lane * 4];
        __syncwarp();
        *(float4*)&semb[w][0][lane * 4] = ev[0];
        *(float4*)&semb[w][1][lane * 4] = ev[1];
        *(float4*)&semb[w][2][lane * 4] = ev[2];
        __syncwarp();

        float acc[3][2];
#pragma unroll
        for (int e = 0; e < 3; e++) { acc[e][0] = b1s[lane]; acc[e][1] = b1s[lane + 32]; }
#pragma unroll 4
        for (int k = 0; k < HH; k++) {
            float w1a = W1s[k * 65 + lane];
            float w1b = W1s[k * 65 + lane + 32];
            float x0 = semb[w][0][k], x1 = semb[w][1][k], x2 = semb[w][2][k];
            acc[0][0] += x0 * w1a; acc[0][1] += x0 * w1b;
            acc[1][0] += x1 * w1a; acc[1][1] += x1 * w1b;
            acc[2][0] += x2 * w1a; acc[2][1] += x2 * w1b;
        }
        float wv[3];
#pragma unroll
        for (int e = 0; e < 3; e++) {
            float tsum = tanh_fast(acc[e][0]) * W2s[lane] +
                         tanh_fast(acc[e][1]) * W2s[lane + 32];
            wv[e] = warpsum_bfly(tsum);
        }
        float m = fmaxf(wv[0], fmaxf(wv[1], wv[2]));
        float e0 = __expf(wv[0] - m), e1 = __expf(wv[1] - m), e2 = __expf(wv[2] - m);
        float inv = __fdividef(1.f, e0 + e1 + e2);
        float be0 = e0 * inv, be1 = e1 * inv, be2 = e2 * inv;
        float4 f;
        f.x = be0 * ev[0].x + be1 * ev[1].x + be2 * ev[2].x;
        f.y = be0 * ev[0].y + be1 * ev[1].y + be2 * ev[2].y;
        f.z = be0 * ev[0].z + be1 * ev[1].z + be2 * ev[2].z;
        f.w = be0 * ev[0].w + be1 * ev[1].w + be2 * ev[2].w;
        *(float4*)&g_fused[(size_t)n * HH + lane * 4] = f;
        csum[0] += f.x; csum[1] += f.y; csum[2] += f.z; csum[3] += f.w;
    }
    atomicAdd(&g_colsum[lane * 4 + 0], csum[0]);
    atomicAdd(&g_colsum[lane * 4 + 1], csum[1]);
    atomicAdd(&g_colsum[lane * 4 + 2], csum[2]);
    atomicAdd(&g_colsum[lane * 4 + 3], csum[3]);
}

// ---------------- kernel 8: pairnorm + predictor -----------------------------
__global__ void __launch_bounds__(256) k_pred(const float* __restrict__ W1,
                                              const float* __restrict__ b1,
                                              const float* __restrict__ W2,
                                              const float* __restrict__ b2,
                                              float* __restrict__ out) {
    __shared__ float W1s[HH * PHD];
    __shared__ float xns[8][HH];
    int tid = threadIdx.x;
    for (int i = tid; i < HH * PHD; i += 256) W1s[i] = W1[i];
    int w = tid >> 5, lane = tid & 31;
    int n = blockIdx.x * 8 + w;
    float xv[4]; float ss = 0.f;
    const float invN = 1.f / (float)NN;
#pragma unroll
    for (int j = 0; j < 4; j++) {
        int d = lane + j * 32;
        float x = g_fused[(size_t)n * HH + d] - g_colsum[d] * invN;
        xv[j] = x; ss += x * x;
    }
    ss = warpsum(ss);
    ss = __shfl_sync(0xffffffffu, ss, 0);
    float rinv = rsqrtf(1e-6f + ss);
#pragma unroll
    for (int j = 0; j < 4; j++) xns[w][lane + j * 32] = xv[j] * rinv;
    __syncthreads();

    float acc = b1[lane];
#pragma unroll 4
    for (int k = 0; k < HH; k++) acc += xns[w][k] * W1s[k * PHD + lane];
    float hgt = acc > 0.f ? acc : 0.f;
    float o = warpsum(hgt * W2[lane]);
    if (lane == 0) out[n] = sigmoid_fast(o + b2[0]);
}

// ---------------- launch -----------------------------------------------------
extern "C" void kernel_launch(void* const* d_in, const int* in_sizes, int n_in,
                              void* d_out, int out_size) {
    const float* features = (const float*)d_in[0];
    const float* pos_adj  = (const float*)d_in[1];
    const float* neg_adj  = (const float*)d_in[2];
    const float* gru_Wih  = (const float*)d_in[3];
    const float* gru_Whh  = (const float*)d_in[4];
    const float* gru_bih  = (const float*)d_in[5];
    const float* gru_bhh  = (const float*)d_in[6];
    const float* pos_W    = (const float*)d_in[7];
    const float* pos_u    = (const float*)d_in[8];
    const float* pos_v    = (const float*)d_in[9];
    const float* pos_b    = (const float*)d_in[10];
    const float* pos_pW   = (const float*)d_in[11];
    const float* pos_pb   = (const float*)d_in[12];
    const float* neg_W    = (const float*)d_in[13];
    const float* neg_u    = (const float*)d_in[14];
    const float* neg_v    = (const float*)d_in[15];
    const float* neg_b    = (const float*)d_in[16];
    const float* neg_pW   = (const float*)d_in[17];
    const float* neg_pb   = (const float*)d_in[18];
    const float* self_W   = (const float*)d_in[19];
    const float* self_b   = (const float*)d_in[20];
    const float* mpos_W   = (const float*)d_in[21];
    const float* mpos_b   = (const float*)d_in[22];
    const float* mneg_W   = (const float*)d_in[23];
    const float* mneg_b   = (const float*)d_in[24];
    const float* sem_W1   = (const float*)d_in[25];
    const float* sem_b1   = (const float*)d_in[26];
    const float* sem_W2   = (const float*)d_in[27];
    const float* pred_W1  = (const float*)d_in[28];
    const float* pred_b1  = (const float*)d_in[29];
    const float* pred_W2  = (const float*)d_in[30];
    const float* pred_b2  = (const float*)d_in[31];
    float* out = (float*)d_out;

    static bool attr_done = false;
    if (!attr_done) {
        cudaFuncSetAttribute(k_gemm, cudaFuncAttributeMaxDynamicSharedMemorySize, GEMM_SMEM);
        attr_done = true;
    }

    float *p_support, *p_gatP, *p_gatN, *p_supP, *p_supN;
    float *p_residP, *p_residN, *p_selfE, *p_posE, *p_negE;
    cudaGetSymbolAddress((void**)&p_support, g_support);
    cudaGetSymbolAddress((void**)&p_supP, g_supP);
    cudaGetSymbolAddress((void**)&p_supN, g_supN);
    cudaGetSymbolAddress((void**)&p_residP, g_residP);
    cudaGetSymbolAddress((void**)&p_residN, g_residN);
    cudaGetSymbolAddress((void**)&p_selfE, g_selfE);
    cudaGetSymbolAddress((void**)&p_gatP, g_gatP);
    cudaGetSymbolAddress((void**)&p_gatN, g_gatN);
    cudaGetSymbolAddress((void**)&p_posE, g_posE);
    cudaGetSymbolAddress((void**)&p_negE, g_negE);

    k_prep<<<48, 256>>>(gru_Whh);                                   // 1
    k_prep_wih<<<6, 256>>>(gru_Wih);                                // 2
    k_zero<<<1, 128>>>();                                           // 3
    k_gru<<<NN / 32, 256>>>(features, gru_bih, gru_bhh);            // 4
    {
        GemmJobs jb;
        jb.j[0] = { p_support, pos_W,  nullptr, nullptr, p_supP };
        jb.j[1] = { p_support, neg_W,  nullptr, nullptr, p_supN };
        jb.j[2] = { p_support, pos_pW, pos_b,   pos_pb,  p_residP };
        jb.j[3] = { p_support, neg_pW, neg_b,   neg_pb,  p_residN };
        jb.j[4] = { p_support, self_W, self_b,  nullptr, p_selfE };
        dim3 grid(NN / 128, 5);
        k_gemm<<<grid, 256, GEMM_SMEM>>>(jb);                       // 5
    }
    {
        dim3 grid(NN / 8, 2);
        k_f1f2<<<grid, 256>>>(pos_u, pos_v, neg_u, neg_v);          // 6
    }
    {
        dim3 grid(NN, 2);
        k_gat<<<grid, 128>>>(pos_adj, neg_adj);                     // 7
    }
    {
        GemmJobs jb;
        jb.j[0] = { p_gatP, mpos_W, mpos_b, nullptr, p_posE };
        jb.j[1] = { p_gatN, mneg_W, mneg_b, nullptr, p_negE };
        jb.j[2] = jb.j[0]; jb.j[3] = jb.j[0]; jb.j[4] = jb.j[0];
        dim3 grid(NN / 128, 2);
        k_gemm<<<grid, 256, GEMM_SMEM>>>(jb);                       // 8
    }
    k_sem<<<NN / 64, 256>>>(sem_W1, sem_b1, sem_W2);                // 9
    k_pred<<<NN / 8, 256>>>(pred_W1, pred_b1, pred_W2, pred_b2, out); // 10
}

// round 13
// speedup vs baseline: 9.7413x; 1.0171x over previous
#include <cuda_runtime.h>
#include <cuda_bf16.h>
#include <cstdint>
#include <cstddef>

#define NN 4096
#define TT 24
#define FF 16
#define HH 128
#define GG 384
#define NHD 4
#define DOD 32
#define SEMD 64
#define PHD 32

// ---------------- scratch (static device globals; no runtime allocation) ----
__device__ float g_support[NN * HH];
__device__ float g_supP[NN * HH];
__device__ float g_supN[NN * HH];
__device__ float g_residP[NN * HH];
__device__ float g_residN[NN * HH];
__device__ float g_selfE[NN * HH];
__device__ float g_f1P[NHD * NN];
__device__ float g_f2P[NHD * NN];
__device__ float g_f1N[NHD * NN];
__device__ float g_f2N[NHD * NN];
__device__ float g_gatP[NN * HH];
__device__ float g_gatN[NN * HH];
__device__ float g_posE[NN * HH];
__device__ float g_negE[NN * HH];
__device__ float g_fused[NN * HH];
__device__ float g_colsum[HH];
// bf16 fragment-ordered Whh: hi (register-staged per warp), lo (streamed)
__device__ __align__(16) uint32_t g_Bhi[8 * 8 * 6 * 32 * 2];   // 24576 words
__device__ __align__(16) uint32_t g_Blo[8 * 8 * 2 * 32 * 8];   // 32768 words
// bf16 fragment-ordered Wih (k=16 -> one k-chunk)
__device__ __align__(16) uint32_t g_WihHi[8 * 6 * 32 * 2];
__device__ __align__(16) uint32_t g_WihLo[8 * 2 * 32 * 8];

__device__ __forceinline__ float warpsum(float v) {
#pragma unroll
    for (int o = 16; o >= 1; o >>= 1) v += __shfl_down_sync(0xffffffffu, v, o);
    return v;
}
__device__ __forceinline__ float warpsum_bfly(float v) {
#pragma unroll
    for (int o = 16; o >= 1; o >>= 1) v += __shfl_xor_sync(0xffffffffu, v, o);
    return v;
}
__device__ __forceinline__ float sigmoid_fast(float x) {
    return __fdividef(1.f, 1.f + __expf(-x));
}
__device__ __forceinline__ float tanh_fast(float x) {
    float e = __expf(-2.f * x);
    return __fdividef(2.f, 1.f + e) - 1.f;
}
__device__ __forceinline__ void mma_bf16(float d[4], const uint32_t a[4],
                                         uint32_t b0, uint32_t b1) {
    asm volatile("mma.sync.aligned.m16n8k16.row.col.f32.bf16.bf16.f32 "
                 "{%0,%1,%2,%3}, {%4,%5,%6,%7}, {%8,%9}, {%0,%1,%2,%3};"
                 : "+f"(d[0]), "+f"(d[1]), "+f"(d[2]), "+f"(d[3])
                 : "r"(a[0]), "r"(a[1]), "r"(a[2]), "r"(a[3]), "r"(b0), "r"(b1));
}

// ---------------- kernel 0: combined prep (Whh + Wih + colsum zero) ---------
__global__ void k_prep_all(const float* __restrict__ Whh,
                           const float* __restrict__ Wih) {
    int blk = blockIdx.x;
    if (blk < 48) {
        int idx = blk * 256 + threadIdx.x;           // 12288 = 8*8*6*32
        int lane = idx & 31; int r = idx >> 5;
        int nt = r % 6; r /= 6;
        int w8 = r & 7; int kt = r >> 3;
        int g = nt >> 1, s = nt & 1;
        int n = g * 128 + w8 * 16 + s * 8 + (lane >> 2);
        int kb = kt * 16 + (lane & 3) * 2;
        float w0 = Whh[n * 128 + kb],     w1 = Whh[n * 128 + kb + 1];
        float w2 = Whh[n * 128 + kb + 8], w3 = Whh[n * 128 + kb + 9];
        __nv_bfloat16 h0 = __float2bfloat16(w0), h1 = __float2bfloat16(w1);
        __nv_bfloat16 h2 = __float2bfloat16(w2), h3 = __float2bfloat16(w3);
        {
            __nv_bfloat162 v; v.x = h0; v.y = h1;
            g_Bhi[idx * 2 + 0] = *(uint32_t*)&v;
            v.x = h2; v.y = h3;
            g_Bhi[idx * 2 + 1] = *(uint32_t*)&v;
        }
        __nv_bfloat162 l01, l23;
        l01.x = __float2bfloat16(w0 - __bfloat162float(h0));
        l01.y = __float2bfloat16(w1 - __bfloat162float(h1));
        l23.x = __float2bfloat16(w2 - __bfloat162float(h2));
        l23.y = __float2bfloat16(w3 - __bfloat162float(h3));
        uint32_t* lo = &g_Blo[(((kt * 8 + w8) * 2 + s) * 32 + lane) * 8 + g * 2];
        lo[0] = *(uint32_t*)&l01;
        lo[1] = *(uint32_t*)&l23;
    } else {
        int idx = (blk - 48) * 256 + threadIdx.x;    // 1536 = 8*6*32
        int lane = idx & 31; int r = idx >> 5;
        int nt = r % 6; int w8 = r / 6;
        int g = nt >> 1, s = nt & 1;
        int n = g * 128 + w8 * 16 + s * 8 + (lane >> 2);
        int kb = (lane & 3) * 2;
        float w0 = Wih[n * FF + kb],     w1 = Wih[n * FF + kb + 1];
        float w2 = Wih[n * FF + kb + 8], w3 = Wih[n * FF + kb + 9];
        __nv_bfloat16 h0 = __float2bfloat16(w0), h1 = __float2bfloat16(w1);
        __nv_bfloat16 h2 = __float2bfloat16(w2), h3 = __float2bfloat16(w3);
        {
            __nv_bfloat162 v; v.x = h0; v.y = h1;
            g_WihHi[idx * 2 + 0] = *(uint32_t*)&v;
            v.x = h2; v.y = h3;
            g_WihHi[idx * 2 + 1] = *(uint32_t*)&v;
        }
        __nv_bfloat162 l01, l23;
        l01.x = __float2bfloat16(w0 - __bfloat162float(h0));
        l01.y = __float2bfloat16(w1 - __bfloat162float(h1));
        l23.x = __float2bfloat16(w2 - __bfloat162float(h2));
        l23.y = __float2bfloat16(w3 - __bfloat162float(h3));
        uint32_t* lo = &g_WihLo[((w8 * 2 + s) * 32 + lane) * 8 + g * 2];
        lo[0] = *(uint32_t*)&l01;
        lo[1] = *(uint32_t*)&l23;
        if (blk == 48 && threadIdx.x < HH) g_colsum[threadIdx.x] = 0.f;
    }
}

// ---------------- kernel 2: fused GRU, 256 thr, B-hi in registers -----------
#define HBUF 2176

__global__ void __launch_bounds__(256, 1) k_gru(const float* __restrict__ feat,
                                                const float* __restrict__ bih,
                                                const float* __restrict__ bhh) {
    __shared__ __align__(16) uint32_t hbase[4 * HBUF];   // 34.8 KB
    int tid = threadIdx.x;
    int w = tid >> 5, lane = tid & 31;                   // w in [0,8)
    int qr = lane >> 2, qc = lane & 3;
    int node0 = blockIdx.x * 32;

    const uint2* Bhi2g = (const uint2*)g_Bhi;
    uint2 bhr[8][3][2];
#pragma unroll
    for (int kt = 0; kt < 8; kt++)
#pragma unroll
        for (int g = 0; g < 3; g++)
#pragma unroll
            for (int s = 0; s < 2; s++)
                bhr[kt][g][s] = __ldg(&Bhi2g[((kt * 8 + w) * 6 + g * 2 + s) * 32 + lane]);

    for (int i = tid; i < 4 * HBUF; i += 256) hbase[i] = 0u;

    float bRr[2][2], bRz[2][2], biN[2][2], bhN[2][2];
#pragma unroll
    for (int s = 0; s < 2; s++)
#pragma unroll
        for (int jj = 0; jj < 2; jj++) {
            int c = w * 16 + s * 8 + 2 * qc + jj;
            bRr[s][jj] = __ldg(&bih[c]) + __ldg(&bhh[c]);
            bRz[s][jj] = __ldg(&bih[128 + c]) + __ldg(&bhh[128 + c]);
            biN[s][jj] = __ldg(&bih[256 + c]);
            bhN[s][jj] = __ldg(&bhh[256 + c]);
        }
    __syncthreads();

    const uint2* WihHi2 = (const uint2*)g_WihHi;
    int cur = 0;

    for (int t = 0; t < TT; t++) {
        uint32_t* h_hi_w = hbase + cur * (2 * HBUF);
        uint32_t* h_lo_w = h_hi_w + HBUF;
        uint32_t* n_hi_w = hbase + (cur ^ 1) * (2 * HBUF);
        uint32_t* n_lo_w = n_hi_w + HBUF;

        uint32_t xh[2][4], xl[2][4];
#pragma unroll
        for (int m = 0; m < 2; m++) {
            const float* base = feat + (size_t)(node0 + m * 16) * (TT * FF) + t * FF;
            float2 v[4];
            v[0] = __ldg((const float2*)(base + (size_t)qr * (TT * FF) + 2 * qc));
            v[1] = __ldg((const float2*)(base + (size_t)(qr + 8) * (TT * FF) + 2 * qc));
            v[2] = __ldg((const float2*)(base + (size_t)qr * (TT * FF) + 2 * qc + 8));
            v[3] = __ldg((const float2*)(base + (size_t)(qr + 8) * (TT * FF) + 2 * qc + 8));
#pragma unroll
            for (int j = 0; j < 4; j++) {
                __nv_bfloat162 hv; hv.x = __float2bfloat16(v[j].x); hv.y = __float2bfloat16(v[j].y);
                xh[m][j] = *(uint32_t*)&hv;
                __nv_bfloat162 lv;
                lv.x = __float2bfloat16(v[j].x - __bfloat162float(hv.x));
                lv.y = __float2bfloat16(v[j].y - __bfloat162float(hv.y));
                xl[m][j] = *(uint32_t*)&lv;
            }
        }

        float d[2][3][2][4];
        float dx[2][2][4];
#pragma unroll
        for (int m = 0; m < 2; m++) {
#pragma unroll
            for (int g = 0; g < 3; g++)
#pragma unroll
                for (int s = 0; s < 2; s++)
#pragma unroll
                    for (int j = 0; j < 4; j++) d[m][g][s][j] = 0.f;
#pragma unroll
            for (int s = 0; s < 2; s++)
#pragma unroll
                for (int j = 0; j < 4; j++) dx[m][s][j] = 0.f;
        }

        // ---- x @ Wih^T (k=16) ----
#pragma unroll
        for (int s = 0; s < 2; s++) {
            const uint32_t* p = &g_WihLo[((w * 2 + s) * 32 + lane) * 8];
            uint4 wlA = __ldg((const uint4*)p);
            uint2 wlB = __ldg((const uint2*)(p + 4));
            uint32_t wlw[6] = {wlA.x, wlA.y, wlA.z, wlA.w, wlB.x, wlB.y};
#pragma unroll
            for (int g = 0; g < 3; g++) {
                uint2 bh = __ldg(&WihHi2[(w * 6 + g * 2 + s) * 32 + lane]);
#pragma unroll
                for (int m = 0; m < 2; m++) {
                    float* D = (g == 2) ? dx[m][s] : d[m][g][s];
                    mma_bf16(D, xh[m], bh.x, bh.y);
                    mma_bf16(D, xl[m], bh.x, bh.y);
                    mma_bf16(D, xh[m], wlw[g * 2], wlw[g * 2 + 1]);
                }
            }
        }

        // ---- h @ Whh^T (bf16, B-hi from registers, lo streamed) ----
        if (t) {
#pragma unroll
            for (int kt = 0; kt < 8; kt++) {
                uint32_t ah[2][4], al[2][4];
#pragma unroll
                for (int m = 0; m < 2; m++) {
                    int r0 = (m * 16 + qr) * 68 + kt * 8 + qc;
                    ah[m][0] = h_hi_w[r0];
                    ah[m][1] = h_hi_w[r0 + 8 * 68];
                    ah[m][2] = h_hi_w[r0 + 4];
                    ah[m][3] = h_hi_w[r0 + 8 * 68 + 4];
                    al[m][0] = h_lo_w[r0];
                    al[m][1] = h_lo_w[r0 + 8 * 68];
                    al[m][2] = h_lo_w[r0 + 4];
                    al[m][3] = h_lo_w[r0 + 8 * 68 + 4];
                }
#pragma unroll
                for (int s = 0; s < 2; s++) {
                    const uint32_t* p = &g_Blo[(((kt * 8 + w) * 2 + s) * 32 + lane) * 8];
                    uint4 lA = __ldg((const uint4*)p);
                    uint2 lB = __ldg((const uint2*)(p + 4));
                    uint32_t lw[6] = {lA.x, lA.y, lA.z, lA.w, lB.x, lB.y};
#pragma unroll
                    for (int g = 0; g < 3; g++) {
                        uint2 bh = bhr[kt][g][s];
#pragma unroll
                        for (int m = 0; m < 2; m++) {
                            mma_bf16(d[m][g][s], ah[m], bh.x, bh.y);
                            mma_bf16(d[m][g][s], al[m], bh.x, bh.y);
                            mma_bf16(d[m][g][s], ah[m], lw[g * 2], lw[g * 2 + 1]);
                        }
                    }
                }
            }
        }

        // ---- gate math: read h[cur], write h[nxt], single barrier ----
#pragma unroll
        for (int m = 0; m < 2; m++)
#pragma unroll
            for (int s = 0; s < 2; s++)
#pragma unroll
                for (int rg = 0; rg < 2; rg++) {
                    int row = m * 16 + qr + rg * 8;
                    int wi = row * 68 + w * 8 + s * 4 + qc;
                    float2 hhf = __bfloat1622float2(*(__nv_bfloat162*)&h_hi_w[wi]);
                    float2 hlf = __bfloat1622float2(*(__nv_bfloat162*)&h_lo_w[wi]);
                    float hn[2];
#pragma unroll
                    for (int jj = 0; jj < 2; jj++) {
                        float hold = jj ? (hhf.y + hlf.y) : (hhf.x + hlf.x);
                        int di = rg * 2 + jj;
                        float rr = sigmoid_fast(d[m][0][s][di] + bRr[s][jj]);
                        float zz = sigmoid_fast(d[m][1][s][di] + bRz[s][jj]);
                        float nv = tanh_fast(dx[m][s][di] + biN[s][jj] +
                                             rr * (d[m][2][s][di] + bhN[s][jj]));
                        hn[jj] = (1.f - zz) * nv + zz * hold;
                    }
                    __nv_bfloat162 hv; hv.x = __float2bfloat16(hn[0]); hv.y = __float2bfloat16(hn[1]);
                    __nv_bfloat162 lv;
                    lv.x = __float2bfloat16(hn[0] - __bfloat162float(hv.x));
                    lv.y = __float2bfloat16(hn[1] - __bfloat162float(hv.y));
                    n_hi_w[wi] = *(uint32_t*)&hv;
                    n_lo_w[wi] = *(uint32_t*)&lv;
                }
        __syncthreads();
        cur ^= 1;
    }

    const __nv_bfloat16* h_hi = (const __nv_bfloat16*)(hbase + cur * (2 * HBUF));
    const __nv_bfloat16* h_lo = h_hi + 2 * HBUF;
    for (int i = tid; i < 32 * HH; i += 256) {
        int row = i >> 7, col = i & 127;
        g_support[(size_t)(node0 + row) * HH + col] =
            __bfloat162float(h_hi[row * 136 + col]) +
            __bfloat162float(h_lo[row * 136 + col]);
    }
}

// ---------------- kernel 3: bf16 GEMM C = A @ B (+b1+b2) [+f1/f2 epilogue] --
struct GemmJob {
    const float* A; const float* B; const float* b1; const float* b2; float* C;
    const float* u; const float* v; float* f1; float* f2;
};
struct GemmJobs { GemmJob j[5]; };

#define GEMM_SMEM (4 * 128 * 136 * 2)   // 139264 B

__global__ void __launch_bounds__(256) k_gemm(GemmJobs jobs) {
    GemmJob job = jobs.j[blockIdx.y];
    extern __shared__ char smc[];
    uint16_t* As_hi = (uint16_t*)smc;
    uint16_t* As_lo = As_hi + 128 * 136;
    uint16_t* Bs_hi = As_lo + 128 * 136;
    uint16_t* Bs_lo = Bs_hi + 128 * 136;
    int tid = threadIdx.x;
    int node0 = blockIdx.x * 128;

    for (int idx = tid; idx < 128 * 128; idx += 256) {
        int r = idx >> 7, c = idx & 127;
        float a = job.A[(size_t)(node0 + r) * HH + c];
        __nv_bfloat16 ah = __float2bfloat16(a);
        As_hi[r * 136 + c] = __bfloat16_as_ushort(ah);
        As_lo[r * 136 + c] =
            __bfloat16_as_ushort(__float2bfloat16(a - __bfloat162float(ah)));
        float b = job.B[idx];
        __nv_bfloat16 bh = __float2bfloat16(b);
        Bs_hi[c * 136 + r] = __bfloat16_as_ushort(bh);
        Bs_lo[c * 136 + r] =
            __bfloat16_as_ushort(__float2bfloat16(b - __bfloat162float(bh)));
    }
    __syncthreads();

    int w = tid >> 5, lane = tid & 31;
    int qr = lane >> 2, qc = lane & 3;
    int r0 = w * 16;
    const uint32_t* Aw_hi = (const uint32_t*)As_hi;
    const uint32_t* Aw_lo = (const uint32_t*)As_lo;
    const uint32_t* Bw_hi = (const uint32_t*)Bs_hi;
    const uint32_t* Bw_lo = (const uint32_t*)Bs_lo;

    float acc[16][4];
#pragma unroll
    for (int ct = 0; ct < 16; ct++)
#pragma unroll
        for (int j = 0; j < 4; j++) acc[ct][j] = 0.f;

#pragma unroll 1
    for (int kt = 0; kt < 8; kt++) {
        int kc = kt * 8 + qc;
        uint32_t ah[4], al[4];
        ah[0] = Aw_hi[(r0 + qr) * 68 + kc];
        ah[1] = Aw_hi[(r0 + qr + 8) * 68 + kc];
        ah[2] = Aw_hi[(r0 + qr) * 68 + kc + 4];
        ah[3] = Aw_hi[(r0 + qr + 8) * 68 + kc + 4];
        al[0] = Aw_lo[(r0 + qr) * 68 + kc];
        al[1] = Aw_lo[(r0 + qr + 8) * 68 + kc];
        al[2] = Aw_lo[(r0 + qr) * 68 + kc + 4];
        al[3] = Aw_lo[(r0 + qr + 8) * 68 + kc + 4];
#pragma unroll
        for (int cg = 0; cg < 4; cg++) {
            uint32_t bh0[4], bh1[4], bl0[4], bl1[4];
#pragma unroll
            for (int j = 0; j < 4; j++) {
                int n0 = (cg * 4 + j) * 8;
                bh0[j] = Bw_hi[(n0 + qr) * 68 + kc];
                bh1[j] = Bw_hi[(n0 + qr) * 68 + kc + 4];
                bl0[j] = Bw_lo[(n0 + qr) * 68 + kc];
                bl1[j] = Bw_lo[(n0 + qr) * 68 + kc + 4];
            }
#pragma unroll
            for (int j = 0; j < 4; j++)
                mma_bf16(acc[cg * 4 + j], ah, bh0[j], bh1[j]);
#pragma unroll
            for (int j = 0; j < 4; j++)
                mma_bf16(acc[cg * 4 + j], al, bh0[j], bh1[j]);
#pragma unroll
            for (int j = 0; j < 4; j++)
                mma_bf16(acc[cg * 4 + j], ah, bl0[j], bl1[j]);
        }
    }

#pragma unroll
    for (int ct = 0; ct < 16; ct++) {
        int c0 = ct * 8 + 2 * qc;
        float b0 = 0.f, b1v = 0.f;
        if (job.b1) { b0 += __ldg(&job.b1[c0]); b1v += __ldg(&job.b1[c0 + 1]); }
        if (job.b2) { b0 += __ldg(&job.b2[c0]); b1v += __ldg(&job.b2[c0 + 1]); }
        acc[ct][0] += b0; acc[ct][1] += b1v;
        acc[ct][2] += b0; acc[ct][3] += b1v;
        int r = node0 + r0 + qr;
        *(float2*)&job.C[(size_t)r * HH + c0] = make_float2(acc[ct][0], acc[ct][1]);
        *(float2*)&job.C[(size_t)(r + 8) * HH + c0] = make_float2(acc[ct][2], acc[ct][3]);
    }

    // ---- fused f1/f2 epilogue (attention logits per head) ----
    if (job.u) {
        float f1p[2][4], f2p[2][4];     // [rowhalf][head]
#pragma unroll
        for (int rh = 0; rh < 2; rh++)
#pragma unroll
            for (int h = 0; h < 4; h++) { f1p[rh][h] = 0.f; f2p[rh][h] = 0.f; }
#pragma unroll
        for (int ct = 0; ct < 16; ct++) {
            int h = ct >> 2;
            int c0 = ct * 8 + 2 * qc;
            float u0 = __ldg(&job.u[c0]),     u1 = __ldg(&job.u[c0 + 1]);
            float v0 = __ldg(&job.v[c0]),     v1 = __ldg(&job.v[c0 + 1]);
            f1p[0][h] += acc[ct][0] * u0 + acc[ct][1] * u1;
            f2p[0][h] += acc[ct][0] * v0 + acc[ct][1] * v1;
            f1p[1][h] += acc[ct][2] * u0 + acc[ct][3] * u1;
            f2p[1][h] += acc[ct][2] * v0 + acc[ct][3] * v1;
        }
        // reduce across the 4 lanes of this quad (same qr, qc = 0..3)
#pragma unroll
        for (int rh = 0; rh < 2; rh++)
#pragma unroll
            for (int h = 0; h < 4; h++) {
                f1p[rh][h] += __shfl_xor_sync(0xffffffffu, f1p[rh][h], 1);
                f1p[rh][h] += __shfl_xor_sync(0xffffffffu, f1p[rh][h], 2);
                f2p[rh][h] += __shfl_xor_sync(0xffffffffu, f2p[rh][h], 1);
                f2p[rh][h] += __shfl_xor_sync(0xffffffffu, f2p[rh][h], 2);
            }
        if (qc == 0) {
#pragma unroll
            for (int rh = 0; rh < 2; rh++) {
                int r = node0 + r0 + qr + rh * 8;
#pragma unroll
                for (int h = 0; h < 4; h++) {
                    job.f1[h * NN + r] = f1p[rh][h];
                    job.f2[h * NN + r] = f2p[rh][h];
                }
            }
        }
    }
}

// ---------------- kernel 5: GAT masked-attention aggregation -----------------
__global__ void __launch_bounds__(128) k_gat(const float* __restrict__ adjP,
                                             const float* __restrict__ adjN) {
    __shared__ int s_cnt;
    __shared__ int s_list[640];
    __shared__ float s_a[640];
    const float* adj; const float* sup; const float* f1; const float* f2;
    const float* resid; float* outp;
    if (blockIdx.y == 0) { adj = adjP; sup = g_supP; f1 = g_f1P; f2 = g_f2P; resid = g_residP; outp = g_gatP; }
    else                 { adj = adjN; sup = g_supN; f1 = g_f1N; f2 = g_f2N; resid = g_residN; outp = g_gatN; }
    int i = blockIdx.x, tid = threadIdx.x;
    int h = tid >> 5;
    if (tid == 0) s_cnt = 0;
    __syncthreads();
    const float4* row = (const float4*)(adj + (size_t)i * NN);
    for (int j4 = tid; j4 < NN / 4; j4 += 128) {
        float4 a = __ldg(&row[j4]);
        if (a.x != 0.f) { int p = atomicAdd(&s_cnt, 1); s_list[p] = j4 * 4 + 0; s_a[p] = a.x; }
        if (a.y != 0.f) { int p = atomicAdd(&s_cnt, 1); s_list[p] = j4 * 4 + 1; s_a[p] = a.y; }
        if (a.z != 0.f) { int p = atomicAdd(&s_cnt, 1); s_list[p] = j4 * 4 + 2; s_a[p] = a.z; }
        if (a.w != 0.f) { int p = atomicAdd(&s_cnt, 1); s_list[p] = j4 * 4 + 3; s_a[p] = a.w; }
    }
    __syncthreads();
    int cnt = s_cnt;
    float f2i = f2[h * NN + i];
    float num = 0.f, den = 0.f;
    for (int t = 0; t < cnt; t++) {
        int j = s_list[t];
        float w = f1[h * NN + j] + f2i;
        w = (w > 0.f) ? w : 0.2f * w;
        w *= s_a[t];
        den += w;
        num += w * sup[(size_t)j * HH + tid];
    }
    float d = (den == 0.f) ? 1.f : den;
    outp[(size_t)i * HH + tid] = num / d + resid[(size_t)i * HH + tid];
}

// ---------------- kernel 7: semantic attention, warp-per-node ----------------
__global__ void __launch_bounds__(256) k_sem(const float* __restrict__ W1,
                                             const float* __restrict__ b1,
                                             const float* __restrict__ W2) {
    __shared__ float W1s[128 * 65];
    __shared__ float W2s[SEMD], b1s[SEMD];
    __shared__ float semb[8][3][128];
    int tid = threadIdx.x;
    for (int i = tid; i < 128 * 64; i += 256) {
        int k = i >> 6, s = i & 63;
        W1s[k * 65 + s] = W1[i];
    }
    if (tid < SEMD) { W2s[tid] = W2[tid]; b1s[tid] = b1[tid]; }
    __syncthreads();

    int w = tid >> 5, lane = tid & 31;
    float csum[4] = {0.f, 0.f, 0.f, 0.f};
    int nbase = (blockIdx.x * 8 + w) * 8;

    for (int i = 0; i < 8; i++) {
        int n = nbase + i;
        float4 ev[3];
        ev[0] = *(const float4*)&g_selfE[(size_t)n * HH + lane * 4];
        ev[1] = *(const float4*)&g_posE[(size_t)n * HH + lane * 4];
        ev[2] = *(const float4*)&g_negE[(size_t)n * HH + lane * 4];
        __syncwarp();
        *(float4*)&semb[w][0][lane * 4] = ev[0];
        *(float4*)&semb[w][1][lane * 4] = ev[1];
        *(float4*)&semb[w][2][lane * 4] = ev[2];
        __syncwarp();

        float acc[3][2];
#pragma unroll
        for (int e = 0; e < 3; e++) { acc[e][0] = b1s[lane]; acc[e][1] = b1s[lane + 32]; }
#pragma unroll 4
        for (int k = 0; k < HH; k++) {
            float w1a = W1s[k * 65 + lane];
            float w1b = W1s[k * 65 + lane + 32];
            float x0 = semb[w][0][k], x1 = semb[w][1][k], x2 = semb[w][2][k];
            acc[0][0] += x0 * w1a; acc[0][1] += x0 * w1b;
            acc[1][0] += x1 * w1a; acc[1][1] += x1 * w1b;
            acc[2][0] += x2 * w1a; acc[2][1] += x2 * w1b;
        }
        float wv[3];
#pragma unroll
        for (int e = 0; e < 3; e++) {
            float tsum = tanh_fast(acc[e][0]) * W2s[lane] +
                         tanh_fast(acc[e][1]) * W2s[lane + 32];
            wv[e] = warpsum_bfly(tsum);
        }
        float m = fmaxf(wv[0], fmaxf(wv[1], wv[2]));
        float e0 = __expf(wv[0] - m), e1 = __expf(wv[1] - m), e2 = __expf(wv[2] - m);
        float inv = __fdividef(1.f, e0 + e1 + e2);
        float be0 = e0 * inv, be1 = e1 * inv, be2 = e2 * inv;
        float4 f;
        f.x = be0 * ev[0].x + be1 * ev[1].x + be2 * ev[2].x;
        f.y = be0 * ev[0].y + be1 * ev[1].y + be2 * ev[2].y;
        f.z = be0 * ev[0].z + be1 * ev[1].z + be2 * ev[2].z;
        f.w = be0 * ev[0].w + be1 * ev[1].w + be2 * ev[2].w;
        *(float4*)&g_fused[(size_t)n * HH + lane * 4] = f;
        csum[0] += f.x; csum[1] += f.y; csum[2] += f.z; csum[3] += f.w;
    }
    atomicAdd(&g_colsum[lane * 4 + 0], csum[0]);
    atomicAdd(&g_colsum[lane * 4 + 1], csum[1]);
    atomicAdd(&g_colsum[lane * 4 + 2], csum[2]);
    atomicAdd(&g_colsum[lane * 4 + 3], csum[3]);
}

// ---------------- kernel 8: pairnorm + predictor -----------------------------
__global__ void __launch_bounds__(256) k_pred(const float* __restrict__ W1,
                                              const float* __restrict__ b1,
                                              const float* __restrict__ W2,
                                              const float* __restrict__ b2,
                                              float* __restrict__ out) {
    __shared__ float W1s[HH * PHD];
    __shared__ float xns[8][HH];
    int tid = threadIdx.x;
    for (int i = tid; i < HH * PHD; i += 256) W1s[i] = W1[i];
    int w = tid >> 5, lane = tid & 31;
    int n = blockIdx.x * 8 + w;
    float xv[4]; float ss = 0.f;
    const float invN = 1.f / (float)NN;
#pragma unroll
    for (int j = 0; j < 4; j++) {
        int d = lane + j * 32;
        float x = g_fused[(size_t)n * HH + d] - g_colsum[d] * invN;
        xv[j] = x; ss += x * x;
    }
    ss = warpsum(ss);
    ss = __shfl_sync(0xffffffffu, ss, 0);
    float rinv = rsqrtf(1e-6f + ss);
#pragma unroll
    for (int j = 0; j < 4; j++) xns[w][lane + j * 32] = xv[j] * rinv;
    __syncthreads();

    float acc = b1[lane];
#pragma unroll 4
    for (int k = 0; k < HH; k++) acc += xns[w][k] * W1s[k * PHD + lane];
    float hgt = acc > 0.f ? acc : 0.f;
    float o = warpsum(hgt * W2[lane]);
    if (lane == 0) out[n] = sigmoid_fast(o + b2[0]);
}

// ---------------- launch -----------------------------------------------------
extern "C" void kernel_launch(void* const* d_in, const int* in_sizes, int n_in,
                              void* d_out, int out_size) {
    const float* features = (const float*)d_in[0];
    const float* pos_adj  = (const float*)d_in[1];
    const float* neg_adj  = (const float*)d_in[2];
    const float* gru_Wih  = (const float*)d_in[3];
    const float* gru_Whh  = (const float*)d_in[4];
    const float* gru_bih  = (const float*)d_in[5];
    const float* gru_bhh  = (const float*)d_in[6];
    const float* pos_W    = (const float*)d_in[7];
    const float* pos_u    = (const float*)d_in[8];
    const float* pos_v    = (const float*)d_in[9];
    const float* pos_b    = (const float*)d_in[10];
    const float* pos_pW   = (const float*)d_in[11];
    const float* pos_pb   = (const float*)d_in[12];
    const float* neg_W    = (const float*)d_in[13];
    const float* neg_u    = (const float*)d_in[14];
    const float* neg_v    = (const float*)d_in[15];
    const float* neg_b    = (const float*)d_in[16];
    const float* neg_pW   = (const float*)d_in[17];
    const float* neg_pb   = (const float*)d_in[18];
    const float* self_W   = (const float*)d_in[19];
    const float* self_b   = (const float*)d_in[20];
    const float* mpos_W   = (const float*)d_in[21];
    const float* mpos_b   = (const float*)d_in[22];
    const float* mneg_W   = (const float*)d_in[23];
    const float* mneg_b   = (const float*)d_in[24];
    const float* sem_W1   = (const float*)d_in[25];
    const float* sem_b1   = (const float*)d_in[26];
    const float* sem_W2   = (const float*)d_in[27];
    const float* pred_W1  = (const float*)d_in[28];
    const float* pred_b1  = (const float*)d_in[29];
    const float* pred_W2  = (const float*)d_in[30];
    const float* pred_b2  = (const float*)d_in[31];
    float* out = (float*)d_out;

    static bool attr_done = false;
    if (!attr_done) {
        cudaFuncSetAttribute(k_gemm, cudaFuncAttributeMaxDynamicSharedMemorySize, GEMM_SMEM);
        attr_done = true;
    }

    float *p_support, *p_gatP, *p_gatN, *p_supP, *p_supN;
    float *p_residP, *p_residN, *p_selfE, *p_posE, *p_negE;
    float *p_f1P, *p_f2P, *p_f1N, *p_f2N;
    cudaGetSymbolAddress((void**)&p_support, g_support);
    cudaGetSymbolAddress((void**)&p_supP, g_supP);
    cudaGetSymbolAddress((void**)&p_supN, g_supN);
    cudaGetSymbolAddress((void**)&p_residP, g_residP);
    cudaGetSymbolAddress((void**)&p_residN, g_residN);
    cudaGetSymbolAddress((void**)&p_selfE, g_selfE);
    cudaGetSymbolAddress((void**)&p_gatP, g_gatP);
    cudaGetSymbolAddress((void**)&p_gatN, g_gatN);
    cudaGetSymbolAddress((void**)&p_posE, g_posE);
    cudaGetSymbolAddress((void**)&p_negE, g_negE);
    cudaGetSymbolAddress((void**)&p_f1P, g_f1P);
    cudaGetSymbolAddress((void**)&p_f2P, g_f2P);
    cudaGetSymbolAddress((void**)&p_f1N, g_f1N);
    cudaGetSymbolAddress((void**)&p_f2N, g_f2N);

    k_prep_all<<<54, 256>>>(gru_Whh, gru_Wih);                      // 1
    k_gru<<<NN / 32, 256>>>(features, gru_bih, gru_bhh);            // 2
    {
        GemmJobs jb;
        jb.j[0] = { p_support, pos_W,  nullptr, nullptr, p_supP, pos_u, pos_v, p_f1P, p_f2P };
        jb.j[1] = { p_support, neg_W,  nullptr, nullptr, p_supN, neg_u, neg_v, p_f1N, p_f2N };
        jb.j[2] = { p_support, pos_pW, pos_b,   pos_pb,  p_residP, nullptr, nullptr, nullptr, nullptr };
        jb.j[3] = { p_support, neg_pW, neg_b,   neg_pb,  p_residN, nullptr, nullptr, nullptr, nullptr };
        jb.j[4] = { p_support, self_W, self_b,  nullptr, p_selfE, nullptr, nullptr, nullptr, nullptr };
        dim3 grid(NN / 128, 5);
        k_gemm<<<grid, 256, GEMM_SMEM>>>(jb);                       // 3
    }
    {
        dim3 grid(NN, 2);
        k_gat<<<grid, 128>>>(pos_adj, neg_adj);                     // 4
    }
    {
        GemmJobs jb;
        jb.j[0] = { p_gatP, mpos_W, mpos_b, nullptr, p_posE, nullptr, nullptr, nullptr, nullptr };
        jb.j[1] = { p_gatN, mneg_W, mneg_b, nullptr, p_negE, nullptr, nullptr, nullptr, nullptr };
        jb.j[2] = jb.j[0]; jb.j[3] = jb.j[0]; jb.j[4] = jb.j[0];
        dim3 grid(NN / 128, 2);
        k_gemm<<<grid, 256, GEMM_SMEM>>>(jb);                       // 5
    }
    k_sem<<<NN / 64, 256>>>(sem_W1, sem_b1, sem_W2);                // 6
    k_pred<<<NN / 8, 256>>>(pred_W1, pred_b1, pred_W2, pred_b2, out); // 7
}